// round 10
// baseline (speedup 1.0000x reference)
#include <cuda_runtime.h>
#include <cuda_fp16.h>
#include <math.h>

#define N_NODES 100000
#define N_EDGES 1600000
#define HID 128
#define NGRAPH 64
#define ETILE 64
#define NTILES (N_EDGES / ETILE)
#define SCAN_B 512
#define SCAN_NB ((N_NODES + SCAN_B - 1) / SCAN_B)   // 196

// ---------------- device scratch ----------------
__device__ float  g_h[N_NODES * HID];
__device__ __half g_hh[N_NODES * HID];
__device__ __half g_PA[N_NODES * 256];   // interleaved: blk k = [f4k..f4k+3 | s4k..s4k+3]
__device__ __half g_PB[N_NODES * 256];   // same interleave
__device__ float  g_agg[N_NODES * HID];
__device__ float  g_pool[NGRAPH * HID + NGRAPH];
__device__ int    g_deg[N_NODES];
__device__ int    g_cursor[N_NODES];
__device__ int    g_part[256];
__device__ int4   g_esd[N_EDGES];
__device__ int    g_srcs[N_EDGES];
__device__ int    g_dsts[N_EDGES];
__device__ __half g_eas[(size_t)N_EDGES * 32];

// ---------------- helpers ----------------
__device__ __forceinline__ float sigmoidf_(float x) { return 1.0f / (1.0f + __expf(-x)); }
__device__ __forceinline__ float softplusf_(float x) {
    return fmaxf(x, 0.0f) + __logf(1.0f + __expf(-fabsf(x)));
}
__device__ __forceinline__ float tanha_(float x) {
    float y;
    asm("tanh.approx.f32 %0, %1;" : "=f"(y) : "f"(x));
    return y;
}
__device__ __forceinline__ unsigned h2exp2_(unsigned x) {
    unsigned y;
    asm("ex2.approx.f16x2 %0, %1;" : "=r"(y) : "r"(x));
    return y;
}
__device__ __forceinline__ void red4(float* p, float4 v) {
    asm volatile("red.global.add.v4.f32 [%0], {%1,%2,%3,%4};"
                 :: "l"(p), "f"(v.x), "f"(v.y), "f"(v.z), "f"(v.w));
}
__device__ __forceinline__ void mma_f16(float d[4],
                                        unsigned a0, unsigned a1, unsigned a2, unsigned a3,
                                        unsigned b0, unsigned b1) {
    asm volatile("mma.sync.aligned.m16n8k16.row.col.f32.f16.f16.f32 "
                 "{%0,%1,%2,%3}, {%4,%5,%6,%7}, {%8,%9}, {%0,%1,%2,%3};\n"
                 : "+f"(d[0]), "+f"(d[1]), "+f"(d[2]), "+f"(d[3])
                 : "r"(a0), "r"(a1), "r"(a2), "r"(a3), "r"(b0), "r"(b1));
}

// ---------------- CSR build ----------------
__global__ void k_hist(const int* __restrict__ ei, int* __restrict__ deg) {
    int e = blockIdx.x * blockDim.x + threadIdx.x;
    if (e < N_EDGES) atomicAdd(&deg[ei[N_EDGES + e]], 1);
}
__global__ void k_scan_a(const int* __restrict__ deg, int* __restrict__ cursor,
                         int* __restrict__ part) {
    __shared__ int s[SCAN_B];
    int i = blockIdx.x * SCAN_B + threadIdx.x;
    int v = (i < N_NODES) ? deg[i] : 0;
    s[threadIdx.x] = v;
    __syncthreads();
    for (int off = 1; off < SCAN_B; off <<= 1) {
        int t = (threadIdx.x >= off) ? s[threadIdx.x - off] : 0;
        __syncthreads();
        s[threadIdx.x] += t;
        __syncthreads();
    }
    if (i < N_NODES) cursor[i] = s[threadIdx.x] - v;
    if (threadIdx.x == SCAN_B - 1) part[blockIdx.x] = s[threadIdx.x];
}
__global__ void k_scan_b(int* __restrict__ part, int nb) {
    __shared__ int s[256];
    int v = (threadIdx.x < nb) ? part[threadIdx.x] : 0;
    s[threadIdx.x] = v;
    __syncthreads();
    for (int off = 1; off < 256; off <<= 1) {
        int t = (threadIdx.x >= off) ? s[threadIdx.x - off] : 0;
        __syncthreads();
        s[threadIdx.x] += t;
        __syncthreads();
    }
    if (threadIdx.x < nb) part[threadIdx.x] = s[threadIdx.x] - v;
}

// ---------------- pass 1: conv1 + light permutation scatter ----------------
__global__ void k_conv1_perm(const float* __restrict__ x, const int* __restrict__ ei,
                             const float* __restrict__ ea,
                             const float* __restrict__ Wf, const float* __restrict__ bf,
                             const float* __restrict__ Ws, const float* __restrict__ bs,
                             int* __restrict__ cursor, const int* __restrict__ part,
                             int4* __restrict__ esd, float* __restrict__ agg) {
    __shared__ float sWf[38 * 3], sWs[38 * 3], sbf[3], sbs[3];
    int t = threadIdx.x;
    if (t < 114) { sWf[t] = Wf[t]; sWs[t] = Ws[t]; }
    if (t < 3)   { sbf[t] = bf[t]; sbs[t] = bs[t]; }
    __syncthreads();
    int e = blockIdx.x * blockDim.x + t;
    if (e >= N_EDGES) return;
    int src = ei[e];
    int dst = ei[N_EDGES + e];

    float z[38];
    z[0] = x[dst * 3 + 0]; z[1] = x[dst * 3 + 1]; z[2] = x[dst * 3 + 2];
    z[3] = x[src * 3 + 0]; z[4] = x[src * 3 + 1]; z[5] = x[src * 3 + 2];
    const float4* s = (const float4*)&ea[(size_t)e * 32];
#pragma unroll
    for (int j = 0; j < 8; j++) {
        float4 v = s[j];
        z[6 + j * 4 + 0] = v.x; z[6 + j * 4 + 1] = v.y;
        z[6 + j * 4 + 2] = v.z; z[6 + j * 4 + 3] = v.w;
    }
#pragma unroll
    for (int c = 0; c < 3; c++) {
        float lf = sbf[c], ls = sbs[c];
#pragma unroll
        for (int k = 0; k < 38; k++) {
            lf += z[k] * sWf[k * 3 + c];
            ls += z[k] * sWs[k * 3 + c];
        }
        float m = sigmoidf_(lf) * softplusf_(ls);
        atomicAdd(&agg[dst * 3 + c], m);
    }
    int pos = atomicAdd(&cursor[dst], 1) + part[dst >> 9];
    esd[pos] = make_int4(src, dst, e, 0);
}

// ---------------- pass 2: coalesced gather-convert ----------------
__global__ void k_gather(const int4* __restrict__ esd, const float* __restrict__ ea,
                         int* __restrict__ srcs, int* __restrict__ dsts,
                         __half* __restrict__ eas) {
    int p = blockIdx.x * blockDim.x + threadIdx.x;
    if (p >= N_EDGES) return;
    int4 v = esd[p];
    srcs[p] = v.x;
    dsts[p] = v.y;
    const float4* s = (const float4*)&ea[(size_t)v.z * 32];
    __half* d = &eas[(size_t)p * 32];
#pragma unroll
    for (int j = 0; j < 4; j++) {
        float4 a = s[j * 2];
        float4 b = s[j * 2 + 1];
        half2 h0 = __floats2half2_rn(a.x, a.y);
        half2 h1 = __floats2half2_rn(a.z, a.w);
        half2 h2 = __floats2half2_rn(b.x, b.y);
        half2 h3 = __floats2half2_rn(b.z, b.w);
        uint4 pk;
        pk.x = *(unsigned*)&h0; pk.y = *(unsigned*)&h1;
        pk.z = *(unsigned*)&h2; pk.w = *(unsigned*)&h3;
        *(uint4*)&d[j * 8] = pk;
    }
}

// ---------------- node projection after conv1 (grid-stride) ----------------
__global__ void k_node1(const float* __restrict__ x, const float* __restrict__ agg,
                        const float* __restrict__ Wp, const float* __restrict__ bp,
                        float* __restrict__ h, __half* __restrict__ hh) {
    int i = blockIdx.x * blockDim.x + threadIdx.x;
    int stride = gridDim.x * blockDim.x;
    for (; i < N_NODES * HID; i += stride) {
        int n = i >> 7;
        int c = i & 127;
        float s0 = x[n * 3 + 0] + agg[n * 3 + 0];
        float s1 = x[n * 3 + 1] + agg[n * 3 + 1];
        float s2 = x[n * 3 + 2] + agg[n * 3 + 2];
        float v = bp[c] + s0 * Wp[c] + s1 * Wp[128 + c] + s2 * Wp[256 + c];
        v = fmaxf(v, 0.0f);
        h[i] = v;
        hh[i] = __float2half_rn(v);
    }
}

// ---------------- fused 4-part node projection (interleaved f/s output) ----------------
#define PJ_S 136
__global__ __launch_bounds__(256, 3) void k_proj_all(
        const __half* __restrict__ hh,
        const float* __restrict__ Wf, const float* __restrict__ Ws,
        const float* __restrict__ bf, const float* __restrict__ bs,
        __half* __restrict__ PA, __half* __restrict__ PB) {
    extern __shared__ __half psm[];
    __half* hs  = psm;                 // [128 rows][136]
    __half* wsT = psm + 128 * PJ_S;    // [128 cols][136 k]

    int t = threadIdx.x;
    int lane = t & 31;
    int w = t >> 5;
    int g = lane >> 2;
    int tig = lane & 3;
    int n0 = blockIdx.x * 128;

#pragma unroll
    for (int j = 0; j < 8; j++) {
        int idx = t + j * 256;
        int row = idx >> 4;
        int c = (idx & 15) * 8;
        uint4 v = make_uint4(0, 0, 0, 0);
        int n = n0 + row;
        if (n < N_NODES) v = *(const uint4*)&hh[(size_t)n * 128 + c];
        *(uint4*)&hs[row * PJ_S + c] = v;
    }

    int r0 = w * 16;
#pragma unroll 1
    for (int part = 0; part < 4; part++) {
        const float* W; const float* bias; __half* out; int sOff;
        if (part == 0)      { W = Wf;             bias = bf;      out = PA; sOff = 0; }
        else if (part == 1) { W = Ws;             bias = bs;      out = PA; sOff = 4; }
        else if (part == 2) { W = Wf + 128 * 128; bias = nullptr; out = PB; sOff = 0; }
        else                { W = Ws + 128 * 128; bias = nullptr; out = PB; sOff = 4; }

        __syncthreads();
#pragma unroll
        for (int j = 0; j < 16; j++) {
            int idx4 = t + j * 256;
            int k = idx4 >> 5;
            int c = (idx4 & 31) * 4;
            float4 v = *(const float4*)&W[k * 128 + c];
            wsT[(c + 0) * PJ_S + k] = __float2half_rn(v.x);
            wsT[(c + 1) * PJ_S + k] = __float2half_rn(v.y);
            wsT[(c + 2) * PJ_S + k] = __float2half_rn(v.z);
            wsT[(c + 3) * PJ_S + k] = __float2half_rn(v.w);
        }
        __syncthreads();

#pragma unroll
        for (int h2i = 0; h2i < 2; h2i++) {
            float acc[8][4];
#pragma unroll
            for (int i = 0; i < 8; i++)
#pragma unroll
                for (int j = 0; j < 4; j++) acc[i][j] = 0.0f;
#pragma unroll
            for (int kb8 = 0; kb8 < 8; kb8++) {
                int kb = kb8 * 16;
                unsigned a0 = *(const unsigned*)&hs[(r0 + g) * PJ_S + kb + 2 * tig];
                unsigned a1 = *(const unsigned*)&hs[(r0 + g + 8) * PJ_S + kb + 2 * tig];
                unsigned a2 = *(const unsigned*)&hs[(r0 + g) * PJ_S + kb + 2 * tig + 8];
                unsigned a3 = *(const unsigned*)&hs[(r0 + g + 8) * PJ_S + kb + 2 * tig + 8];
#pragma unroll
                for (int nt = 0; nt < 8; nt++) {
                    int col = h2i * 64 + nt * 8 + g;
                    unsigned b0 = *(const unsigned*)&wsT[col * PJ_S + kb + 2 * tig];
                    unsigned b1 = *(const unsigned*)&wsT[col * PJ_S + kb + 2 * tig + 8];
                    mma_f16(acc[nt], a0, a1, a2, a3, b0, b1);
                }
            }
#pragma unroll
            for (int nt = 0; nt < 8; nt++) {
                int c = h2i * 64 + nt * 8 + 2 * tig;
                int pos = ((c >> 2) * 8) + (c & 3) + sOff;   // interleaved f/s
                float b0 = 0.f, b1 = 0.f;
                if (bias) { b0 = bias[c]; b1 = bias[c + 1]; }
                int n = n0 + r0 + g;
                if (n < N_NODES)
                    *(half2*)&out[(size_t)n * 256 + pos] =
                        __floats2half2_rn(acc[nt][0] + b0, acc[nt][1] + b1);
                n = n0 + r0 + g + 8;
                if (n < N_NODES)
                    *(half2*)&out[(size_t)n * 256 + pos] =
                        __floats2half2_rn(acc[nt][2] + b0, acc[nt][3] + b1);
            }
        }
    }
}

// ---------------- fused edge kernel over CSR-sorted edges ----------------
#define WT_S 40
#define EA_S 40
#define EH_S 264
__global__ __launch_bounds__(256, 3) void k_edge_fused(
        const int* __restrict__ srcs, const int* __restrict__ dsts,
        const __half* __restrict__ eas,
        const __half* __restrict__ PA, const __half* __restrict__ PB,
        const float* __restrict__ Wf, const float* __restrict__ Ws,
        float* __restrict__ agg) {
    extern __shared__ __half sm[];
    __half* wsT  = sm;
    __half* seas = sm + 256 * WT_S;
    __half* Eh   = sm + 256 * WT_S + 64 * EA_S;

    int t = threadIdx.x;
    int lane = t & 31;
    int w = t >> 5;
    int g = lane >> 2;
    int tig = lane & 3;

#pragma unroll
    for (int j = 0; j < 32; j++) {
        int idx = t + j * 256;
        int k = idx >> 8;
        int c = idx & 255;
        float v = (c < 128) ? Wf[(256 + k) * 128 + c]
                            : Ws[(256 + k) * 128 + (c - 128)];
        wsT[c * WT_S + k] = __float2half_rn(v);
    }
    __syncthreads();

    int erow0 = (w & 3) * 16;
    int col0 = (w >> 2) * 128;
    int sOff = (w >> 2) * 4;     // warps 4-7 compute s-part -> interleave offset +4
    const half2 nl2e = __floats2half2_rn(-1.44269504f, -1.44269504f);

    for (int tile = blockIdx.x; tile < NTILES; tile += gridDim.x) {
        long e0 = (long)tile * ETILE;
        {
            uint4 v = *(const uint4*)&eas[e0 * 32 + t * 8];
            int row = t >> 2;
            int c = (t & 3) * 8;
            *(uint4*)&seas[row * EA_S + c] = v;
        }
        __syncthreads();

        // phase 1: E = ea @ [Wef|Wes], stored interleaved f/s
#pragma unroll
        for (int h2i = 0; h2i < 2; h2i++) {
            float acc[8][4];
#pragma unroll
            for (int i = 0; i < 8; i++)
#pragma unroll
                for (int j = 0; j < 4; j++) acc[i][j] = 0.0f;
#pragma unroll
            for (int ks = 0; ks < 2; ks++) {
                int kb = ks * 16;
                unsigned a0 = *(const unsigned*)&seas[(erow0 + g) * EA_S + kb + 2 * tig];
                unsigned a1 = *(const unsigned*)&seas[(erow0 + g + 8) * EA_S + kb + 2 * tig];
                unsigned a2 = *(const unsigned*)&seas[(erow0 + g) * EA_S + kb + 2 * tig + 8];
                unsigned a3 = *(const unsigned*)&seas[(erow0 + g + 8) * EA_S + kb + 2 * tig + 8];
#pragma unroll
                for (int nt = 0; nt < 8; nt++) {
                    int col = col0 + h2i * 64 + nt * 8 + g;
                    unsigned b0 = *(const unsigned*)&wsT[col * WT_S + kb + 2 * tig];
                    unsigned b1 = *(const unsigned*)&wsT[col * WT_S + kb + 2 * tig + 8];
                    mma_f16(acc[nt], a0, a1, a2, a3, b0, b1);
                }
            }
#pragma unroll
            for (int nt = 0; nt < 8; nt++) {
                int cc = h2i * 64 + nt * 8 + 2 * tig;          // local col within part
                int pos = ((cc >> 2) * 8) + (cc & 3) + sOff;   // interleaved position
                *(half2*)&Eh[(erow0 + g) * EH_S + pos]     = __floats2half2_rn(acc[nt][0], acc[nt][1]);
                *(half2*)&Eh[(erow0 + g + 8) * EH_S + pos] = __floats2half2_rn(acc[nt][2], acc[nt][3]);
            }
        }
        __syncthreads();

        // phase 2: single-LDG.128 gathers, reduced-MUFU gating, grouped flush
        {
            int srcs8[8], dsts8[8];
#pragma unroll
            for (int j = 0; j < 8; j++) {
                long e = e0 + w * 8 + j;
                srcs8[j] = srcs[e];
                dsts8[j] = dsts[e];
            }
            uint4 pb[8];
#pragma unroll
            for (int j = 0; j < 8; j++)
                pb[j] = *(const uint4*)&PB[(size_t)srcs8[j] * 256 + lane * 8];

            int prev = -1;
            float4 acc = make_float4(0.f, 0.f, 0.f, 0.f);
            half2 af01, af23, as01, as23;
            af01 = af23 = as01 = as23 = __floats2half2_rn(0.f, 0.f);
#pragma unroll
            for (int j = 0; j < 8; j++) {
                int le = w * 8 + j;
                int dst = dsts8[j];
                if (dst != prev) {
                    if (prev >= 0)
                        red4(&agg[(size_t)prev * HID + lane * 4], acc);
                    acc = make_float4(0.f, 0.f, 0.f, 0.f);
                    uint4 pa = *(const uint4*)&PA[(size_t)dst * 256 + lane * 8];
                    af01 = *(half2*)&pa.x; af23 = *(half2*)&pa.y;
                    as01 = *(half2*)&pa.z; as23 = *(half2*)&pa.w;
                    prev = dst;
                }
                uint4 ev = *(const uint4*)&Eh[le * EH_S + lane * 8];

                half2 lf01 = __hadd2(__hadd2(*(half2*)&ev.x, af01), *(half2*)&pb[j].x);
                half2 lf23 = __hadd2(__hadd2(*(half2*)&ev.y, af23), *(half2*)&pb[j].y);
                half2 ls01 = __hadd2(__hadd2(*(half2*)&ev.z, as01), *(half2*)&pb[j].z);
                half2 ls23 = __hadd2(__hadd2(*(half2*)&ev.w, as23), *(half2*)&pb[j].w);

                half2 e01 = __hmul2(__habs2(ls01), nl2e);
                half2 e23 = __hmul2(__habs2(ls23), nl2e);
                unsigned tu01 = h2exp2_(*(unsigned*)&e01);
                unsigned tu23 = h2exp2_(*(unsigned*)&e23);

                float2 f0 = __half22float2(lf01), f1 = __half22float2(lf23);
                float2 s0 = __half22float2(ls01), s1 = __half22float2(ls23);
                float2 t0 = __half22float2(*(half2*)&tu01), t1 = __half22float2(*(half2*)&tu23);

                float sg0 = fmaf(tanha_(0.5f * f0.x), 0.5f, 0.5f);
                float sg1 = fmaf(tanha_(0.5f * f0.y), 0.5f, 0.5f);
                float sg2 = fmaf(tanha_(0.5f * f1.x), 0.5f, 0.5f);
                float sg3 = fmaf(tanha_(0.5f * f1.y), 0.5f, 0.5f);

                float sp0 = fmaxf(s0.x, 0.f) + __logf(1.f + t0.x);
                float sp1 = fmaxf(s0.y, 0.f) + __logf(1.f + t0.y);
                float sp2 = fmaxf(s1.x, 0.f) + __logf(1.f + t1.x);
                float sp3 = fmaxf(s1.y, 0.f) + __logf(1.f + t1.y);

                acc.x = fmaf(sg0, sp0, acc.x);
                acc.y = fmaf(sg1, sp1, acc.y);
                acc.z = fmaf(sg2, sp2, acc.z);
                acc.w = fmaf(sg3, sp3, acc.w);
            }
            if (prev >= 0)
                red4(&agg[(size_t)prev * HID + lane * 4], acc);
        }
        __syncthreads();
    }
}

// ---------------- residual + relu (+ fp16 mirror) ----------------
__global__ void k_update(float* __restrict__ h, __half* __restrict__ hh,
                         const float* __restrict__ agg, int n) {
    int i = blockIdx.x * blockDim.x + threadIdx.x;
    int stride = gridDim.x * blockDim.x;
    for (; i < n; i += stride) {
        float v = fmaxf(h[i] + agg[i], 0.0f);
        h[i] = v;
        hh[i] = __float2half_rn(v);
    }
}

// ---------------- fused last update + pooling (batch sorted) ----------------
__global__ void k_update_pool(const float* __restrict__ h, const float* __restrict__ agg,
                              const int* __restrict__ batch,
                              float* __restrict__ pool, float* __restrict__ cnt) {
    const int NPB = 256;
    int n0 = blockIdx.x * NPB;
    if (n0 >= N_NODES) return;
    int c = threadIdx.x;  // 128
    float s = 0.0f;
    int cur = batch[n0];
    int mycnt = 0;
    for (int i = 0; i < NPB; i++) {
        int n = n0 + i;
        if (n >= N_NODES) break;
        int b = batch[n];
        if (b != cur) {
            atomicAdd(&pool[cur * HID + c], s);
            if (c == 0) atomicAdd(&cnt[cur], (float)mycnt);
            s = 0.0f; mycnt = 0; cur = b;
        }
        s += fmaxf(h[(size_t)n * HID + c] + agg[(size_t)n * HID + c], 0.0f);
        mycnt++;
    }
    atomicAdd(&pool[cur * HID + c], s);
    if (c == 0) atomicAdd(&cnt[cur], (float)mycnt);
}

// ---------------- head ----------------
__global__ void k_head(const float* __restrict__ pool, const float* __restrict__ cnt,
                       const float* __restrict__ W1, const float* __restrict__ b1,
                       const float* __restrict__ W2, const float* __restrict__ b2,
                       float* __restrict__ out) {
    int g = blockIdx.x;
    int c = threadIdx.x;
    __shared__ float p[128];
    __shared__ float t1[128];
    float invc = 1.0f / fmaxf(cnt[g], 1.0f);
    p[c] = pool[g * HID + c] * invc;
    __syncthreads();
    float v = b1[c];
#pragma unroll 16
    for (int k = 0; k < 128; k++) v += p[k] * W1[k * 128 + c];
    t1[c] = fmaxf(v, 0.0f);
    __syncthreads();
    if (c < 3) {
        float o = b2[c];
        for (int k = 0; k < 128; k++) o += t1[k] * W2[k * 3 + c];
        out[g * 3 + c] = o;
    }
}

// ---------------- launch ----------------
extern "C" void kernel_launch(void* const* d_in, const int* in_sizes, int n_in,
                              void* d_out, int out_size) {
    const float* x   = (const float*)d_in[0];
    const int*   ei  = (const int*)d_in[1];
    const float* ea  = (const float*)d_in[2];
    const int*   bat = (const int*)d_in[3];
    const float* Wf1 = (const float*)d_in[4];
    const float* bf1 = (const float*)d_in[5];
    const float* Ws1 = (const float*)d_in[6];
    const float* bs1 = (const float*)d_in[7];
    const float* Wp  = (const float*)d_in[8];
    const float* bp  = (const float*)d_in[9];
    const float* Wc[2]  = { (const float*)d_in[10], (const float*)d_in[14] };
    const float* bcf[2] = { (const float*)d_in[11], (const float*)d_in[15] };
    const float* Wsc[2] = { (const float*)d_in[12], (const float*)d_in[16] };
    const float* bcs[2] = { (const float*)d_in[13], (const float*)d_in[17] };
    const float* W1  = (const float*)d_in[18];
    const float* b1  = (const float*)d_in[19];
    const float* W2  = (const float*)d_in[20];
    const float* b2  = (const float*)d_in[21];
    float* out = (float*)d_out;

    float *pH, *pAgg, *pPool;
    __half *pPA, *pPB, *pHH, *pEAS;
    int *pDeg, *pCur, *pPart, *pSrcs, *pDsts;
    int4 *pEsd;
    cudaGetSymbolAddress((void**)&pH,    g_h);
    cudaGetSymbolAddress((void**)&pHH,   g_hh);
    cudaGetSymbolAddress((void**)&pPA,   g_PA);
    cudaGetSymbolAddress((void**)&pPB,   g_PB);
    cudaGetSymbolAddress((void**)&pAgg,  g_agg);
    cudaGetSymbolAddress((void**)&pPool, g_pool);
    cudaGetSymbolAddress((void**)&pDeg,  g_deg);
    cudaGetSymbolAddress((void**)&pCur,  g_cursor);
    cudaGetSymbolAddress((void**)&pPart, g_part);
    cudaGetSymbolAddress((void**)&pEsd,  g_esd);
    cudaGetSymbolAddress((void**)&pSrcs, g_srcs);
    cudaGetSymbolAddress((void**)&pDsts, g_dsts);
    cudaGetSymbolAddress((void**)&pEAS,  g_eas);

    const int EDGE_SMEM = (256 * WT_S + 64 * EA_S + 64 * EH_S) * 2;
    const int PROJ_SMEM = 2 * 128 * PJ_S * 2;
    cudaFuncSetAttribute(k_edge_fused, cudaFuncAttributeMaxDynamicSharedMemorySize, EDGE_SMEM);
    cudaFuncSetAttribute(k_proj_all, cudaFuncAttributeMaxDynamicSharedMemorySize, PROJ_SMEM);

    // ---- zeroing via graph memset nodes ----
    cudaMemsetAsync(pDeg, 0, N_NODES * sizeof(int));
    cudaMemsetAsync(pAgg, 0, N_NODES * 3 * sizeof(float));
    cudaMemsetAsync(pPool, 0, (NGRAPH * HID + NGRAPH) * sizeof(float));

    // ---- build CSR + conv1 ----
    k_hist<<<N_EDGES / 256, 256>>>(ei, pDeg);
    k_scan_a<<<SCAN_NB, SCAN_B>>>(pDeg, pCur, pPart);
    k_scan_b<<<1, 256>>>(pPart, SCAN_NB);
    k_conv1_perm<<<N_EDGES / 256, 256>>>(x, ei, ea, Wf1, bf1, Ws1, bs1,
                                         pCur, pPart, pEsd, pAgg);
    k_gather<<<N_EDGES / 256, 256>>>(pEsd, ea, pSrcs, pDsts, pEAS);
    k_node1<<<592, 256>>>(x, pAgg, Wp, bp, pH, pHH);

    // ---- hidden convs ----
    for (int l = 0; l < 2; l++) {
        k_proj_all<<<(N_NODES + 127) / 128, 256, PROJ_SMEM>>>(
            pHH, Wc[l], Wsc[l], bcf[l], bcs[l], pPA, pPB);
        cudaMemsetAsync(pAgg, 0, (size_t)N_NODES * HID * sizeof(float));
        k_edge_fused<<<444, 256, EDGE_SMEM>>>(pSrcs, pDsts, pEAS, pPA, pPB,
                                              Wc[l], Wsc[l], pAgg);
        if (l == 0)
            k_update<<<2048, 256>>>(pH, pHH, pAgg, N_NODES * HID);
        else
            k_update_pool<<<(N_NODES + 255) / 256, 128>>>(pH, pAgg, bat,
                                                          pPool, pPool + NGRAPH * HID);
    }

    // ---- head ----
    k_head<<<NGRAPH, 128>>>(pPool, pPool + NGRAPH * HID, W1, b1, W2, b2, out);
}

// round 11
// speedup vs baseline: 1.0624x; 1.0624x over previous
#include <cuda_runtime.h>
#include <cuda_fp16.h>
#include <math.h>

#define N_NODES 100000
#define N_EDGES 1600000
#define HID 128
#define NGRAPH 64
#define ETILE 64
#define NTILES (N_EDGES / ETILE)
#define SCAN_B 512
#define SCAN_NB ((N_NODES + SCAN_B - 1) / SCAN_B)   // 196

// ---------------- device scratch ----------------
__device__ float  g_h[N_NODES * HID];
__device__ __half g_hh[N_NODES * HID];
__device__ __half g_PA[N_NODES * 256];   // [f(128) | s(128)] per node (+bias)
__device__ __half g_PB[N_NODES * 256];
__device__ float  g_agg[N_NODES * HID];
__device__ float  g_pool[NGRAPH * HID + NGRAPH];
__device__ int    g_deg[N_NODES];
__device__ int    g_cursor[N_NODES];
__device__ int    g_part[256];
__device__ int4   g_esd[N_EDGES];
__device__ int    g_srcs[N_EDGES];
__device__ int    g_dsts[N_EDGES];
__device__ __half g_eas[(size_t)N_EDGES * 32];

// ---------------- helpers ----------------
__device__ __forceinline__ float sigmoidf_(float x) { return 1.0f / (1.0f + __expf(-x)); }
__device__ __forceinline__ float softplusf_(float x) {
    return fmaxf(x, 0.0f) + __logf(1.0f + __expf(-fabsf(x)));
}
__device__ __forceinline__ float tanha_(float x) {
    float y;
    asm("tanh.approx.f32 %0, %1;" : "=f"(y) : "f"(x));
    return y;
}
__device__ __forceinline__ half2 ex2h2_(half2 x) {
    unsigned y;
    asm("ex2.approx.f16x2 %0, %1;" : "=r"(y) : "r"(*(unsigned*)&x));
    return *(half2*)&y;
}
__device__ __forceinline__ void red4(float* p, float4 v) {
    asm volatile("red.global.add.v4.f32 [%0], {%1,%2,%3,%4};"
                 :: "l"(p), "f"(v.x), "f"(v.y), "f"(v.z), "f"(v.w));
}
__device__ __forceinline__ void mma_f16(float d[4],
                                        unsigned a0, unsigned a1, unsigned a2, unsigned a3,
                                        unsigned b0, unsigned b1) {
    asm volatile("mma.sync.aligned.m16n8k16.row.col.f32.f16.f16.f32 "
                 "{%0,%1,%2,%3}, {%4,%5,%6,%7}, {%8,%9}, {%0,%1,%2,%3};\n"
                 : "+f"(d[0]), "+f"(d[1]), "+f"(d[2]), "+f"(d[3])
                 : "r"(a0), "r"(a1), "r"(a2), "r"(a3), "r"(b0), "r"(b1));
}

// ---------------- CSR build ----------------
__global__ void k_hist(const int* __restrict__ ei, int* __restrict__ deg) {
    int e = blockIdx.x * blockDim.x + threadIdx.x;
    if (e < N_EDGES) atomicAdd(&deg[ei[N_EDGES + e]], 1);
}
__global__ void k_scan_a(const int* __restrict__ deg, int* __restrict__ cursor,
                         int* __restrict__ part) {
    __shared__ int s[SCAN_B];
    int i = blockIdx.x * SCAN_B + threadIdx.x;
    int v = (i < N_NODES) ? deg[i] : 0;
    s[threadIdx.x] = v;
    __syncthreads();
    for (int off = 1; off < SCAN_B; off <<= 1) {
        int t = (threadIdx.x >= off) ? s[threadIdx.x - off] : 0;
        __syncthreads();
        s[threadIdx.x] += t;
        __syncthreads();
    }
    if (i < N_NODES) cursor[i] = s[threadIdx.x] - v;
    if (threadIdx.x == SCAN_B - 1) part[blockIdx.x] = s[threadIdx.x];
}
__global__ void k_scan_b(int* __restrict__ part, int nb) {
    __shared__ int s[256];
    int v = (threadIdx.x < nb) ? part[threadIdx.x] : 0;
    s[threadIdx.x] = v;
    __syncthreads();
    for (int off = 1; off < 256; off <<= 1) {
        int t = (threadIdx.x >= off) ? s[threadIdx.x - off] : 0;
        __syncthreads();
        s[threadIdx.x] += t;
        __syncthreads();
    }
    if (threadIdx.x < nb) part[threadIdx.x] = s[threadIdx.x] - v;
}

// ---------------- pass 1: conv1 + light permutation scatter (no local arrays) ----------------
__global__ void k_conv1_perm(const float* __restrict__ x, const int* __restrict__ ei,
                             const float* __restrict__ ea,
                             const float* __restrict__ Wf, const float* __restrict__ bf,
                             const float* __restrict__ Ws, const float* __restrict__ bs,
                             int* __restrict__ cursor, const int* __restrict__ part,
                             int4* __restrict__ esd, float* __restrict__ agg) {
    __shared__ float sWf[38 * 3], sWs[38 * 3], sbf[3], sbs[3];
    int t = threadIdx.x;
    if (t < 114) { sWf[t] = Wf[t]; sWs[t] = Ws[t]; }
    if (t < 3)   { sbf[t] = bf[t]; sbs[t] = bs[t]; }
    __syncthreads();
    int e = blockIdx.x * blockDim.x + t;
    if (e >= N_EDGES) return;
    int src = ei[e];
    int dst = ei[N_EDGES + e];

    float lf0 = sbf[0], lf1 = sbf[1], lf2 = sbf[2];
    float ls0 = sbs[0], ls1 = sbs[1], ls2 = sbs[2];

    // x parts (rows 0..5)
    {
        float xz0 = x[dst * 3 + 0], xz1 = x[dst * 3 + 1], xz2 = x[dst * 3 + 2];
        float xz3 = x[src * 3 + 0], xz4 = x[src * 3 + 1], xz5 = x[src * 3 + 2];
        float zz[6] = { xz0, xz1, xz2, xz3, xz4, xz5 };
#pragma unroll
        for (int r = 0; r < 6; r++) {
            float zv = zz[r];
            lf0 = fmaf(zv, sWf[r * 3 + 0], lf0);
            lf1 = fmaf(zv, sWf[r * 3 + 1], lf1);
            lf2 = fmaf(zv, sWf[r * 3 + 2], lf2);
            ls0 = fmaf(zv, sWs[r * 3 + 0], ls0);
            ls1 = fmaf(zv, sWs[r * 3 + 1], ls1);
            ls2 = fmaf(zv, sWs[r * 3 + 2], ls2);
        }
    }
    // edge-attr rows 6..37, accumulate on the fly (no z materialization)
    const float4* s = (const float4*)&ea[(size_t)e * 32];
#pragma unroll
    for (int j = 0; j < 8; j++) {
        float4 v = s[j];
        float q[4] = { v.x, v.y, v.z, v.w };
#pragma unroll
        for (int k = 0; k < 4; k++) {
            int r = 6 + j * 4 + k;
            float zv = q[k];
            lf0 = fmaf(zv, sWf[r * 3 + 0], lf0);
            lf1 = fmaf(zv, sWf[r * 3 + 1], lf1);
            lf2 = fmaf(zv, sWf[r * 3 + 2], lf2);
            ls0 = fmaf(zv, sWs[r * 3 + 0], ls0);
            ls1 = fmaf(zv, sWs[r * 3 + 1], ls1);
            ls2 = fmaf(zv, sWs[r * 3 + 2], ls2);
        }
    }
    atomicAdd(&agg[dst * 3 + 0], sigmoidf_(lf0) * softplusf_(ls0));
    atomicAdd(&agg[dst * 3 + 1], sigmoidf_(lf1) * softplusf_(ls1));
    atomicAdd(&agg[dst * 3 + 2], sigmoidf_(lf2) * softplusf_(ls2));

    int pos = atomicAdd(&cursor[dst], 1) + part[dst >> 9];
    esd[pos] = make_int4(src, dst, e, 0);
}

// ---------------- pass 2: coalesced gather-convert ----------------
__global__ void k_gather(const int4* __restrict__ esd, const float* __restrict__ ea,
                         int* __restrict__ srcs, int* __restrict__ dsts,
                         __half* __restrict__ eas) {
    int p = blockIdx.x * blockDim.x + threadIdx.x;
    if (p >= N_EDGES) return;
    int4 v = esd[p];
    srcs[p] = v.x;
    dsts[p] = v.y;
    const float4* s = (const float4*)&ea[(size_t)v.z * 32];
    __half* d = &eas[(size_t)p * 32];
#pragma unroll
    for (int j = 0; j < 4; j++) {
        float4 a = s[j * 2];
        float4 b = s[j * 2 + 1];
        half2 h0 = __floats2half2_rn(a.x, a.y);
        half2 h1 = __floats2half2_rn(a.z, a.w);
        half2 h2 = __floats2half2_rn(b.x, b.y);
        half2 h3 = __floats2half2_rn(b.z, b.w);
        uint4 pk;
        pk.x = *(unsigned*)&h0; pk.y = *(unsigned*)&h1;
        pk.z = *(unsigned*)&h2; pk.w = *(unsigned*)&h3;
        *(uint4*)&d[j * 8] = pk;
    }
}

// ---------------- node projection after conv1 (grid-stride) ----------------
__global__ void k_node1(const float* __restrict__ x, const float* __restrict__ agg,
                        const float* __restrict__ Wp, const float* __restrict__ bp,
                        float* __restrict__ h, __half* __restrict__ hh) {
    int i = blockIdx.x * blockDim.x + threadIdx.x;
    int stride = gridDim.x * blockDim.x;
    for (; i < N_NODES * HID; i += stride) {
        int n = i >> 7;
        int c = i & 127;
        float s0 = x[n * 3 + 0] + agg[n * 3 + 0];
        float s1 = x[n * 3 + 1] + agg[n * 3 + 1];
        float s2 = x[n * 3 + 2] + agg[n * 3 + 2];
        float v = bp[c] + s0 * Wp[c] + s1 * Wp[128 + c] + s2 * Wp[256 + c];
        v = fmaxf(v, 0.0f);
        h[i] = v;
        hh[i] = __float2half_rn(v);
    }
}

// ---------------- fused 4-part node projection (round-9 layout) ----------------
#define PJ_S 136
__global__ __launch_bounds__(256, 3) void k_proj_all(
        const __half* __restrict__ hh,
        const float* __restrict__ Wf, const float* __restrict__ Ws,
        const float* __restrict__ bf, const float* __restrict__ bs,
        __half* __restrict__ PA, __half* __restrict__ PB) {
    extern __shared__ __half psm[];
    __half* hs  = psm;                 // [128 rows][136]
    __half* wsT = psm + 128 * PJ_S;    // [128 cols][136 k]

    int t = threadIdx.x;
    int lane = t & 31;
    int w = t >> 5;
    int g = lane >> 2;
    int tig = lane & 3;
    int n0 = blockIdx.x * 128;

#pragma unroll
    for (int j = 0; j < 8; j++) {
        int idx = t + j * 256;
        int row = idx >> 4;
        int c = (idx & 15) * 8;
        uint4 v = make_uint4(0, 0, 0, 0);
        int n = n0 + row;
        if (n < N_NODES) v = *(const uint4*)&hh[(size_t)n * 128 + c];
        *(uint4*)&hs[row * PJ_S + c] = v;
    }

    int r0 = w * 16;
#pragma unroll 1
    for (int part = 0; part < 4; part++) {
        const float* W; const float* bias; __half* out; int coloff;
        if (part == 0)      { W = Wf;             bias = bf;      out = PA; coloff = 0;   }
        else if (part == 1) { W = Ws;             bias = bs;      out = PA; coloff = 128; }
        else if (part == 2) { W = Wf + 128 * 128; bias = nullptr; out = PB; coloff = 0;   }
        else                { W = Ws + 128 * 128; bias = nullptr; out = PB; coloff = 128; }

        __syncthreads();
#pragma unroll
        for (int j = 0; j < 16; j++) {
            int idx4 = t + j * 256;
            int k = idx4 >> 5;
            int c = (idx4 & 31) * 4;
            float4 v = *(const float4*)&W[k * 128 + c];
            wsT[(c + 0) * PJ_S + k] = __float2half_rn(v.x);
            wsT[(c + 1) * PJ_S + k] = __float2half_rn(v.y);
            wsT[(c + 2) * PJ_S + k] = __float2half_rn(v.z);
            wsT[(c + 3) * PJ_S + k] = __float2half_rn(v.w);
        }
        __syncthreads();

#pragma unroll
        for (int h2i = 0; h2i < 2; h2i++) {
            float acc[8][4];
#pragma unroll
            for (int i = 0; i < 8; i++)
#pragma unroll
                for (int j = 0; j < 4; j++) acc[i][j] = 0.0f;
#pragma unroll
            for (int kb8 = 0; kb8 < 8; kb8++) {
                int kb = kb8 * 16;
                unsigned a0 = *(const unsigned*)&hs[(r0 + g) * PJ_S + kb + 2 * tig];
                unsigned a1 = *(const unsigned*)&hs[(r0 + g + 8) * PJ_S + kb + 2 * tig];
                unsigned a2 = *(const unsigned*)&hs[(r0 + g) * PJ_S + kb + 2 * tig + 8];
                unsigned a3 = *(const unsigned*)&hs[(r0 + g + 8) * PJ_S + kb + 2 * tig + 8];
#pragma unroll
                for (int nt = 0; nt < 8; nt++) {
                    int col = h2i * 64 + nt * 8 + g;
                    unsigned b0 = *(const unsigned*)&wsT[col * PJ_S + kb + 2 * tig];
                    unsigned b1 = *(const unsigned*)&wsT[col * PJ_S + kb + 2 * tig + 8];
                    mma_f16(acc[nt], a0, a1, a2, a3, b0, b1);
                }
            }
#pragma unroll
            for (int nt = 0; nt < 8; nt++) {
                int c = h2i * 64 + nt * 8 + 2 * tig;
                float b0 = 0.f, b1 = 0.f;
                if (bias) { b0 = bias[c]; b1 = bias[c + 1]; }
                int n = n0 + r0 + g;
                if (n < N_NODES)
                    *(half2*)&out[(size_t)n * 256 + coloff + c] =
                        __floats2half2_rn(acc[nt][0] + b0, acc[nt][1] + b1);
                n = n0 + r0 + g + 8;
                if (n < N_NODES)
                    *(half2*)&out[(size_t)n * 256 + coloff + c] =
                        __floats2half2_rn(acc[nt][2] + b0, acc[nt][3] + b1);
            }
        }
    }
}

// ---------------- fused edge kernel (round-9 layout, poly softplus) ----------------
#define WT_S 40
#define EA_S 40
#define EH_S 264
__global__ __launch_bounds__(256, 3) void k_edge_fused(
        const int* __restrict__ srcs, const int* __restrict__ dsts,
        const __half* __restrict__ eas,
        const __half* __restrict__ PA, const __half* __restrict__ PB,
        const float* __restrict__ Wf, const float* __restrict__ Ws,
        float* __restrict__ agg) {
    extern __shared__ __half sm[];
    __half* wsT  = sm;
    __half* seas = sm + 256 * WT_S;
    __half* Eh   = sm + 256 * WT_S + 64 * EA_S;

    int t = threadIdx.x;
    int lane = t & 31;
    int w = t >> 5;
    int g = lane >> 2;
    int tig = lane & 3;

#pragma unroll
    for (int j = 0; j < 32; j++) {
        int idx = t + j * 256;
        int k = idx >> 8;
        int c = idx & 255;
        float v = (c < 128) ? Wf[(256 + k) * 128 + c]
                            : Ws[(256 + k) * 128 + (c - 128)];
        wsT[c * WT_S + k] = __float2half_rn(v);
    }
    __syncthreads();

    int erow0 = (w & 3) * 16;
    int col0 = (w >> 2) * 128;
    const half2 nl2e = __floats2half2_rn(-1.44269504f, -1.44269504f);
    const half2 two2 = __floats2half2_rn(2.f, 2.f);
    const half2 m1h  = __floats2half2_rn(-1.f, -1.f);
    const half2 zr2  = __floats2half2_rn(0.f, 0.f);
    // deg-5 Chebyshev-derived monomial coeffs of log1p(t) in u = 2t-1
    const half2 c0h = __floats2half2_rn(0.405542f, 0.405542f);
    const half2 c1h = __floats2half2_rn(0.333342f, 0.333342f);
    const half2 c2h = __floats2half2_rn(-0.0554078f, -0.0554078f);
    const half2 c3h = __floats2half2_rn(0.0122789f, 0.0122789f);
    const half2 c4h = __floats2half2_rn(-0.00346625f, -0.00346625f);
    const half2 c5h = __floats2half2_rn(0.000951552f, 0.000951552f);

    for (int tile = blockIdx.x; tile < NTILES; tile += gridDim.x) {
        long e0 = (long)tile * ETILE;
        {
            uint4 v = *(const uint4*)&eas[e0 * 32 + t * 8];
            int row = t >> 2;
            int c = (t & 3) * 8;
            *(uint4*)&seas[row * EA_S + c] = v;
        }
        __syncthreads();

        // phase 1: E = ea @ [Wef|Wes]
#pragma unroll
        for (int h2i = 0; h2i < 2; h2i++) {
            float acc[8][4];
#pragma unroll
            for (int i = 0; i < 8; i++)
#pragma unroll
                for (int j = 0; j < 4; j++) acc[i][j] = 0.0f;
#pragma unroll
            for (int ks = 0; ks < 2; ks++) {
                int kb = ks * 16;
                unsigned a0 = *(const unsigned*)&seas[(erow0 + g) * EA_S + kb + 2 * tig];
                unsigned a1 = *(const unsigned*)&seas[(erow0 + g + 8) * EA_S + kb + 2 * tig];
                unsigned a2 = *(const unsigned*)&seas[(erow0 + g) * EA_S + kb + 2 * tig + 8];
                unsigned a3 = *(const unsigned*)&seas[(erow0 + g + 8) * EA_S + kb + 2 * tig + 8];
#pragma unroll
                for (int nt = 0; nt < 8; nt++) {
                    int col = col0 + h2i * 64 + nt * 8 + g;
                    unsigned b0 = *(const unsigned*)&wsT[col * WT_S + kb + 2 * tig];
                    unsigned b1 = *(const unsigned*)&wsT[col * WT_S + kb + 2 * tig + 8];
                    mma_f16(acc[nt], a0, a1, a2, a3, b0, b1);
                }
            }
#pragma unroll
            for (int nt = 0; nt < 8; nt++) {
                int c = col0 + h2i * 64 + nt * 8 + 2 * tig;
                *(half2*)&Eh[(erow0 + g) * EH_S + c]     = __floats2half2_rn(acc[nt][0], acc[nt][1]);
                *(half2*)&Eh[(erow0 + g + 8) * EH_S + c] = __floats2half2_rn(acc[nt][2], acc[nt][3]);
            }
        }
        __syncthreads();

        // phase 2: prefetch-8 gather, tanh sigmoid + poly softplus, grouped flush
        {
            int srcs8[8], dsts8[8];
#pragma unroll
            for (int j = 0; j < 8; j++) {
                long e = e0 + w * 8 + j;
                srcs8[j] = srcs[e];
                dsts8[j] = dsts[e];
            }
            uint2 pbf[8], pbs[8];
#pragma unroll
            for (int j = 0; j < 8; j++) {
                size_t base = (size_t)srcs8[j] * 256 + lane * 4;
                pbf[j] = *(const uint2*)&PB[base];
                pbs[j] = *(const uint2*)&PB[base + 128];
            }
            int prev = -1;
            float4 acc = make_float4(0.f, 0.f, 0.f, 0.f);
            half2 af01, af23, as01, as23;
            af01 = af23 = as01 = as23 = __floats2half2_rn(0.f, 0.f);
#pragma unroll
            for (int j = 0; j < 8; j++) {
                int le = w * 8 + j;
                int dst = dsts8[j];
                if (dst != prev) {
                    if (prev >= 0)
                        red4(&agg[(size_t)prev * HID + lane * 4], acc);
                    acc = make_float4(0.f, 0.f, 0.f, 0.f);
                    size_t base = (size_t)dst * 256 + lane * 4;
                    uint2 pafu = *(const uint2*)&PA[base];
                    uint2 pasu = *(const uint2*)&PA[base + 128];
                    af01 = *(half2*)&pafu.x; af23 = *(half2*)&pafu.y;
                    as01 = *(half2*)&pasu.x; as23 = *(half2*)&pasu.y;
                    prev = dst;
                }
                uint2 efu = *(const uint2*)&Eh[le * EH_S + lane * 4];
                uint2 esu = *(const uint2*)&Eh[le * EH_S + 128 + lane * 4];

                half2 lf01 = __hadd2(__hadd2(*(half2*)&efu.x, af01), *(half2*)&pbf[j].x);
                half2 lf23 = __hadd2(__hadd2(*(half2*)&efu.y, af23), *(half2*)&pbf[j].y);
                half2 ls01 = __hadd2(__hadd2(*(half2*)&esu.x, as01), *(half2*)&pbs[j].x);
                half2 ls23 = __hadd2(__hadd2(*(half2*)&esu.y, as23), *(half2*)&pbs[j].y);

                // t = exp(-|s|) in (0,1], packed
                half2 t01 = ex2h2_(__hmul2(__habs2(ls01), nl2e));
                half2 t23 = ex2h2_(__hmul2(__habs2(ls23), nl2e));

                // log1p(t) ~ deg-5 Horner in u = 2t-1, packed half2
                half2 u01 = __hfma2(t01, two2, m1h);
                half2 u23 = __hfma2(t23, two2, m1h);
                half2 p01 = __hfma2(c5h, u01, c4h);
                half2 p23 = __hfma2(c5h, u23, c4h);
                p01 = __hfma2(p01, u01, c3h);  p23 = __hfma2(p23, u23, c3h);
                p01 = __hfma2(p01, u01, c2h);  p23 = __hfma2(p23, u23, c2h);
                p01 = __hfma2(p01, u01, c1h);  p23 = __hfma2(p23, u23, c1h);
                p01 = __hfma2(p01, u01, c0h);  p23 = __hfma2(p23, u23, c0h);

                // sp = max(s,0) + log1p(t)
                half2 sp01 = __hadd2(__hmax2(ls01, zr2), p01);
                half2 sp23 = __hadd2(__hmax2(ls23, zr2), p23);

                float2 f0 = __half22float2(lf01), f1 = __half22float2(lf23);
                float2 q0 = __half22float2(sp01), q1 = __half22float2(sp23);

                float sg0 = fmaf(tanha_(0.5f * f0.x), 0.5f, 0.5f);
                float sg1 = fmaf(tanha_(0.5f * f0.y), 0.5f, 0.5f);
                float sg2 = fmaf(tanha_(0.5f * f1.x), 0.5f, 0.5f);
                float sg3 = fmaf(tanha_(0.5f * f1.y), 0.5f, 0.5f);

                acc.x = fmaf(sg0, q0.x, acc.x);
                acc.y = fmaf(sg1, q0.y, acc.y);
                acc.z = fmaf(sg2, q1.x, acc.z);
                acc.w = fmaf(sg3, q1.y, acc.w);
            }
            if (prev >= 0)
                red4(&agg[(size_t)prev * HID + lane * 4], acc);
        }
        __syncthreads();
    }
}

// ---------------- residual + relu (+ fp16 mirror) ----------------
__global__ void k_update(float* __restrict__ h, __half* __restrict__ hh,
                         const float* __restrict__ agg, int n) {
    int i = blockIdx.x * blockDim.x + threadIdx.x;
    int stride = gridDim.x * blockDim.x;
    for (; i < n; i += stride) {
        float v = fmaxf(h[i] + agg[i], 0.0f);
        h[i] = v;
        hh[i] = __float2half_rn(v);
    }
}

// ---------------- fused last update + pooling (batch sorted) ----------------
__global__ void k_update_pool(const float* __restrict__ h, const float* __restrict__ agg,
                              const int* __restrict__ batch,
                              float* __restrict__ pool, float* __restrict__ cnt) {
    const int NPB = 256;
    int n0 = blockIdx.x * NPB;
    if (n0 >= N_NODES) return;
    int c = threadIdx.x;  // 128
    float s = 0.0f;
    int cur = batch[n0];
    int mycnt = 0;
    for (int i = 0; i < NPB; i++) {
        int n = n0 + i;
        if (n >= N_NODES) break;
        int b = batch[n];
        if (b != cur) {
            atomicAdd(&pool[cur * HID + c], s);
            if (c == 0) atomicAdd(&cnt[cur], (float)mycnt);
            s = 0.0f; mycnt = 0; cur = b;
        }
        s += fmaxf(h[(size_t)n * HID + c] + agg[(size_t)n * HID + c], 0.0f);
        mycnt++;
    }
    atomicAdd(&pool[cur * HID + c], s);
    if (c == 0) atomicAdd(&cnt[cur], (float)mycnt);
}

// ---------------- head ----------------
__global__ void k_head(const float* __restrict__ pool, const float* __restrict__ cnt,
                       const float* __restrict__ W1, const float* __restrict__ b1,
                       const float* __restrict__ W2, const float* __restrict__ b2,
                       float* __restrict__ out) {
    int g = blockIdx.x;
    int c = threadIdx.x;
    __shared__ float p[128];
    __shared__ float t1[128];
    float invc = 1.0f / fmaxf(cnt[g], 1.0f);
    p[c] = pool[g * HID + c] * invc;
    __syncthreads();
    float v = b1[c];
#pragma unroll 16
    for (int k = 0; k < 128; k++) v += p[k] * W1[k * 128 + c];
    t1[c] = fmaxf(v, 0.0f);
    __syncthreads();
    if (c < 3) {
        float o = b2[c];
        for (int k = 0; k < 128; k++) o += t1[k] * W2[k * 3 + c];
        out[g * 3 + c] = o;
    }
}

// ---------------- launch ----------------
extern "C" void kernel_launch(void* const* d_in, const int* in_sizes, int n_in,
                              void* d_out, int out_size) {
    const float* x   = (const float*)d_in[0];
    const int*   ei  = (const int*)d_in[1];
    const float* ea  = (const float*)d_in[2];
    const int*   bat = (const int*)d_in[3];
    const float* Wf1 = (const float*)d_in[4];
    const float* bf1 = (const float*)d_in[5];
    const float* Ws1 = (const float*)d_in[6];
    const float* bs1 = (const float*)d_in[7];
    const float* Wp  = (const float*)d_in[8];
    const float* bp  = (const float*)d_in[9];
    const float* Wc[2]  = { (const float*)d_in[10], (const float*)d_in[14] };
    const float* bcf[2] = { (const float*)d_in[11], (const float*)d_in[15] };
    const float* Wsc[2] = { (const float*)d_in[12], (const float*)d_in[16] };
    const float* bcs[2] = { (const float*)d_in[13], (const float*)d_in[17] };
    const float* W1  = (const float*)d_in[18];
    const float* b1  = (const float*)d_in[19];
    const float* W2  = (const float*)d_in[20];
    const float* b2  = (const float*)d_in[21];
    float* out = (float*)d_out;

    float *pH, *pAgg, *pPool;
    __half *pPA, *pPB, *pHH, *pEAS;
    int *pDeg, *pCur, *pPart, *pSrcs, *pDsts;
    int4 *pEsd;
    cudaGetSymbolAddress((void**)&pH,    g_h);
    cudaGetSymbolAddress((void**)&pHH,   g_hh);
    cudaGetSymbolAddress((void**)&pPA,   g_PA);
    cudaGetSymbolAddress((void**)&pPB,   g_PB);
    cudaGetSymbolAddress((void**)&pAgg,  g_agg);
    cudaGetSymbolAddress((void**)&pPool, g_pool);
    cudaGetSymbolAddress((void**)&pDeg,  g_deg);
    cudaGetSymbolAddress((void**)&pCur,  g_cursor);
    cudaGetSymbolAddress((void**)&pPart, g_part);
    cudaGetSymbolAddress((void**)&pEsd,  g_esd);
    cudaGetSymbolAddress((void**)&pSrcs, g_srcs);
    cudaGetSymbolAddress((void**)&pDsts, g_dsts);
    cudaGetSymbolAddress((void**)&pEAS,  g_eas);

    const int EDGE_SMEM = (256 * WT_S + 64 * EA_S + 64 * EH_S) * 2;
    const int PROJ_SMEM = 2 * 128 * PJ_S * 2;
    cudaFuncSetAttribute(k_edge_fused, cudaFuncAttributeMaxDynamicSharedMemorySize, EDGE_SMEM);
    cudaFuncSetAttribute(k_proj_all, cudaFuncAttributeMaxDynamicSharedMemorySize, PROJ_SMEM);

    // ---- zeroing via graph memset nodes ----
    cudaMemsetAsync(pDeg, 0, N_NODES * sizeof(int));
    cudaMemsetAsync(pAgg, 0, N_NODES * 3 * sizeof(float));
    cudaMemsetAsync(pPool, 0, (NGRAPH * HID + NGRAPH) * sizeof(float));

    // ---- build CSR + conv1 ----
    k_hist<<<N_EDGES / 256, 256>>>(ei, pDeg);
    k_scan_a<<<SCAN_NB, SCAN_B>>>(pDeg, pCur, pPart);
    k_scan_b<<<1, 256>>>(pPart, SCAN_NB);
    k_conv1_perm<<<N_EDGES / 256, 256>>>(x, ei, ea, Wf1, bf1, Ws1, bs1,
                                         pCur, pPart, pEsd, pAgg);
    k_gather<<<N_EDGES / 256, 256>>>(pEsd, ea, pSrcs, pDsts, pEAS);
    k_node1<<<592, 256>>>(x, pAgg, Wp, bp, pH, pHH);

    // ---- hidden convs ----
    for (int l = 0; l < 2; l++) {
        k_proj_all<<<(N_NODES + 127) / 128, 256, PROJ_SMEM>>>(
            pHH, Wc[l], Wsc[l], bcf[l], bcs[l], pPA, pPB);
        cudaMemsetAsync(pAgg, 0, (size_t)N_NODES * HID * sizeof(float));
        k_edge_fused<<<444, 256, EDGE_SMEM>>>(pSrcs, pDsts, pEAS, pPA, pPB,
                                              Wc[l], Wsc[l], pAgg);
        if (l == 0)
            k_update<<<2048, 256>>>(pH, pHH, pAgg, N_NODES * HID);
        else
            k_update_pool<<<(N_NODES + 255) / 256, 128>>>(pH, pAgg, bat,
                                                          pPool, pPool + NGRAPH * HID);
    }

    // ---- head ----
    k_head<<<NGRAPH, 128>>>(pPool, pPool + NGRAPH * HID, W1, b1, W2, b2, out);
}

// round 12
// speedup vs baseline: 1.2643x; 1.1900x over previous
#include <cuda_runtime.h>
#include <cuda_fp16.h>
#include <math.h>

#define N_NODES 100000
#define N_EDGES 1600000
#define HID 128
#define NGRAPH 64
#define ETILE 64
#define NTILES (N_EDGES / ETILE)
#define SCAN_B 512
#define SCAN_NB ((N_NODES + SCAN_B - 1) / SCAN_B)   // 196

// ---------------- device scratch ----------------
__device__ float  g_h[N_NODES * HID];
__device__ __half g_hh[N_NODES * HID];
__device__ __half g_PA[N_NODES * 256];   // [f(128) | s(128)] per node (+bias)
__device__ __half g_PB[N_NODES * 256];
__device__ float  g_agg[N_NODES * HID];
__device__ float  g_pool[NGRAPH * HID + NGRAPH];
__device__ int    g_deg[N_NODES];
__device__ int    g_cursor[N_NODES];
__device__ int    g_part[256];
__device__ int4   g_esd[N_EDGES];
__device__ int    g_srcs[N_EDGES];
__device__ int    g_dsts[N_EDGES];
__device__ __half g_eas[(size_t)N_EDGES * 32];
// prepped fp16 transposed weights: per layer: proj 4*128*128, edge 256*32
__device__ __half g_wTproj[2 * 4 * 128 * 128];
__device__ __half g_wTedge[2 * 256 * 32];

// ---------------- helpers ----------------
__device__ __forceinline__ float sigmoidf_(float x) { return 1.0f / (1.0f + __expf(-x)); }
__device__ __forceinline__ float softplusf_(float x) {
    return fmaxf(x, 0.0f) + __logf(1.0f + __expf(-fabsf(x)));
}
__device__ __forceinline__ float tanha_(float x) {
    float y;
    asm("tanh.approx.f32 %0, %1;" : "=f"(y) : "f"(x));
    return y;
}
__device__ __forceinline__ half2 ex2h2_(half2 x) {
    unsigned y;
    asm("ex2.approx.f16x2 %0, %1;" : "=r"(y) : "r"(*(unsigned*)&x));
    return *(half2*)&y;
}
__device__ __forceinline__ void red4(float* p, float4 v) {
    asm volatile("red.global.add.v4.f32 [%0], {%1,%2,%3,%4};"
                 :: "l"(p), "f"(v.x), "f"(v.y), "f"(v.z), "f"(v.w));
}
__device__ __forceinline__ void mma_f16(float d[4],
                                        unsigned a0, unsigned a1, unsigned a2, unsigned a3,
                                        unsigned b0, unsigned b1) {
    asm volatile("mma.sync.aligned.m16n8k16.row.col.f32.f16.f16.f32 "
                 "{%0,%1,%2,%3}, {%4,%5,%6,%7}, {%8,%9}, {%0,%1,%2,%3};\n"
                 : "+f"(d[0]), "+f"(d[1]), "+f"(d[2]), "+f"(d[3])
                 : "r"(a0), "r"(a1), "r"(a2), "r"(a3), "r"(b0), "r"(b1));
}

// ---------------- weight prep: fp16 transposed, once ----------------
__global__ void k_wprep(const float* __restrict__ Wf, const float* __restrict__ Ws,
                        __half* __restrict__ wTproj, __half* __restrict__ wTedge) {
    int idx = blockIdx.x * blockDim.x + threadIdx.x;
    if (idx < 4 * 128 * 128) {
        int part = idx >> 14;
        int rem = idx & 16383;
        int c = rem >> 7;
        int k = rem & 127;
        const float* W;
        if (part == 0)      W = Wf;
        else if (part == 1) W = Ws;
        else if (part == 2) W = Wf + 128 * 128;
        else                W = Ws + 128 * 128;
        wTproj[idx] = __float2half_rn(W[k * 128 + c]);
    } else if (idx < 4 * 128 * 128 + 256 * 32) {
        int i2 = idx - 4 * 128 * 128;
        int c = i2 >> 5;
        int k = i2 & 31;
        float v = (c < 128) ? Wf[(256 + k) * 128 + c]
                            : Ws[(256 + k) * 128 + (c - 128)];
        wTedge[i2] = __float2half_rn(v);
    }
}

// ---------------- CSR build ----------------
__global__ void k_hist(const int* __restrict__ ei, int* __restrict__ deg) {
    int e = blockIdx.x * blockDim.x + threadIdx.x;
    if (e < N_EDGES) atomicAdd(&deg[ei[N_EDGES + e]], 1);
}
__global__ void k_scan_a(const int* __restrict__ deg, int* __restrict__ cursor,
                         int* __restrict__ part) {
    __shared__ int s[SCAN_B];
    int i = blockIdx.x * SCAN_B + threadIdx.x;
    int v = (i < N_NODES) ? deg[i] : 0;
    s[threadIdx.x] = v;
    __syncthreads();
    for (int off = 1; off < SCAN_B; off <<= 1) {
        int t = (threadIdx.x >= off) ? s[threadIdx.x - off] : 0;
        __syncthreads();
        s[threadIdx.x] += t;
        __syncthreads();
    }
    if (i < N_NODES) cursor[i] = s[threadIdx.x] - v;
    if (threadIdx.x == SCAN_B - 1) part[blockIdx.x] = s[threadIdx.x];
}
__global__ void k_scan_b(int* __restrict__ part, int nb) {
    __shared__ int s[256];
    int v = (threadIdx.x < nb) ? part[threadIdx.x] : 0;
    s[threadIdx.x] = v;
    __syncthreads();
    for (int off = 1; off < 256; off <<= 1) {
        int t = (threadIdx.x >= off) ? s[threadIdx.x - off] : 0;
        __syncthreads();
        s[threadIdx.x] += t;
        __syncthreads();
    }
    if (threadIdx.x < nb) part[threadIdx.x] = s[threadIdx.x] - v;
}

// ---------------- pass 1: conv1 + light permutation scatter ----------------
__global__ void k_conv1_perm(const float* __restrict__ x, const int* __restrict__ ei,
                             const float* __restrict__ ea,
                             const float* __restrict__ Wf, const float* __restrict__ bf,
                             const float* __restrict__ Ws, const float* __restrict__ bs,
                             int* __restrict__ cursor, const int* __restrict__ part,
                             int4* __restrict__ esd, float* __restrict__ agg) {
    __shared__ float sWf[38 * 3], sWs[38 * 3], sbf[3], sbs[3];
    int t = threadIdx.x;
    if (t < 114) { sWf[t] = Wf[t]; sWs[t] = Ws[t]; }
    if (t < 3)   { sbf[t] = bf[t]; sbs[t] = bs[t]; }
    __syncthreads();
    int e = blockIdx.x * blockDim.x + t;
    if (e >= N_EDGES) return;
    int src = ei[e];
    int dst = ei[N_EDGES + e];

    float lf0 = sbf[0], lf1 = sbf[1], lf2 = sbf[2];
    float ls0 = sbs[0], ls1 = sbs[1], ls2 = sbs[2];

    {
        float zz[6] = { x[dst * 3 + 0], x[dst * 3 + 1], x[dst * 3 + 2],
                        x[src * 3 + 0], x[src * 3 + 1], x[src * 3 + 2] };
#pragma unroll
        for (int r = 0; r < 6; r++) {
            float zv = zz[r];
            lf0 = fmaf(zv, sWf[r * 3 + 0], lf0);
            lf1 = fmaf(zv, sWf[r * 3 + 1], lf1);
            lf2 = fmaf(zv, sWf[r * 3 + 2], lf2);
            ls0 = fmaf(zv, sWs[r * 3 + 0], ls0);
            ls1 = fmaf(zv, sWs[r * 3 + 1], ls1);
            ls2 = fmaf(zv, sWs[r * 3 + 2], ls2);
        }
    }
    const float4* s = (const float4*)&ea[(size_t)e * 32];
#pragma unroll
    for (int j = 0; j < 8; j++) {
        float4 v = s[j];
        float q[4] = { v.x, v.y, v.z, v.w };
#pragma unroll
        for (int k = 0; k < 4; k++) {
            int r = 6 + j * 4 + k;
            float zv = q[k];
            lf0 = fmaf(zv, sWf[r * 3 + 0], lf0);
            lf1 = fmaf(zv, sWf[r * 3 + 1], lf1);
            lf2 = fmaf(zv, sWf[r * 3 + 2], lf2);
            ls0 = fmaf(zv, sWs[r * 3 + 0], ls0);
            ls1 = fmaf(zv, sWs[r * 3 + 1], ls1);
            ls2 = fmaf(zv, sWs[r * 3 + 2], ls2);
        }
    }
    atomicAdd(&agg[dst * 3 + 0], sigmoidf_(lf0) * softplusf_(ls0));
    atomicAdd(&agg[dst * 3 + 1], sigmoidf_(lf1) * softplusf_(ls1));
    atomicAdd(&agg[dst * 3 + 2], sigmoidf_(lf2) * softplusf_(ls2));

    int pos = atomicAdd(&cursor[dst], 1) + part[dst >> 9];
    esd[pos] = make_int4(src, dst, e, 0);
}

// ---------------- pass 2: coalesced gather-convert ----------------
__global__ void k_gather(const int4* __restrict__ esd, const float* __restrict__ ea,
                         int* __restrict__ srcs, int* __restrict__ dsts,
                         __half* __restrict__ eas) {
    int p = blockIdx.x * blockDim.x + threadIdx.x;
    if (p >= N_EDGES) return;
    int4 v = esd[p];
    srcs[p] = v.x;
    dsts[p] = v.y;
    const float4* s = (const float4*)&ea[(size_t)v.z * 32];
    __half* d = &eas[(size_t)p * 32];
#pragma unroll
    for (int j = 0; j < 4; j++) {
        float4 a = s[j * 2];
        float4 b = s[j * 2 + 1];
        half2 h0 = __floats2half2_rn(a.x, a.y);
        half2 h1 = __floats2half2_rn(a.z, a.w);
        half2 h2 = __floats2half2_rn(b.x, b.y);
        half2 h3 = __floats2half2_rn(b.z, b.w);
        uint4 pk;
        pk.x = *(unsigned*)&h0; pk.y = *(unsigned*)&h1;
        pk.z = *(unsigned*)&h2; pk.w = *(unsigned*)&h3;
        *(uint4*)&d[j * 8] = pk;
    }
}

// ---------------- node projection after conv1 (grid-stride) ----------------
__global__ void k_node1(const float* __restrict__ x, const float* __restrict__ agg,
                        const float* __restrict__ Wp, const float* __restrict__ bp,
                        float* __restrict__ h, __half* __restrict__ hh) {
    int i = blockIdx.x * blockDim.x + threadIdx.x;
    int stride = gridDim.x * blockDim.x;
    for (; i < N_NODES * HID; i += stride) {
        int n = i >> 7;
        int c = i & 127;
        float s0 = x[n * 3 + 0] + agg[n * 3 + 0];
        float s1 = x[n * 3 + 1] + agg[n * 3 + 1];
        float s2 = x[n * 3 + 2] + agg[n * 3 + 2];
        float v = bp[c] + s0 * Wp[c] + s1 * Wp[128 + c] + s2 * Wp[256 + c];
        v = fmaxf(v, 0.0f);
        h[i] = v;
        hh[i] = __float2half_rn(v);
    }
}

// ---------------- fused 4-part node projection (prepped fp16 W) ----------------
#define PJ_S 136
__global__ __launch_bounds__(256, 3) void k_proj_all(
        const __half* __restrict__ hh,
        const __half* __restrict__ wT,          // [4][128 col][128 k] fp16
        const float* __restrict__ bf, const float* __restrict__ bs,
        __half* __restrict__ PA, __half* __restrict__ PB) {
    extern __shared__ __half psm[];
    __half* hs  = psm;                 // [128 rows][136]
    __half* wsT = psm + 128 * PJ_S;    // [128 cols][136 k]

    int t = threadIdx.x;
    int lane = t & 31;
    int w = t >> 5;
    int g = lane >> 2;
    int tig = lane & 3;
    int n0 = blockIdx.x * 128;

#pragma unroll
    for (int j = 0; j < 8; j++) {
        int idx = t + j * 256;
        int row = idx >> 4;
        int c = (idx & 15) * 8;
        uint4 v = make_uint4(0, 0, 0, 0);
        int n = n0 + row;
        if (n < N_NODES) v = *(const uint4*)&hh[(size_t)n * 128 + c];
        *(uint4*)&hs[row * PJ_S + c] = v;
    }

    int r0 = w * 16;
#pragma unroll 1
    for (int part = 0; part < 4; part++) {
        const float* bias; __half* out; int coloff;
        if (part == 0)      { bias = bf;      out = PA; coloff = 0;   }
        else if (part == 1) { bias = bs;      out = PA; coloff = 128; }
        else if (part == 2) { bias = nullptr; out = PB; coloff = 0;   }
        else                { bias = nullptr; out = PB; coloff = 128; }
        const uint4* wsrc = (const uint4*)&wT[part * 128 * 128];

        __syncthreads();
#pragma unroll
        for (int j = 0; j < 8; j++) {
            int idx4 = t + j * 256;         // 2048 uint4 total
            int col = idx4 >> 4;            // 16 uint4 per col
            int k8 = idx4 & 15;
            *(uint4*)&wsT[col * PJ_S + k8 * 8] = wsrc[idx4];
        }
        __syncthreads();

#pragma unroll
        for (int h2i = 0; h2i < 2; h2i++) {
            float acc[8][4];
#pragma unroll
            for (int i = 0; i < 8; i++)
#pragma unroll
                for (int j = 0; j < 4; j++) acc[i][j] = 0.0f;
#pragma unroll
            for (int kb8 = 0; kb8 < 8; kb8++) {
                int kb = kb8 * 16;
                unsigned a0 = *(const unsigned*)&hs[(r0 + g) * PJ_S + kb + 2 * tig];
                unsigned a1 = *(const unsigned*)&hs[(r0 + g + 8) * PJ_S + kb + 2 * tig];
                unsigned a2 = *(const unsigned*)&hs[(r0 + g) * PJ_S + kb + 2 * tig + 8];
                unsigned a3 = *(const unsigned*)&hs[(r0 + g + 8) * PJ_S + kb + 2 * tig + 8];
#pragma unroll
                for (int nt = 0; nt < 8; nt++) {
                    int col = h2i * 64 + nt * 8 + g;
                    unsigned b0 = *(const unsigned*)&wsT[col * PJ_S + kb + 2 * tig];
                    unsigned b1 = *(const unsigned*)&wsT[col * PJ_S + kb + 2 * tig + 8];
                    mma_f16(acc[nt], a0, a1, a2, a3, b0, b1);
                }
            }
#pragma unroll
            for (int nt = 0; nt < 8; nt++) {
                int c = h2i * 64 + nt * 8 + 2 * tig;
                float b0 = 0.f, b1 = 0.f;
                if (bias) { b0 = bias[c]; b1 = bias[c + 1]; }
                int n = n0 + r0 + g;
                if (n < N_NODES)
                    *(half2*)&out[(size_t)n * 256 + coloff + c] =
                        __floats2half2_rn(acc[nt][0] + b0, acc[nt][1] + b1);
                n = n0 + r0 + g + 8;
                if (n < N_NODES)
                    *(half2*)&out[(size_t)n * 256 + coloff + c] =
                        __floats2half2_rn(acc[nt][2] + b0, acc[nt][3] + b1);
            }
        }
    }
}

// ---------------- fused edge kernel (prepped fp16 W) ----------------
#define WT_S 40
#define EA_S 40
#define EH_S 264
__global__ __launch_bounds__(256, 3) void k_edge_fused(
        const int* __restrict__ srcs, const int* __restrict__ dsts,
        const __half* __restrict__ eas,
        const __half* __restrict__ PA, const __half* __restrict__ PB,
        const __half* __restrict__ wTe,        // [256 col][32 k] fp16
        float* __restrict__ agg) {
    extern __shared__ __half sm[];
    __half* wsT  = sm;
    __half* seas = sm + 256 * WT_S;
    __half* Eh   = sm + 256 * WT_S + 64 * EA_S;

    int t = threadIdx.x;
    int lane = t & 31;
    int w = t >> 5;
    int g = lane >> 2;
    int tig = lane & 3;

    {
        const uint4* wsrc = (const uint4*)wTe;    // 1024 uint4
#pragma unroll
        for (int j = 0; j < 4; j++) {
            int idx4 = t + j * 256;
            int col = idx4 >> 2;                  // 4 uint4 per col
            int k8 = idx4 & 3;
            *(uint4*)&wsT[col * WT_S + k8 * 8] = wsrc[idx4];
        }
    }
    __syncthreads();

    int erow0 = (w & 3) * 16;
    int col0 = (w >> 2) * 128;
    const half2 nl2e = __floats2half2_rn(-1.44269504f, -1.44269504f);
    const half2 two2 = __floats2half2_rn(2.f, 2.f);
    const half2 m1h  = __floats2half2_rn(-1.f, -1.f);
    const half2 zr2  = __floats2half2_rn(0.f, 0.f);
    const half2 c0h = __floats2half2_rn(0.405542f, 0.405542f);
    const half2 c1h = __floats2half2_rn(0.333342f, 0.333342f);
    const half2 c2h = __floats2half2_rn(-0.0554078f, -0.0554078f);
    const half2 c3h = __floats2half2_rn(0.0122789f, 0.0122789f);
    const half2 c4h = __floats2half2_rn(-0.00346625f, -0.00346625f);
    const half2 c5h = __floats2half2_rn(0.000951552f, 0.000951552f);

    for (int tile = blockIdx.x; tile < NTILES; tile += gridDim.x) {
        long e0 = (long)tile * ETILE;
        {
            uint4 v = *(const uint4*)&eas[e0 * 32 + t * 8];
            int row = t >> 2;
            int c = (t & 3) * 8;
            *(uint4*)&seas[row * EA_S + c] = v;
        }
        __syncthreads();

        // phase 1: E = ea @ [Wef|Wes]
#pragma unroll
        for (int h2i = 0; h2i < 2; h2i++) {
            float acc[8][4];
#pragma unroll
            for (int i = 0; i < 8; i++)
#pragma unroll
                for (int j = 0; j < 4; j++) acc[i][j] = 0.0f;
#pragma unroll
            for (int ks = 0; ks < 2; ks++) {
                int kb = ks * 16;
                unsigned a0 = *(const unsigned*)&seas[(erow0 + g) * EA_S + kb + 2 * tig];
                unsigned a1 = *(const unsigned*)&seas[(erow0 + g + 8) * EA_S + kb + 2 * tig];
                unsigned a2 = *(const unsigned*)&seas[(erow0 + g) * EA_S + kb + 2 * tig + 8];
                unsigned a3 = *(const unsigned*)&seas[(erow0 + g + 8) * EA_S + kb + 2 * tig + 8];
#pragma unroll
                for (int nt = 0; nt < 8; nt++) {
                    int col = col0 + h2i * 64 + nt * 8 + g;
                    unsigned b0 = *(const unsigned*)&wsT[col * WT_S + kb + 2 * tig];
                    unsigned b1 = *(const unsigned*)&wsT[col * WT_S + kb + 2 * tig + 8];
                    mma_f16(acc[nt], a0, a1, a2, a3, b0, b1);
                }
            }
#pragma unroll
            for (int nt = 0; nt < 8; nt++) {
                int c = col0 + h2i * 64 + nt * 8 + 2 * tig;
                *(half2*)&Eh[(erow0 + g) * EH_S + c]     = __floats2half2_rn(acc[nt][0], acc[nt][1]);
                *(half2*)&Eh[(erow0 + g + 8) * EH_S + c] = __floats2half2_rn(acc[nt][2], acc[nt][3]);
            }
        }
        __syncthreads();

        // phase 2: prefetch-8 gather, tanh sigmoid + poly softplus, grouped flush
        {
            int srcs8[8], dsts8[8];
#pragma unroll
            for (int j = 0; j < 8; j++) {
                long e = e0 + w * 8 + j;
                srcs8[j] = srcs[e];
                dsts8[j] = dsts[e];
            }
            uint2 pbf[8], pbs[8];
#pragma unroll
            for (int j = 0; j < 8; j++) {
                size_t base = (size_t)srcs8[j] * 256 + lane * 4;
                pbf[j] = *(const uint2*)&PB[base];
                pbs[j] = *(const uint2*)&PB[base + 128];
            }
            int prev = -1;
            float4 acc = make_float4(0.f, 0.f, 0.f, 0.f);
            half2 af01, af23, as01, as23;
            af01 = af23 = as01 = as23 = __floats2half2_rn(0.f, 0.f);
#pragma unroll
            for (int j = 0; j < 8; j++) {
                int le = w * 8 + j;
                int dst = dsts8[j];
                if (dst != prev) {
                    if (prev >= 0)
                        red4(&agg[(size_t)prev * HID + lane * 4], acc);
                    acc = make_float4(0.f, 0.f, 0.f, 0.f);
                    size_t base = (size_t)dst * 256 + lane * 4;
                    uint2 pafu = *(const uint2*)&PA[base];
                    uint2 pasu = *(const uint2*)&PA[base + 128];
                    af01 = *(half2*)&pafu.x; af23 = *(half2*)&pafu.y;
                    as01 = *(half2*)&pasu.x; as23 = *(half2*)&pasu.y;
                    prev = dst;
                }
                uint2 efu = *(const uint2*)&Eh[le * EH_S + lane * 4];
                uint2 esu = *(const uint2*)&Eh[le * EH_S + 128 + lane * 4];

                half2 lf01 = __hadd2(__hadd2(*(half2*)&efu.x, af01), *(half2*)&pbf[j].x);
                half2 lf23 = __hadd2(__hadd2(*(half2*)&efu.y, af23), *(half2*)&pbf[j].y);
                half2 ls01 = __hadd2(__hadd2(*(half2*)&esu.x, as01), *(half2*)&pbs[j].x);
                half2 ls23 = __hadd2(__hadd2(*(half2*)&esu.y, as23), *(half2*)&pbs[j].y);

                half2 t01 = ex2h2_(__hmul2(__habs2(ls01), nl2e));
                half2 t23 = ex2h2_(__hmul2(__habs2(ls23), nl2e));

                half2 u01 = __hfma2(t01, two2, m1h);
                half2 u23 = __hfma2(t23, two2, m1h);
                half2 p01 = __hfma2(c5h, u01, c4h);
                half2 p23 = __hfma2(c5h, u23, c4h);
                p01 = __hfma2(p01, u01, c3h);  p23 = __hfma2(p23, u23, c3h);
                p01 = __hfma2(p01, u01, c2h);  p23 = __hfma2(p23, u23, c2h);
                p01 = __hfma2(p01, u01, c1h);  p23 = __hfma2(p23, u23, c1h);
                p01 = __hfma2(p01, u01, c0h);  p23 = __hfma2(p23, u23, c0h);

                half2 sp01 = __hadd2(__hmax2(ls01, zr2), p01);
                half2 sp23 = __hadd2(__hmax2(ls23, zr2), p23);

                float2 f0 = __half22float2(lf01), f1 = __half22float2(lf23);
                float2 q0 = __half22float2(sp01), q1 = __half22float2(sp23);

                float sg0 = fmaf(tanha_(0.5f * f0.x), 0.5f, 0.5f);
                float sg1 = fmaf(tanha_(0.5f * f0.y), 0.5f, 0.5f);
                float sg2 = fmaf(tanha_(0.5f * f1.x), 0.5f, 0.5f);
                float sg3 = fmaf(tanha_(0.5f * f1.y), 0.5f, 0.5f);

                acc.x = fmaf(sg0, q0.x, acc.x);
                acc.y = fmaf(sg1, q0.y, acc.y);
                acc.z = fmaf(sg2, q1.x, acc.z);
                acc.w = fmaf(sg3, q1.y, acc.w);
            }
            if (prev >= 0)
                red4(&agg[(size_t)prev * HID + lane * 4], acc);
        }
        __syncthreads();
    }
}

// ---------------- residual + relu (+ fp16 mirror) ----------------
__global__ void k_update(float* __restrict__ h, __half* __restrict__ hh,
                         const float* __restrict__ agg, int n) {
    int i = blockIdx.x * blockDim.x + threadIdx.x;
    int stride = gridDim.x * blockDim.x;
    for (; i < n; i += stride) {
        float v = fmaxf(h[i] + agg[i], 0.0f);
        h[i] = v;
        hh[i] = __float2half_rn(v);
    }
}

// ---------------- fused last update + pooling (batch sorted) ----------------
__global__ void k_update_pool(const float* __restrict__ h, const float* __restrict__ agg,
                              const int* __restrict__ batch,
                              float* __restrict__ pool, float* __restrict__ cnt) {
    const int NPB = 256;
    int n0 = blockIdx.x * NPB;
    if (n0 >= N_NODES) return;
    int c = threadIdx.x;  // 128
    float s = 0.0f;
    int cur = batch[n0];
    int mycnt = 0;
    for (int i = 0; i < NPB; i++) {
        int n = n0 + i;
        if (n >= N_NODES) break;
        int b = batch[n];
        if (b != cur) {
            atomicAdd(&pool[cur * HID + c], s);
            if (c == 0) atomicAdd(&cnt[cur], (float)mycnt);
            s = 0.0f; mycnt = 0; cur = b;
        }
        s += fmaxf(h[(size_t)n * HID + c] + agg[(size_t)n * HID + c], 0.0f);
        mycnt++;
    }
    atomicAdd(&pool[cur * HID + c], s);
    if (c == 0) atomicAdd(&cnt[cur], (float)mycnt);
}

// ---------------- head ----------------
__global__ void k_head(const float* __restrict__ pool, const float* __restrict__ cnt,
                       const float* __restrict__ W1, const float* __restrict__ b1,
                       const float* __restrict__ W2, const float* __restrict__ b2,
                       float* __restrict__ out) {
    int g = blockIdx.x;
    int c = threadIdx.x;
    __shared__ float p[128];
    __shared__ float t1[128];
    float invc = 1.0f / fmaxf(cnt[g], 1.0f);
    p[c] = pool[g * HID + c] * invc;
    __syncthreads();
    float v = b1[c];
#pragma unroll 16
    for (int k = 0; k < 128; k++) v += p[k] * W1[k * 128 + c];
    t1[c] = fmaxf(v, 0.0f);
    __syncthreads();
    if (c < 3) {
        float o = b2[c];
        for (int k = 0; k < 128; k++) o += t1[k] * W2[k * 3 + c];
        out[g * 3 + c] = o;
    }
}

// ---------------- launch ----------------
extern "C" void kernel_launch(void* const* d_in, const int* in_sizes, int n_in,
                              void* d_out, int out_size) {
    const float* x   = (const float*)d_in[0];
    const int*   ei  = (const int*)d_in[1];
    const float* ea  = (const float*)d_in[2];
    const int*   bat = (const int*)d_in[3];
    const float* Wf1 = (const float*)d_in[4];
    const float* bf1 = (const float*)d_in[5];
    const float* Ws1 = (const float*)d_in[6];
    const float* bs1 = (const float*)d_in[7];
    const float* Wp  = (const float*)d_in[8];
    const float* bp  = (const float*)d_in[9];
    const float* Wc[2]  = { (const float*)d_in[10], (const float*)d_in[14] };
    const float* bcf[2] = { (const float*)d_in[11], (const float*)d_in[15] };
    const float* Wsc[2] = { (const float*)d_in[12], (const float*)d_in[16] };
    const float* bcs[2] = { (const float*)d_in[13], (const float*)d_in[17] };
    const float* W1  = (const float*)d_in[18];
    const float* b1  = (const float*)d_in[19];
    const float* W2  = (const float*)d_in[20];
    const float* b2  = (const float*)d_in[21];
    float* out = (float*)d_out;

    float *pH, *pAgg, *pPool;
    __half *pPA, *pPB, *pHH, *pEAS, *pWTP, *pWTE;
    int *pDeg, *pCur, *pPart, *pSrcs, *pDsts;
    int4 *pEsd;
    cudaGetSymbolAddress((void**)&pH,    g_h);
    cudaGetSymbolAddress((void**)&pHH,   g_hh);
    cudaGetSymbolAddress((void**)&pPA,   g_PA);
    cudaGetSymbolAddress((void**)&pPB,   g_PB);
    cudaGetSymbolAddress((void**)&pAgg,  g_agg);
    cudaGetSymbolAddress((void**)&pPool, g_pool);
    cudaGetSymbolAddress((void**)&pDeg,  g_deg);
    cudaGetSymbolAddress((void**)&pCur,  g_cursor);
    cudaGetSymbolAddress((void**)&pPart, g_part);
    cudaGetSymbolAddress((void**)&pEsd,  g_esd);
    cudaGetSymbolAddress((void**)&pSrcs, g_srcs);
    cudaGetSymbolAddress((void**)&pDsts, g_dsts);
    cudaGetSymbolAddress((void**)&pEAS,  g_eas);
    cudaGetSymbolAddress((void**)&pWTP,  g_wTproj);
    cudaGetSymbolAddress((void**)&pWTE,  g_wTedge);

    const int EDGE_SMEM = (256 * WT_S + 64 * EA_S + 64 * EH_S) * 2;
    const int PROJ_SMEM = 2 * 128 * PJ_S * 2;
    cudaFuncSetAttribute(k_edge_fused, cudaFuncAttributeMaxDynamicSharedMemorySize, EDGE_SMEM);
    cudaFuncSetAttribute(k_proj_all, cudaFuncAttributeMaxDynamicSharedMemorySize, PROJ_SMEM);

    // ---- zeroing via graph memset nodes ----
    cudaMemsetAsync(pDeg, 0, N_NODES * sizeof(int));
    cudaMemsetAsync(pAgg, 0, N_NODES * 3 * sizeof(float));
    cudaMemsetAsync(pPool, 0, (NGRAPH * HID + NGRAPH) * sizeof(float));

    // ---- weight prep (once per layer) ----
    const int WPREP_N = 4 * 128 * 128 + 256 * 32;
    for (int l = 0; l < 2; l++)
        k_wprep<<<(WPREP_N + 255) / 256, 256>>>(Wc[l], Wsc[l],
                                                pWTP + l * 4 * 128 * 128,
                                                pWTE + l * 256 * 32);

    // ---- build CSR + conv1 ----
    k_hist<<<N_EDGES / 256, 256>>>(ei, pDeg);
    k_scan_a<<<SCAN_NB, SCAN_B>>>(pDeg, pCur, pPart);
    k_scan_b<<<1, 256>>>(pPart, SCAN_NB);
    k_conv1_perm<<<N_EDGES / 256, 256>>>(x, ei, ea, Wf1, bf1, Ws1, bs1,
                                         pCur, pPart, pEsd, pAgg);
    k_gather<<<N_EDGES / 256, 256>>>(pEsd, ea, pSrcs, pDsts, pEAS);
    k_node1<<<592, 256>>>(x, pAgg, Wp, bp, pH, pHH);

    // ---- hidden convs ----
    for (int l = 0; l < 2; l++) {
        k_proj_all<<<(N_NODES + 127) / 128, 256, PROJ_SMEM>>>(
            pHH, pWTP + l * 4 * 128 * 128, bcf[l], bcs[l], pPA, pPB);
        cudaMemsetAsync(pAgg, 0, (size_t)N_NODES * HID * sizeof(float));
        k_edge_fused<<<444, 256, EDGE_SMEM>>>(pSrcs, pDsts, pEAS, pPA, pPB,
                                              pWTE + l * 256 * 32, pAgg);
        if (l == 0)
            k_update<<<2048, 256>>>(pH, pHH, pAgg, N_NODES * HID);
        else
            k_update_pool<<<(N_NODES + 255) / 256, 128>>>(pH, pAgg, bat,
                                                          pPool, pPool + NGRAPH * HID);
    }

    // ---- head ----
    k_head<<<NGRAPH, 128>>>(pPool, pPool + NGRAPH * HID, W1, b1, W2, b2, out);
}

// round 13
// speedup vs baseline: 1.3101x; 1.0362x over previous
#include <cuda_runtime.h>
#include <cuda_fp16.h>
#include <math.h>

#define N_NODES 100000
#define N_EDGES 1600000
#define HID 128
#define NGRAPH 64
#define ETILE 64
#define NTILES (N_EDGES / ETILE)
#define SCAN_B 512
#define SCAN_NB ((N_NODES + SCAN_B - 1) / SCAN_B)   // 196

// ---------------- device scratch ----------------
__device__ float  g_h[N_NODES * HID];
__device__ __half g_hh[N_NODES * HID];
__device__ __half g_PA[N_NODES * 256];   // [f(128) | s(128)] per node (+bias)
__device__ __half g_PB[N_NODES * 256];
__device__ float  g_agg[N_NODES * HID];
__device__ float  g_pool[NGRAPH * HID + NGRAPH];
__device__ int    g_deg[N_NODES];
__device__ int    g_cursor[N_NODES];
__device__ int    g_part[256];
__device__ int4   g_esd[N_EDGES];
__device__ int    g_srcs[N_EDGES];
__device__ int    g_dsts[N_EDGES];
__device__ __half g_eas[(size_t)N_EDGES * 32];
__device__ __half g_wTproj[2 * 4 * 128 * 128];
__device__ __half g_wTedge[2 * 256 * 32];

// ---------------- helpers ----------------
__device__ __forceinline__ float sigmoidf_(float x) { return 1.0f / (1.0f + __expf(-x)); }
__device__ __forceinline__ float softplusf_(float x) {
    return fmaxf(x, 0.0f) + __logf(1.0f + __expf(-fabsf(x)));
}
__device__ __forceinline__ float tanha_(float x) {
    float y;
    asm("tanh.approx.f32 %0, %1;" : "=f"(y) : "f"(x));
    return y;
}
__device__ __forceinline__ half2 ex2h2_(half2 x) {
    unsigned y;
    asm("ex2.approx.f16x2 %0, %1;" : "=r"(y) : "r"(*(unsigned*)&x));
    return *(half2*)&y;
}
__device__ __forceinline__ void red4(float* p, float4 v) {
    asm volatile("red.global.add.v4.f32 [%0], {%1,%2,%3,%4};"
                 :: "l"(p), "f"(v.x), "f"(v.y), "f"(v.z), "f"(v.w));
}
__device__ __forceinline__ void mma_f16(float d[4],
                                        unsigned a0, unsigned a1, unsigned a2, unsigned a3,
                                        unsigned b0, unsigned b1) {
    asm volatile("mma.sync.aligned.m16n8k16.row.col.f32.f16.f16.f32 "
                 "{%0,%1,%2,%3}, {%4,%5,%6,%7}, {%8,%9}, {%0,%1,%2,%3};\n"
                 : "+f"(d[0]), "+f"(d[1]), "+f"(d[2]), "+f"(d[3])
                 : "r"(a0), "r"(a1), "r"(a2), "r"(a3), "r"(b0), "r"(b1));
}

// ---------------- weight prep ----------------
__global__ void k_wprep(const float* __restrict__ Wf, const float* __restrict__ Ws,
                        __half* __restrict__ wTproj, __half* __restrict__ wTedge) {
    int idx = blockIdx.x * blockDim.x + threadIdx.x;
    if (idx < 4 * 128 * 128) {
        int part = idx >> 14;
        int rem = idx & 16383;
        int c = rem >> 7;
        int k = rem & 127;
        const float* W;
        if (part == 0)      W = Wf;
        else if (part == 1) W = Ws;
        else if (part == 2) W = Wf + 128 * 128;
        else                W = Ws + 128 * 128;
        wTproj[idx] = __float2half_rn(W[k * 128 + c]);
    } else if (idx < 4 * 128 * 128 + 256 * 32) {
        int i2 = idx - 4 * 128 * 128;
        int c = i2 >> 5;
        int k = i2 & 31;
        float v = (c < 128) ? Wf[(256 + k) * 128 + c]
                            : Ws[(256 + k) * 128 + (c - 128)];
        wTedge[i2] = __float2half_rn(v);
    }
}

// ---------------- CSR build ----------------
__global__ void k_hist(const int* __restrict__ ei, int* __restrict__ deg) {
    int e = blockIdx.x * blockDim.x + threadIdx.x;
    if (e < N_EDGES) atomicAdd(&deg[ei[N_EDGES + e]], 1);
}
__global__ void k_scan_a(const int* __restrict__ deg, int* __restrict__ cursor,
                         int* __restrict__ part) {
    __shared__ int s[SCAN_B];
    int i = blockIdx.x * SCAN_B + threadIdx.x;
    int v = (i < N_NODES) ? deg[i] : 0;
    s[threadIdx.x] = v;
    __syncthreads();
    for (int off = 1; off < SCAN_B; off <<= 1) {
        int t = (threadIdx.x >= off) ? s[threadIdx.x - off] : 0;
        __syncthreads();
        s[threadIdx.x] += t;
        __syncthreads();
    }
    if (i < N_NODES) cursor[i] = s[threadIdx.x] - v;
    if (threadIdx.x == SCAN_B - 1) part[blockIdx.x] = s[threadIdx.x];
}
__global__ void k_scan_b(int* __restrict__ part, int nb) {
    __shared__ int s[256];
    int v = (threadIdx.x < nb) ? part[threadIdx.x] : 0;
    s[threadIdx.x] = v;
    __syncthreads();
    for (int off = 1; off < 256; off <<= 1) {
        int t = (threadIdx.x >= off) ? s[threadIdx.x - off] : 0;
        __syncthreads();
        s[threadIdx.x] += t;
        __syncthreads();
    }
    if (threadIdx.x < nb) part[threadIdx.x] = s[threadIdx.x] - v;
}

// ---------------- pass 1: pure permutation scatter (ei only) ----------------
__global__ void k_perm(const int* __restrict__ ei,
                       int* __restrict__ cursor, const int* __restrict__ part,
                       int4* __restrict__ esd) {
    int e = blockIdx.x * blockDim.x + threadIdx.x;
    if (e >= N_EDGES) return;
    int src = ei[e];
    int dst = ei[N_EDGES + e];
    int pos = atomicAdd(&cursor[dst], 1) + part[dst >> 9];  // SCAN_B = 512
    esd[pos] = make_int4(src, dst, e, 0);
}

// ---------------- pass 2: gather-convert + conv1 (single ea pass) ----------------
__global__ void k_gather_conv1(const int4* __restrict__ esd, const float* __restrict__ ea,
                               const float* __restrict__ x,
                               const float* __restrict__ Wf, const float* __restrict__ bf,
                               const float* __restrict__ Ws, const float* __restrict__ bs,
                               int* __restrict__ srcs, int* __restrict__ dsts,
                               __half* __restrict__ eas, float* __restrict__ agg) {
    __shared__ float sWf[38 * 3], sWs[38 * 3], sbf[3], sbs[3];
    int t = threadIdx.x;
    if (t < 114) { sWf[t] = Wf[t]; sWs[t] = Ws[t]; }
    if (t < 3)   { sbf[t] = bf[t]; sbs[t] = bs[t]; }
    __syncthreads();
    int p = blockIdx.x * blockDim.x + t;
    if (p >= N_EDGES) return;
    int4 rec = esd[p];
    int src = rec.x;
    int dst = rec.y;
    srcs[p] = src;
    dsts[p] = dst;

    float lf0 = sbf[0], lf1 = sbf[1], lf2 = sbf[2];
    float ls0 = sbs[0], ls1 = sbs[1], ls2 = sbs[2];
    {
        float zz[6] = { x[dst * 3 + 0], x[dst * 3 + 1], x[dst * 3 + 2],
                        x[src * 3 + 0], x[src * 3 + 1], x[src * 3 + 2] };
#pragma unroll
        for (int r = 0; r < 6; r++) {
            float zv = zz[r];
            lf0 = fmaf(zv, sWf[r * 3 + 0], lf0);
            lf1 = fmaf(zv, sWf[r * 3 + 1], lf1);
            lf2 = fmaf(zv, sWf[r * 3 + 2], lf2);
            ls0 = fmaf(zv, sWs[r * 3 + 0], ls0);
            ls1 = fmaf(zv, sWs[r * 3 + 1], ls1);
            ls2 = fmaf(zv, sWs[r * 3 + 2], ls2);
        }
    }
    const float4* s = (const float4*)&ea[(size_t)rec.z * 32];   // full 128B line
    __half* d = &eas[(size_t)p * 32];
#pragma unroll
    for (int j = 0; j < 4; j++) {
        float4 a = s[j * 2];
        float4 b = s[j * 2 + 1];
        // conv1 accumulation (rows 6+8j .. 6+8j+7)
        float q[8] = { a.x, a.y, a.z, a.w, b.x, b.y, b.z, b.w };
#pragma unroll
        for (int k = 0; k < 8; k++) {
            int r = 6 + j * 8 + k;
            float zv = q[k];
            lf0 = fmaf(zv, sWf[r * 3 + 0], lf0);
            lf1 = fmaf(zv, sWf[r * 3 + 1], lf1);
            lf2 = fmaf(zv, sWf[r * 3 + 2], lf2);
            ls0 = fmaf(zv, sWs[r * 3 + 0], ls0);
            ls1 = fmaf(zv, sWs[r * 3 + 1], ls1);
            ls2 = fmaf(zv, sWs[r * 3 + 2], ls2);
        }
        // fp16 conversion + coalesced store
        half2 h0 = __floats2half2_rn(a.x, a.y);
        half2 h1 = __floats2half2_rn(a.z, a.w);
        half2 h2 = __floats2half2_rn(b.x, b.y);
        half2 h3 = __floats2half2_rn(b.z, b.w);
        uint4 pk;
        pk.x = *(unsigned*)&h0; pk.y = *(unsigned*)&h1;
        pk.z = *(unsigned*)&h2; pk.w = *(unsigned*)&h3;
        *(uint4*)&d[j * 8] = pk;
    }
    atomicAdd(&agg[dst * 3 + 0], sigmoidf_(lf0) * softplusf_(ls0));
    atomicAdd(&agg[dst * 3 + 1], sigmoidf_(lf1) * softplusf_(ls1));
    atomicAdd(&agg[dst * 3 + 2], sigmoidf_(lf2) * softplusf_(ls2));
}

// ---------------- node projection after conv1 (grid-stride) ----------------
__global__ void k_node1(const float* __restrict__ x, const float* __restrict__ agg,
                        const float* __restrict__ Wp, const float* __restrict__ bp,
                        float* __restrict__ h, __half* __restrict__ hh) {
    int i = blockIdx.x * blockDim.x + threadIdx.x;
    int stride = gridDim.x * blockDim.x;
    for (; i < N_NODES * HID; i += stride) {
        int n = i >> 7;
        int c = i & 127;
        float s0 = x[n * 3 + 0] + agg[n * 3 + 0];
        float s1 = x[n * 3 + 1] + agg[n * 3 + 1];
        float s2 = x[n * 3 + 2] + agg[n * 3 + 2];
        float v = bp[c] + s0 * Wp[c] + s1 * Wp[128 + c] + s2 * Wp[256 + c];
        v = fmaxf(v, 0.0f);
        h[i] = v;
        hh[i] = __float2half_rn(v);
    }
}

// ---------------- fused 4-part node projection (prepped fp16 W) ----------------
#define PJ_S 136
__global__ __launch_bounds__(256, 3) void k_proj_all(
        const __half* __restrict__ hh,
        const __half* __restrict__ wT,
        const float* __restrict__ bf, const float* __restrict__ bs,
        __half* __restrict__ PA, __half* __restrict__ PB) {
    extern __shared__ __half psm[];
    __half* hs  = psm;                 // [128 rows][136]
    __half* wsT = psm + 128 * PJ_S;    // [128 cols][136 k]

    int t = threadIdx.x;
    int lane = t & 31;
    int w = t >> 5;
    int g = lane >> 2;
    int tig = lane & 3;
    int n0 = blockIdx.x * 128;

#pragma unroll
    for (int j = 0; j < 8; j++) {
        int idx = t + j * 256;
        int row = idx >> 4;
        int c = (idx & 15) * 8;
        uint4 v = make_uint4(0, 0, 0, 0);
        int n = n0 + row;
        if (n < N_NODES) v = *(const uint4*)&hh[(size_t)n * 128 + c];
        *(uint4*)&hs[row * PJ_S + c] = v;
    }

    int r0 = w * 16;
#pragma unroll 1
    for (int part = 0; part < 4; part++) {
        const float* bias; __half* out; int coloff;
        if (part == 0)      { bias = bf;      out = PA; coloff = 0;   }
        else if (part == 1) { bias = bs;      out = PA; coloff = 128; }
        else if (part == 2) { bias = nullptr; out = PB; coloff = 0;   }
        else                { bias = nullptr; out = PB; coloff = 128; }
        const uint4* wsrc = (const uint4*)&wT[part * 128 * 128];

        __syncthreads();
#pragma unroll
        for (int j = 0; j < 8; j++) {
            int idx4 = t + j * 256;
            int col = idx4 >> 4;
            int k8 = idx4 & 15;
            *(uint4*)&wsT[col * PJ_S + k8 * 8] = wsrc[idx4];
        }
        __syncthreads();

#pragma unroll
        for (int h2i = 0; h2i < 2; h2i++) {
            float acc[8][4];
#pragma unroll
            for (int i = 0; i < 8; i++)
#pragma unroll
                for (int j = 0; j < 4; j++) acc[i][j] = 0.0f;
#pragma unroll
            for (int kb8 = 0; kb8 < 8; kb8++) {
                int kb = kb8 * 16;
                unsigned a0 = *(const unsigned*)&hs[(r0 + g) * PJ_S + kb + 2 * tig];
                unsigned a1 = *(const unsigned*)&hs[(r0 + g + 8) * PJ_S + kb + 2 * tig];
                unsigned a2 = *(const unsigned*)&hs[(r0 + g) * PJ_S + kb + 2 * tig + 8];
                unsigned a3 = *(const unsigned*)&hs[(r0 + g + 8) * PJ_S + kb + 2 * tig + 8];
#pragma unroll
                for (int nt = 0; nt < 8; nt++) {
                    int col = h2i * 64 + nt * 8 + g;
                    unsigned b0 = *(const unsigned*)&wsT[col * PJ_S + kb + 2 * tig];
                    unsigned b1 = *(const unsigned*)&wsT[col * PJ_S + kb + 2 * tig + 8];
                    mma_f16(acc[nt], a0, a1, a2, a3, b0, b1);
                }
            }
#pragma unroll
            for (int nt = 0; nt < 8; nt++) {
                int c = h2i * 64 + nt * 8 + 2 * tig;
                float b0 = 0.f, b1 = 0.f;
                if (bias) { b0 = bias[c]; b1 = bias[c + 1]; }
                int n = n0 + r0 + g;
                if (n < N_NODES)
                    *(half2*)&out[(size_t)n * 256 + coloff + c] =
                        __floats2half2_rn(acc[nt][0] + b0, acc[nt][1] + b1);
                n = n0 + r0 + g + 8;
                if (n < N_NODES)
                    *(half2*)&out[(size_t)n * 256 + coloff + c] =
                        __floats2half2_rn(acc[nt][2] + b0, acc[nt][3] + b1);
            }
        }
    }
}

// ---------------- fused edge kernel (prepped fp16 W) ----------------
#define WT_S 40
#define EA_S 40
#define EH_S 264
__global__ __launch_bounds__(256, 3) void k_edge_fused(
        const int* __restrict__ srcs, const int* __restrict__ dsts,
        const __half* __restrict__ eas,
        const __half* __restrict__ PA, const __half* __restrict__ PB,
        const __half* __restrict__ wTe,
        float* __restrict__ agg) {
    extern __shared__ __half sm[];
    __half* wsT  = sm;
    __half* seas = sm + 256 * WT_S;
    __half* Eh   = sm + 256 * WT_S + 64 * EA_S;

    int t = threadIdx.x;
    int lane = t & 31;
    int w = t >> 5;
    int g = lane >> 2;
    int tig = lane & 3;

    {
        const uint4* wsrc = (const uint4*)wTe;
#pragma unroll
        for (int j = 0; j < 4; j++) {
            int idx4 = t + j * 256;
            int col = idx4 >> 2;
            int k8 = idx4 & 3;
            *(uint4*)&wsT[col * WT_S + k8 * 8] = wsrc[idx4];
        }
    }
    __syncthreads();

    int erow0 = (w & 3) * 16;
    int col0 = (w >> 2) * 128;
    const half2 nl2e = __floats2half2_rn(-1.44269504f, -1.44269504f);
    const half2 two2 = __floats2half2_rn(2.f, 2.f);
    const half2 m1h  = __floats2half2_rn(-1.f, -1.f);
    const half2 zr2  = __floats2half2_rn(0.f, 0.f);
    const half2 c0h = __floats2half2_rn(0.405542f, 0.405542f);
    const half2 c1h = __floats2half2_rn(0.333342f, 0.333342f);
    const half2 c2h = __floats2half2_rn(-0.0554078f, -0.0554078f);
    const half2 c3h = __floats2half2_rn(0.0122789f, 0.0122789f);
    const half2 c4h = __floats2half2_rn(-0.00346625f, -0.00346625f);
    const half2 c5h = __floats2half2_rn(0.000951552f, 0.000951552f);

    for (int tile = blockIdx.x; tile < NTILES; tile += gridDim.x) {
        long e0 = (long)tile * ETILE;
        {
            uint4 v = *(const uint4*)&eas[e0 * 32 + t * 8];
            int row = t >> 2;
            int c = (t & 3) * 8;
            *(uint4*)&seas[row * EA_S + c] = v;
        }
        __syncthreads();

        // phase 1: E = ea @ [Wef|Wes]
#pragma unroll
        for (int h2i = 0; h2i < 2; h2i++) {
            float acc[8][4];
#pragma unroll
            for (int i = 0; i < 8; i++)
#pragma unroll
                for (int j = 0; j < 4; j++) acc[i][j] = 0.0f;
#pragma unroll
            for (int ks = 0; ks < 2; ks++) {
                int kb = ks * 16;
                unsigned a0 = *(const unsigned*)&seas[(erow0 + g) * EA_S + kb + 2 * tig];
                unsigned a1 = *(const unsigned*)&seas[(erow0 + g + 8) * EA_S + kb + 2 * tig];
                unsigned a2 = *(const unsigned*)&seas[(erow0 + g) * EA_S + kb + 2 * tig + 8];
                unsigned a3 = *(const unsigned*)&seas[(erow0 + g + 8) * EA_S + kb + 2 * tig + 8];
#pragma unroll
                for (int nt = 0; nt < 8; nt++) {
                    int col = col0 + h2i * 64 + nt * 8 + g;
                    unsigned b0 = *(const unsigned*)&wsT[col * WT_S + kb + 2 * tig];
                    unsigned b1 = *(const unsigned*)&wsT[col * WT_S + kb + 2 * tig + 8];
                    mma_f16(acc[nt], a0, a1, a2, a3, b0, b1);
                }
            }
#pragma unroll
            for (int nt = 0; nt < 8; nt++) {
                int c = col0 + h2i * 64 + nt * 8 + 2 * tig;
                *(half2*)&Eh[(erow0 + g) * EH_S + c]     = __floats2half2_rn(acc[nt][0], acc[nt][1]);
                *(half2*)&Eh[(erow0 + g + 8) * EH_S + c] = __floats2half2_rn(acc[nt][2], acc[nt][3]);
            }
        }
        __syncthreads();

        // phase 2: prefetch-8 gather, tanh sigmoid + poly softplus, grouped flush
        {
            int srcs8[8], dsts8[8];
#pragma unroll
            for (int j = 0; j < 8; j++) {
                long e = e0 + w * 8 + j;
                srcs8[j] = srcs[e];
                dsts8[j] = dsts[e];
            }
            uint2 pbf[8], pbs[8];
#pragma unroll
            for (int j = 0; j < 8; j++) {
                size_t base = (size_t)srcs8[j] * 256 + lane * 4;
                pbf[j] = *(const uint2*)&PB[base];
                pbs[j] = *(const uint2*)&PB[base + 128];
            }
            int prev = -1;
            float4 acc = make_float4(0.f, 0.f, 0.f, 0.f);
            half2 af01, af23, as01, as23;
            af01 = af23 = as01 = as23 = __floats2half2_rn(0.f, 0.f);
#pragma unroll
            for (int j = 0; j < 8; j++) {
                int le = w * 8 + j;
                int dst = dsts8[j];
                if (dst != prev) {
                    if (prev >= 0)
                        red4(&agg[(size_t)prev * HID + lane * 4], acc);
                    acc = make_float4(0.f, 0.f, 0.f, 0.f);
                    size_t base = (size_t)dst * 256 + lane * 4;
                    uint2 pafu = *(const uint2*)&PA[base];
                    uint2 pasu = *(const uint2*)&PA[base + 128];
                    af01 = *(half2*)&pafu.x; af23 = *(half2*)&pafu.y;
                    as01 = *(half2*)&pasu.x; as23 = *(half2*)&pasu.y;
                    prev = dst;
                }
                uint2 efu = *(const uint2*)&Eh[le * EH_S + lane * 4];
                uint2 esu = *(const uint2*)&Eh[le * EH_S + 128 + lane * 4];

                half2 lf01 = __hadd2(__hadd2(*(half2*)&efu.x, af01), *(half2*)&pbf[j].x);
                half2 lf23 = __hadd2(__hadd2(*(half2*)&efu.y, af23), *(half2*)&pbf[j].y);
                half2 ls01 = __hadd2(__hadd2(*(half2*)&esu.x, as01), *(half2*)&pbs[j].x);
                half2 ls23 = __hadd2(__hadd2(*(half2*)&esu.y, as23), *(half2*)&pbs[j].y);

                half2 t01 = ex2h2_(__hmul2(__habs2(ls01), nl2e));
                half2 t23 = ex2h2_(__hmul2(__habs2(ls23), nl2e));

                half2 u01 = __hfma2(t01, two2, m1h);
                half2 u23 = __hfma2(t23, two2, m1h);
                half2 p01 = __hfma2(c5h, u01, c4h);
                half2 p23 = __hfma2(c5h, u23, c4h);
                p01 = __hfma2(p01, u01, c3h);  p23 = __hfma2(p23, u23, c3h);
                p01 = __hfma2(p01, u01, c2h);  p23 = __hfma2(p23, u23, c2h);
                p01 = __hfma2(p01, u01, c1h);  p23 = __hfma2(p23, u23, c1h);
                p01 = __hfma2(p01, u01, c0h);  p23 = __hfma2(p23, u23, c0h);

                half2 sp01 = __hadd2(__hmax2(ls01, zr2), p01);
                half2 sp23 = __hadd2(__hmax2(ls23, zr2), p23);

                float2 f0 = __half22float2(lf01), f1 = __half22float2(lf23);
                float2 q0 = __half22float2(sp01), q1 = __half22float2(sp23);

                float sg0 = fmaf(tanha_(0.5f * f0.x), 0.5f, 0.5f);
                float sg1 = fmaf(tanha_(0.5f * f0.y), 0.5f, 0.5f);
                float sg2 = fmaf(tanha_(0.5f * f1.x), 0.5f, 0.5f);
                float sg3 = fmaf(tanha_(0.5f * f1.y), 0.5f, 0.5f);

                acc.x = fmaf(sg0, q0.x, acc.x);
                acc.y = fmaf(sg1, q0.y, acc.y);
                acc.z = fmaf(sg2, q1.x, acc.z);
                acc.w = fmaf(sg3, q1.y, acc.w);
            }
            if (prev >= 0)
                red4(&agg[(size_t)prev * HID + lane * 4], acc);
        }
        __syncthreads();
    }
}

// ---------------- residual + relu (+ fp16 mirror) ----------------
__global__ void k_update(float* __restrict__ h, __half* __restrict__ hh,
                         const float* __restrict__ agg, int n) {
    int i = blockIdx.x * blockDim.x + threadIdx.x;
    int stride = gridDim.x * blockDim.x;
    for (; i < n; i += stride) {
        float v = fmaxf(h[i] + agg[i], 0.0f);
        h[i] = v;
        hh[i] = __float2half_rn(v);
    }
}

// ---------------- fused last update + pooling (batch sorted) ----------------
__global__ void k_update_pool(const float* __restrict__ h, const float* __restrict__ agg,
                              const int* __restrict__ batch,
                              float* __restrict__ pool, float* __restrict__ cnt) {
    const int NPB = 256;
    int n0 = blockIdx.x * NPB;
    if (n0 >= N_NODES) return;
    int c = threadIdx.x;  // 128
    float s = 0.0f;
    int cur = batch[n0];
    int mycnt = 0;
    for (int i = 0; i < NPB; i++) {
        int n = n0 + i;
        if (n >= N_NODES) break;
        int b = batch[n];
        if (b != cur) {
            atomicAdd(&pool[cur * HID + c], s);
            if (c == 0) atomicAdd(&cnt[cur], (float)mycnt);
            s = 0.0f; mycnt = 0; cur = b;
        }
        s += fmaxf(h[(size_t)n * HID + c] + agg[(size_t)n * HID + c], 0.0f);
        mycnt++;
    }
    atomicAdd(&pool[cur * HID + c], s);
    if (c == 0) atomicAdd(&cnt[cur], (float)mycnt);
}

// ---------------- head ----------------
__global__ void k_head(const float* __restrict__ pool, const float* __restrict__ cnt,
                       const float* __restrict__ W1, const float* __restrict__ b1,
                       const float* __restrict__ W2, const float* __restrict__ b2,
                       float* __restrict__ out) {
    int g = blockIdx.x;
    int c = threadIdx.x;
    __shared__ float p[128];
    __shared__ float t1[128];
    float invc = 1.0f / fmaxf(cnt[g], 1.0f);
    p[c] = pool[g * HID + c] * invc;
    __syncthreads();
    float v = b1[c];
#pragma unroll 16
    for (int k = 0; k < 128; k++) v += p[k] * W1[k * 128 + c];
    t1[c] = fmaxf(v, 0.0f);
    __syncthreads();
    if (c < 3) {
        float o = b2[c];
        for (int k = 0; k < 128; k++) o += t1[k] * W2[k * 3 + c];
        out[g * 3 + c] = o;
    }
}

// ---------------- launch ----------------
extern "C" void kernel_launch(void* const* d_in, const int* in_sizes, int n_in,
                              void* d_out, int out_size) {
    const float* x   = (const float*)d_in[0];
    const int*   ei  = (const int*)d_in[1];
    const float* ea  = (const float*)d_in[2];
    const int*   bat = (const int*)d_in[3];
    const float* Wf1 = (const float*)d_in[4];
    const float* bf1 = (const float*)d_in[5];
    const float* Ws1 = (const float*)d_in[6];
    const float* bs1 = (const float*)d_in[7];
    const float* Wp  = (const float*)d_in[8];
    const float* bp  = (const float*)d_in[9];
    const float* Wc[2]  = { (const float*)d_in[10], (const float*)d_in[14] };
    const float* bcf[2] = { (const float*)d_in[11], (const float*)d_in[15] };
    const float* Wsc[2] = { (const float*)d_in[12], (const float*)d_in[16] };
    const float* bcs[2] = { (const float*)d_in[13], (const float*)d_in[17] };
    const float* W1  = (const float*)d_in[18];
    const float* b1  = (const float*)d_in[19];
    const float* W2  = (const float*)d_in[20];
    const float* b2  = (const float*)d_in[21];
    float* out = (float*)d_out;

    float *pH, *pAgg, *pPool;
    __half *pPA, *pPB, *pHH, *pEAS, *pWTP, *pWTE;
    int *pDeg, *pCur, *pPart, *pSrcs, *pDsts;
    int4 *pEsd;
    cudaGetSymbolAddress((void**)&pH,    g_h);
    cudaGetSymbolAddress((void**)&pHH,   g_hh);
    cudaGetSymbolAddress((void**)&pPA,   g_PA);
    cudaGetSymbolAddress((void**)&pPB,   g_PB);
    cudaGetSymbolAddress((void**)&pAgg,  g_agg);
    cudaGetSymbolAddress((void**)&pPool, g_pool);
    cudaGetSymbolAddress((void**)&pDeg,  g_deg);
    cudaGetSymbolAddress((void**)&pCur,  g_cursor);
    cudaGetSymbolAddress((void**)&pPart, g_part);
    cudaGetSymbolAddress((void**)&pEsd,  g_esd);
    cudaGetSymbolAddress((void**)&pSrcs, g_srcs);
    cudaGetSymbolAddress((void**)&pDsts, g_dsts);
    cudaGetSymbolAddress((void**)&pEAS,  g_eas);
    cudaGetSymbolAddress((void**)&pWTP,  g_wTproj);
    cudaGetSymbolAddress((void**)&pWTE,  g_wTedge);

    const int EDGE_SMEM = (256 * WT_S + 64 * EA_S + 64 * EH_S) * 2;
    const int PROJ_SMEM = 2 * 128 * PJ_S * 2;
    cudaFuncSetAttribute(k_edge_fused, cudaFuncAttributeMaxDynamicSharedMemorySize, EDGE_SMEM);
    cudaFuncSetAttribute(k_proj_all, cudaFuncAttributeMaxDynamicSharedMemorySize, PROJ_SMEM);

    // ---- zeroing via graph memset nodes ----
    cudaMemsetAsync(pDeg, 0, N_NODES * sizeof(int));
    cudaMemsetAsync(pAgg, 0, N_NODES * 3 * sizeof(float));
    cudaMemsetAsync(pPool, 0, (NGRAPH * HID + NGRAPH) * sizeof(float));

    // ---- weight prep (once per layer) ----
    const int WPREP_N = 4 * 128 * 128 + 256 * 32;
    for (int l = 0; l < 2; l++)
        k_wprep<<<(WPREP_N + 255) / 256, 256>>>(Wc[l], Wsc[l],
                                                pWTP + l * 4 * 128 * 128,
                                                pWTE + l * 256 * 32);

    // ---- build CSR + conv1 (ea read exactly once) ----
    k_hist<<<N_EDGES / 256, 256>>>(ei, pDeg);
    k_scan_a<<<SCAN_NB, SCAN_B>>>(pDeg, pCur, pPart);
    k_scan_b<<<1, 256>>>(pPart, SCAN_NB);
    k_perm<<<N_EDGES / 256, 256>>>(ei, pCur, pPart, pEsd);
    k_gather_conv1<<<N_EDGES / 256, 256>>>(pEsd, ea, x, Wf1, bf1, Ws1, bs1,
                                           pSrcs, pDsts, pEAS, pAgg);
    k_node1<<<592, 256>>>(x, pAgg, Wp, bp, pH, pHH);

    // ---- hidden convs ----
    for (int l = 0; l < 2; l++) {
        k_proj_all<<<(N_NODES + 127) / 128, 256, PROJ_SMEM>>>(
            pHH, pWTP + l * 4 * 128 * 128, bcf[l], bcs[l], pPA, pPB);
        cudaMemsetAsync(pAgg, 0, (size_t)N_NODES * HID * sizeof(float));
        k_edge_fused<<<444, 256, EDGE_SMEM>>>(pSrcs, pDsts, pEAS, pPA, pPB,
                                              pWTE + l * 256 * 32, pAgg);
        if (l == 0)
            k_update<<<2048, 256>>>(pH, pHH, pAgg, N_NODES * HID);
        else
            k_update_pool<<<(N_NODES + 255) / 256, 128>>>(pH, pAgg, bat,
                                                          pPool, pPool + NGRAPH * HID);
    }

    // ---- head ----
    k_head<<<NGRAPH, 128>>>(pPool, pPool + NGRAPH * HID, W1, b1, W2, b2, out);
}

// round 14
// speedup vs baseline: 1.3175x; 1.0056x over previous
#include <cuda_runtime.h>
#include <cuda_fp16.h>
#include <math.h>

#define N_NODES 100000
#define N_EDGES 1600000
#define HID 128
#define NGRAPH 64
#define ETILE 64
#define NTILES (N_EDGES / ETILE)
#define SCAN_B 512
#define SCAN_NB ((N_NODES + SCAN_B - 1) / SCAN_B)   // 196

// ---------------- device scratch ----------------
__device__ float  g_h[N_NODES * HID];
__device__ __half g_hh[N_NODES * HID];
__device__ __half g_PA[N_NODES * 256];   // [f(128) | s(128)] per node (+bias)
__device__ __half g_PB[N_NODES * 256];
__device__ float  g_agg[N_NODES * HID];
__device__ float  g_pool[NGRAPH * HID + NGRAPH];
__device__ int    g_deg[N_NODES];
__device__ int    g_cursor[N_NODES];
__device__ int    g_part[256];
__device__ int4   g_esd[N_EDGES];
__device__ int    g_srcs[N_EDGES];
__device__ int    g_dsts[N_EDGES];
__device__ __half g_eas[(size_t)N_EDGES * 32];
__device__ __half g_wTproj[2 * 4 * 128 * 128];
__device__ __half g_wTedge[2 * 256 * 32];

// ---------------- helpers ----------------
__device__ __forceinline__ float sigmoidf_(float x) { return 1.0f / (1.0f + __expf(-x)); }
__device__ __forceinline__ float softplusf_(float x) {
    return fmaxf(x, 0.0f) + __logf(1.0f + __expf(-fabsf(x)));
}
__device__ __forceinline__ half2 ex2h2_(half2 x) {
    unsigned y;
    asm("ex2.approx.f16x2 %0, %1;" : "=r"(y) : "r"(*(unsigned*)&x));
    return *(half2*)&y;
}
__device__ __forceinline__ half2 tanhh2_(half2 x) {
    unsigned y;
    asm("tanh.approx.f16x2 %0, %1;" : "=r"(y) : "r"(*(unsigned*)&x));
    return *(half2*)&y;
}
__device__ __forceinline__ void red4(float* p, float4 v) {
    asm volatile("red.global.add.v4.f32 [%0], {%1,%2,%3,%4};"
                 :: "l"(p), "f"(v.x), "f"(v.y), "f"(v.z), "f"(v.w));
}
__device__ __forceinline__ void mma_f16(float d[4],
                                        unsigned a0, unsigned a1, unsigned a2, unsigned a3,
                                        unsigned b0, unsigned b1) {
    asm volatile("mma.sync.aligned.m16n8k16.row.col.f32.f16.f16.f32 "
                 "{%0,%1,%2,%3}, {%4,%5,%6,%7}, {%8,%9}, {%0,%1,%2,%3};\n"
                 : "+f"(d[0]), "+f"(d[1]), "+f"(d[2]), "+f"(d[3])
                 : "r"(a0), "r"(a1), "r"(a2), "r"(a3), "r"(b0), "r"(b1));
}

// ---------------- weight prep ----------------
__global__ void k_wprep(const float* __restrict__ Wf, const float* __restrict__ Ws,
                        __half* __restrict__ wTproj, __half* __restrict__ wTedge) {
    int idx = blockIdx.x * blockDim.x + threadIdx.x;
    if (idx < 4 * 128 * 128) {
        int part = idx >> 14;
        int rem = idx & 16383;
        int c = rem >> 7;
        int k = rem & 127;
        const float* W;
        if (part == 0)      W = Wf;
        else if (part == 1) W = Ws;
        else if (part == 2) W = Wf + 128 * 128;
        else                W = Ws + 128 * 128;
        wTproj[idx] = __float2half_rn(W[k * 128 + c]);
    } else if (idx < 4 * 128 * 128 + 256 * 32) {
        int i2 = idx - 4 * 128 * 128;
        int c = i2 >> 5;
        int k = i2 & 31;
        float v = (c < 128) ? Wf[(256 + k) * 128 + c]
                            : Ws[(256 + k) * 128 + (c - 128)];
        wTedge[i2] = __float2half_rn(v);
    }
}

// ---------------- CSR build ----------------
__global__ void k_hist(const int* __restrict__ ei, int* __restrict__ deg) {
    int e = blockIdx.x * blockDim.x + threadIdx.x;
    if (e < N_EDGES) atomicAdd(&deg[ei[N_EDGES + e]], 1);
}
__global__ void k_scan_a(const int* __restrict__ deg, int* __restrict__ cursor,
                         int* __restrict__ part) {
    __shared__ int s[SCAN_B];
    int i = blockIdx.x * SCAN_B + threadIdx.x;
    int v = (i < N_NODES) ? deg[i] : 0;
    s[threadIdx.x] = v;
    __syncthreads();
    for (int off = 1; off < SCAN_B; off <<= 1) {
        int t = (threadIdx.x >= off) ? s[threadIdx.x - off] : 0;
        __syncthreads();
        s[threadIdx.x] += t;
        __syncthreads();
    }
    if (i < N_NODES) cursor[i] = s[threadIdx.x] - v;
    if (threadIdx.x == SCAN_B - 1) part[blockIdx.x] = s[threadIdx.x];
}
__global__ void k_scan_b(int* __restrict__ part, int nb) {
    __shared__ int s[256];
    int v = (threadIdx.x < nb) ? part[threadIdx.x] : 0;
    s[threadIdx.x] = v;
    __syncthreads();
    for (int off = 1; off < 256; off <<= 1) {
        int t = (threadIdx.x >= off) ? s[threadIdx.x - off] : 0;
        __syncthreads();
        s[threadIdx.x] += t;
        __syncthreads();
    }
    if (threadIdx.x < nb) part[threadIdx.x] = s[threadIdx.x] - v;
}

// ---------------- pass 1: pure permutation scatter ----------------
__global__ void k_perm(const int* __restrict__ ei,
                       int* __restrict__ cursor, const int* __restrict__ part,
                       int4* __restrict__ esd) {
    int e = blockIdx.x * blockDim.x + threadIdx.x;
    if (e >= N_EDGES) return;
    int src = ei[e];
    int dst = ei[N_EDGES + e];
    int pos = atomicAdd(&cursor[dst], 1) + part[dst >> 9];  // SCAN_B = 512
    esd[pos] = make_int4(src, dst, e, 0);
}

// ---------------- pass 2: gather-convert + conv1 (single ea pass) ----------------
__global__ void k_gather_conv1(const int4* __restrict__ esd, const float* __restrict__ ea,
                               const float* __restrict__ x,
                               const float* __restrict__ Wf, const float* __restrict__ bf,
                               const float* __restrict__ Ws, const float* __restrict__ bs,
                               int* __restrict__ srcs, int* __restrict__ dsts,
                               __half* __restrict__ eas, float* __restrict__ agg) {
    __shared__ float sWf[38 * 3], sWs[38 * 3], sbf[3], sbs[3];
    int t = threadIdx.x;
    if (t < 114) { sWf[t] = Wf[t]; sWs[t] = Ws[t]; }
    if (t < 3)   { sbf[t] = bf[t]; sbs[t] = bs[t]; }
    __syncthreads();
    int p = blockIdx.x * blockDim.x + t;
    if (p >= N_EDGES) return;
    int4 rec = esd[p];
    int src = rec.x;
    int dst = rec.y;
    srcs[p] = src;
    dsts[p] = dst;

    float lf0 = sbf[0], lf1 = sbf[1], lf2 = sbf[2];
    float ls0 = sbs[0], ls1 = sbs[1], ls2 = sbs[2];
    {
        float zz[6] = { x[dst * 3 + 0], x[dst * 3 + 1], x[dst * 3 + 2],
                        x[src * 3 + 0], x[src * 3 + 1], x[src * 3 + 2] };
#pragma unroll
        for (int r = 0; r < 6; r++) {
            float zv = zz[r];
            lf0 = fmaf(zv, sWf[r * 3 + 0], lf0);
            lf1 = fmaf(zv, sWf[r * 3 + 1], lf1);
            lf2 = fmaf(zv, sWf[r * 3 + 2], lf2);
            ls0 = fmaf(zv, sWs[r * 3 + 0], ls0);
            ls1 = fmaf(zv, sWs[r * 3 + 1], ls1);
            ls2 = fmaf(zv, sWs[r * 3 + 2], ls2);
        }
    }
    const float4* s = (const float4*)&ea[(size_t)rec.z * 32];
    __half* d = &eas[(size_t)p * 32];
#pragma unroll
    for (int j = 0; j < 4; j++) {
        float4 a = s[j * 2];
        float4 b = s[j * 2 + 1];
        float q[8] = { a.x, a.y, a.z, a.w, b.x, b.y, b.z, b.w };
#pragma unroll
        for (int k = 0; k < 8; k++) {
            int r = 6 + j * 8 + k;
            float zv = q[k];
            lf0 = fmaf(zv, sWf[r * 3 + 0], lf0);
            lf1 = fmaf(zv, sWf[r * 3 + 1], lf1);
            lf2 = fmaf(zv, sWf[r * 3 + 2], lf2);
            ls0 = fmaf(zv, sWs[r * 3 + 0], ls0);
            ls1 = fmaf(zv, sWs[r * 3 + 1], ls1);
            ls2 = fmaf(zv, sWs[r * 3 + 2], ls2);
        }
        half2 h0 = __floats2half2_rn(a.x, a.y);
        half2 h1 = __floats2half2_rn(a.z, a.w);
        half2 h2 = __floats2half2_rn(b.x, b.y);
        half2 h3 = __floats2half2_rn(b.z, b.w);
        uint4 pk;
        pk.x = *(unsigned*)&h0; pk.y = *(unsigned*)&h1;
        pk.z = *(unsigned*)&h2; pk.w = *(unsigned*)&h3;
        *(uint4*)&d[j * 8] = pk;
    }
    atomicAdd(&agg[dst * 3 + 0], sigmoidf_(lf0) * softplusf_(ls0));
    atomicAdd(&agg[dst * 3 + 1], sigmoidf_(lf1) * softplusf_(ls1));
    atomicAdd(&agg[dst * 3 + 2], sigmoidf_(lf2) * softplusf_(ls2));
}

// ---------------- node projection after conv1 (grid-stride) ----------------
__global__ void k_node1(const float* __restrict__ x, const float* __restrict__ agg,
                        const float* __restrict__ Wp, const float* __restrict__ bp,
                        float* __restrict__ h, __half* __restrict__ hh) {
    int i = blockIdx.x * blockDim.x + threadIdx.x;
    int stride = gridDim.x * blockDim.x;
    for (; i < N_NODES * HID; i += stride) {
        int n = i >> 7;
        int c = i & 127;
        float s0 = x[n * 3 + 0] + agg[n * 3 + 0];
        float s1 = x[n * 3 + 1] + agg[n * 3 + 1];
        float s2 = x[n * 3 + 2] + agg[n * 3 + 2];
        float v = bp[c] + s0 * Wp[c] + s1 * Wp[128 + c] + s2 * Wp[256 + c];
        v = fmaxf(v, 0.0f);
        h[i] = v;
        hh[i] = __float2half_rn(v);
    }
}

// ---------------- fused 4-part node projection (prepped fp16 W) ----------------
#define PJ_S 136
__global__ __launch_bounds__(256, 3) void k_proj_all(
        const __half* __restrict__ hh,
        const __half* __restrict__ wT,
        const float* __restrict__ bf, const float* __restrict__ bs,
        __half* __restrict__ PA, __half* __restrict__ PB) {
    extern __shared__ __half psm[];
    __half* hs  = psm;                 // [128 rows][136]
    __half* wsT = psm + 128 * PJ_S;    // [128 cols][136 k]

    int t = threadIdx.x;
    int lane = t & 31;
    int w = t >> 5;
    int g = lane >> 2;
    int tig = lane & 3;
    int n0 = blockIdx.x * 128;

#pragma unroll
    for (int j = 0; j < 8; j++) {
        int idx = t + j * 256;
        int row = idx >> 4;
        int c = (idx & 15) * 8;
        uint4 v = make_uint4(0, 0, 0, 0);
        int n = n0 + row;
        if (n < N_NODES) v = *(const uint4*)&hh[(size_t)n * 128 + c];
        *(uint4*)&hs[row * PJ_S + c] = v;
    }

    int r0 = w * 16;
#pragma unroll 1
    for (int part = 0; part < 4; part++) {
        const float* bias; __half* out; int coloff;
        if (part == 0)      { bias = bf;      out = PA; coloff = 0;   }
        else if (part == 1) { bias = bs;      out = PA; coloff = 128; }
        else if (part == 2) { bias = nullptr; out = PB; coloff = 0;   }
        else                { bias = nullptr; out = PB; coloff = 128; }
        const uint4* wsrc = (const uint4*)&wT[part * 128 * 128];

        __syncthreads();
#pragma unroll
        for (int j = 0; j < 8; j++) {
            int idx4 = t + j * 256;
            int col = idx4 >> 4;
            int k8 = idx4 & 15;
            *(uint4*)&wsT[col * PJ_S + k8 * 8] = wsrc[idx4];
        }
        __syncthreads();

#pragma unroll
        for (int h2i = 0; h2i < 2; h2i++) {
            float acc[8][4];
#pragma unroll
            for (int i = 0; i < 8; i++)
#pragma unroll
                for (int j = 0; j < 4; j++) acc[i][j] = 0.0f;
#pragma unroll
            for (int kb8 = 0; kb8 < 8; kb8++) {
                int kb = kb8 * 16;
                unsigned a0 = *(const unsigned*)&hs[(r0 + g) * PJ_S + kb + 2 * tig];
                unsigned a1 = *(const unsigned*)&hs[(r0 + g + 8) * PJ_S + kb + 2 * tig];
                unsigned a2 = *(const unsigned*)&hs[(r0 + g) * PJ_S + kb + 2 * tig + 8];
                unsigned a3 = *(const unsigned*)&hs[(r0 + g + 8) * PJ_S + kb + 2 * tig + 8];
#pragma unroll
                for (int nt = 0; nt < 8; nt++) {
                    int col = h2i * 64 + nt * 8 + g;
                    unsigned b0 = *(const unsigned*)&wsT[col * PJ_S + kb + 2 * tig];
                    unsigned b1 = *(const unsigned*)&wsT[col * PJ_S + kb + 2 * tig + 8];
                    mma_f16(acc[nt], a0, a1, a2, a3, b0, b1);
                }
            }
#pragma unroll
            for (int nt = 0; nt < 8; nt++) {
                int c = h2i * 64 + nt * 8 + 2 * tig;
                float b0 = 0.f, b1 = 0.f;
                if (bias) { b0 = bias[c]; b1 = bias[c + 1]; }
                int n = n0 + r0 + g;
                if (n < N_NODES)
                    *(half2*)&out[(size_t)n * 256 + coloff + c] =
                        __floats2half2_rn(acc[nt][0] + b0, acc[nt][1] + b1);
                n = n0 + r0 + g + 8;
                if (n < N_NODES)
                    *(half2*)&out[(size_t)n * 256 + coloff + c] =
                        __floats2half2_rn(acc[nt][2] + b0, acc[nt][3] + b1);
            }
        }
    }
}

// ---------------- fused edge kernel (fp16 gating throughout) ----------------
#define WT_S 40
#define EA_S 40
#define EH_S 264
__global__ __launch_bounds__(256, 3) void k_edge_fused(
        const int* __restrict__ srcs, const int* __restrict__ dsts,
        const __half* __restrict__ eas,
        const __half* __restrict__ PA, const __half* __restrict__ PB,
        const __half* __restrict__ wTe,
        float* __restrict__ agg) {
    extern __shared__ __half sm[];
    __half* wsT  = sm;
    __half* seas = sm + 256 * WT_S;
    __half* Eh   = sm + 256 * WT_S + 64 * EA_S;

    int t = threadIdx.x;
    int lane = t & 31;
    int w = t >> 5;
    int g = lane >> 2;
    int tig = lane & 3;

    {
        const uint4* wsrc = (const uint4*)wTe;
#pragma unroll
        for (int j = 0; j < 4; j++) {
            int idx4 = t + j * 256;
            int col = idx4 >> 2;
            int k8 = idx4 & 3;
            *(uint4*)&wsT[col * WT_S + k8 * 8] = wsrc[idx4];
        }
    }
    __syncthreads();

    int erow0 = (w & 3) * 16;
    int col0 = (w >> 2) * 128;
    const half2 nl2e = __floats2half2_rn(-1.44269504f, -1.44269504f);
    const half2 two2 = __floats2half2_rn(2.f, 2.f);
    const half2 m1h  = __floats2half2_rn(-1.f, -1.f);
    const half2 zr2  = __floats2half2_rn(0.f, 0.f);
    const half2 h05  = __floats2half2_rn(0.5f, 0.5f);
    const half2 c0h = __floats2half2_rn(0.405542f, 0.405542f);
    const half2 c1h = __floats2half2_rn(0.333342f, 0.333342f);
    const half2 c2h = __floats2half2_rn(-0.0554078f, -0.0554078f);
    const half2 c3h = __floats2half2_rn(0.0122789f, 0.0122789f);
    const half2 c4h = __floats2half2_rn(-0.00346625f, -0.00346625f);
    const half2 c5h = __floats2half2_rn(0.000951552f, 0.000951552f);

    for (int tile = blockIdx.x; tile < NTILES; tile += gridDim.x) {
        long e0 = (long)tile * ETILE;
        {
            uint4 v = *(const uint4*)&eas[e0 * 32 + t * 8];
            int row = t >> 2;
            int c = (t & 3) * 8;
            *(uint4*)&seas[row * EA_S + c] = v;
        }
        __syncthreads();

        // phase 1: E = ea @ [Wef|Wes]
#pragma unroll
        for (int h2i = 0; h2i < 2; h2i++) {
            float acc[8][4];
#pragma unroll
            for (int i = 0; i < 8; i++)
#pragma unroll
                for (int j = 0; j < 4; j++) acc[i][j] = 0.0f;
#pragma unroll
            for (int ks = 0; ks < 2; ks++) {
                int kb = ks * 16;
                unsigned a0 = *(const unsigned*)&seas[(erow0 + g) * EA_S + kb + 2 * tig];
                unsigned a1 = *(const unsigned*)&seas[(erow0 + g + 8) * EA_S + kb + 2 * tig];
                unsigned a2 = *(const unsigned*)&seas[(erow0 + g) * EA_S + kb + 2 * tig + 8];
                unsigned a3 = *(const unsigned*)&seas[(erow0 + g + 8) * EA_S + kb + 2 * tig + 8];
#pragma unroll
                for (int nt = 0; nt < 8; nt++) {
                    int col = col0 + h2i * 64 + nt * 8 + g;
                    unsigned b0 = *(const unsigned*)&wsT[col * WT_S + kb + 2 * tig];
                    unsigned b1 = *(const unsigned*)&wsT[col * WT_S + kb + 2 * tig + 8];
                    mma_f16(acc[nt], a0, a1, a2, a3, b0, b1);
                }
            }
#pragma unroll
            for (int nt = 0; nt < 8; nt++) {
                int c = col0 + h2i * 64 + nt * 8 + 2 * tig;
                *(half2*)&Eh[(erow0 + g) * EH_S + c]     = __floats2half2_rn(acc[nt][0], acc[nt][1]);
                *(half2*)&Eh[(erow0 + g + 8) * EH_S + c] = __floats2half2_rn(acc[nt][2], acc[nt][3]);
            }
        }
        __syncthreads();

        // phase 2: prefetch-8 gather, fp16 tanh sigmoid + poly softplus, grouped flush
        {
            int srcs8[8], dsts8[8];
#pragma unroll
            for (int j = 0; j < 8; j++) {
                long e = e0 + w * 8 + j;
                srcs8[j] = srcs[e];
                dsts8[j] = dsts[e];
            }
            uint2 pbf[8], pbs[8];
#pragma unroll
            for (int j = 0; j < 8; j++) {
                size_t base = (size_t)srcs8[j] * 256 + lane * 4;
                pbf[j] = *(const uint2*)&PB[base];
                pbs[j] = *(const uint2*)&PB[base + 128];
            }
            int prev = -1;
            float4 acc = make_float4(0.f, 0.f, 0.f, 0.f);
            half2 af01, af23, as01, as23;
            af01 = af23 = as01 = as23 = __floats2half2_rn(0.f, 0.f);
#pragma unroll
            for (int j = 0; j < 8; j++) {
                int le = w * 8 + j;
                int dst = dsts8[j];
                if (dst != prev) {
                    if (prev >= 0)
                        red4(&agg[(size_t)prev * HID + lane * 4], acc);
                    acc = make_float4(0.f, 0.f, 0.f, 0.f);
                    size_t base = (size_t)dst * 256 + lane * 4;
                    uint2 pafu = *(const uint2*)&PA[base];
                    uint2 pasu = *(const uint2*)&PA[base + 128];
                    af01 = *(half2*)&pafu.x; af23 = *(half2*)&pafu.y;
                    as01 = *(half2*)&pasu.x; as23 = *(half2*)&pasu.y;
                    prev = dst;
                }
                uint2 efu = *(const uint2*)&Eh[le * EH_S + lane * 4];
                uint2 esu = *(const uint2*)&Eh[le * EH_S + 128 + lane * 4];

                half2 lf01 = __hadd2(__hadd2(*(half2*)&efu.x, af01), *(half2*)&pbf[j].x);
                half2 lf23 = __hadd2(__hadd2(*(half2*)&efu.y, af23), *(half2*)&pbf[j].y);
                half2 ls01 = __hadd2(__hadd2(*(half2*)&esu.x, as01), *(half2*)&pbs[j].x);
                half2 ls23 = __hadd2(__hadd2(*(half2*)&esu.y, as23), *(half2*)&pbs[j].y);

                // softplus: t = exp(-|s|), log1p(t) deg-5 Horner in u = 2t-1
                half2 t01 = ex2h2_(__hmul2(__habs2(ls01), nl2e));
                half2 t23 = ex2h2_(__hmul2(__habs2(ls23), nl2e));
                half2 u01 = __hfma2(t01, two2, m1h);
                half2 u23 = __hfma2(t23, two2, m1h);
                half2 p01 = __hfma2(c5h, u01, c4h);
                half2 p23 = __hfma2(c5h, u23, c4h);
                p01 = __hfma2(p01, u01, c3h);  p23 = __hfma2(p23, u23, c3h);
                p01 = __hfma2(p01, u01, c2h);  p23 = __hfma2(p23, u23, c2h);
                p01 = __hfma2(p01, u01, c1h);  p23 = __hfma2(p23, u23, c1h);
                p01 = __hfma2(p01, u01, c0h);  p23 = __hfma2(p23, u23, c0h);
                half2 sp01 = __hadd2(__hmax2(ls01, zr2), p01);
                half2 sp23 = __hadd2(__hmax2(ls23, zr2), p23);

                // sigmoid in packed fp16: 0.5*tanh(0.5*lf) + 0.5
                half2 sg01 = __hfma2(tanhh2_(__hmul2(lf01, h05)), h05, h05);
                half2 sg23 = __hfma2(tanhh2_(__hmul2(lf23, h05)), h05, h05);

                // message in fp16, accumulate in fp32
                float2 m0 = __half22float2(__hmul2(sg01, sp01));
                float2 m1 = __half22float2(__hmul2(sg23, sp23));
                acc.x += m0.x;
                acc.y += m0.y;
                acc.z += m1.x;
                acc.w += m1.y;
            }
            if (prev >= 0)
                red4(&agg[(size_t)prev * HID + lane * 4], acc);
        }
        __syncthreads();
    }
}

// ---------------- residual + relu (+ fp16 mirror) ----------------
__global__ void k_update(float* __restrict__ h, __half* __restrict__ hh,
                         const float* __restrict__ agg, int n) {
    int i = blockIdx.x * blockDim.x + threadIdx.x;
    int stride = gridDim.x * blockDim.x;
    for (; i < n; i += stride) {
        float v = fmaxf(h[i] + agg[i], 0.0f);
        h[i] = v;
        hh[i] = __float2half_rn(v);
    }
}

// ---------------- fused last update + pooling (batch sorted) ----------------
__global__ void k_update_pool(const float* __restrict__ h, const float* __restrict__ agg,
                              const int* __restrict__ batch,
                              float* __restrict__ pool, float* __restrict__ cnt) {
    const int NPB = 256;
    int n0 = blockIdx.x * NPB;
    if (n0 >= N_NODES) return;
    int c = threadIdx.x;  // 128
    float s = 0.0f;
    int cur = batch[n0];
    int mycnt = 0;
    for (int i = 0; i < NPB; i++) {
        int n = n0 + i;
        if (n >= N_NODES) break;
        int b = batch[n];
        if (b != cur) {
            atomicAdd(&pool[cur * HID + c], s);
            if (c == 0) atomicAdd(&cnt[cur], (float)mycnt);
            s = 0.0f; mycnt = 0; cur = b;
        }
        s += fmaxf(h[(size_t)n * HID + c] + agg[(size_t)n * HID + c], 0.0f);
        mycnt++;
    }
    atomicAdd(&pool[cur * HID + c], s);
    if (c == 0) atomicAdd(&cnt[cur], (float)mycnt);
}

// ---------------- head ----------------
__global__ void k_head(const float* __restrict__ pool, const float* __restrict__ cnt,
                       const float* __restrict__ W1, const float* __restrict__ b1,
                       const float* __restrict__ W2, const float* __restrict__ b2,
                       float* __restrict__ out) {
    int g = blockIdx.x;
    int c = threadIdx.x;
    __shared__ float p[128];
    __shared__ float t1[128];
    float invc = 1.0f / fmaxf(cnt[g], 1.0f);
    p[c] = pool[g * HID + c] * invc;
    __syncthreads();
    float v = b1[c];
#pragma unroll 16
    for (int k = 0; k < 128; k++) v += p[k] * W1[k * 128 + c];
    t1[c] = fmaxf(v, 0.0f);
    __syncthreads();
    if (c < 3) {
        float o = b2[c];
        for (int k = 0; k < 128; k++) o += t1[k] * W2[k * 3 + c];
        out[g * 3 + c] = o;
    }
}

// ---------------- launch ----------------
extern "C" void kernel_launch(void* const* d_in, const int* in_sizes, int n_in,
                              void* d_out, int out_size) {
    const float* x   = (const float*)d_in[0];
    const int*   ei  = (const int*)d_in[1];
    const float* ea  = (const float*)d_in[2];
    const int*   bat = (const int*)d_in[3];
    const float* Wf1 = (const float*)d_in[4];
    const float* bf1 = (const float*)d_in[5];
    const float* Ws1 = (const float*)d_in[6];
    const float* bs1 = (const float*)d_in[7];
    const float* Wp  = (const float*)d_in[8];
    const float* bp  = (const float*)d_in[9];
    const float* Wc[2]  = { (const float*)d_in[10], (const float*)d_in[14] };
    const float* bcf[2] = { (const float*)d_in[11], (const float*)d_in[15] };
    const float* Wsc[2] = { (const float*)d_in[12], (const float*)d_in[16] };
    const float* bcs[2] = { (const float*)d_in[13], (const float*)d_in[17] };
    const float* W1  = (const float*)d_in[18];
    const float* b1  = (const float*)d_in[19];
    const float* W2  = (const float*)d_in[20];
    const float* b2  = (const float*)d_in[21];
    float* out = (float*)d_out;

    float *pH, *pAgg, *pPool;
    __half *pPA, *pPB, *pHH, *pEAS, *pWTP, *pWTE;
    int *pDeg, *pCur, *pPart, *pSrcs, *pDsts;
    int4 *pEsd;
    cudaGetSymbolAddress((void**)&pH,    g_h);
    cudaGetSymbolAddress((void**)&pHH,   g_hh);
    cudaGetSymbolAddress((void**)&pPA,   g_PA);
    cudaGetSymbolAddress((void**)&pPB,   g_PB);
    cudaGetSymbolAddress((void**)&pAgg,  g_agg);
    cudaGetSymbolAddress((void**)&pPool, g_pool);
    cudaGetSymbolAddress((void**)&pDeg,  g_deg);
    cudaGetSymbolAddress((void**)&pCur,  g_cursor);
    cudaGetSymbolAddress((void**)&pPart, g_part);
    cudaGetSymbolAddress((void**)&pEsd,  g_esd);
    cudaGetSymbolAddress((void**)&pSrcs, g_srcs);
    cudaGetSymbolAddress((void**)&pDsts, g_dsts);
    cudaGetSymbolAddress((void**)&pEAS,  g_eas);
    cudaGetSymbolAddress((void**)&pWTP,  g_wTproj);
    cudaGetSymbolAddress((void**)&pWTE,  g_wTedge);

    const int EDGE_SMEM = (256 * WT_S + 64 * EA_S + 64 * EH_S) * 2;
    const int PROJ_SMEM = 2 * 128 * PJ_S * 2;
    cudaFuncSetAttribute(k_edge_fused, cudaFuncAttributeMaxDynamicSharedMemorySize, EDGE_SMEM);
    cudaFuncSetAttribute(k_proj_all, cudaFuncAttributeMaxDynamicSharedMemorySize, PROJ_SMEM);

    // ---- zeroing via graph memset nodes ----
    cudaMemsetAsync(pDeg, 0, N_NODES * sizeof(int));
    cudaMemsetAsync(pAgg, 0, N_NODES * 3 * sizeof(float));
    cudaMemsetAsync(pPool, 0, (NGRAPH * HID + NGRAPH) * sizeof(float));

    // ---- weight prep (once per layer) ----
    const int WPREP_N = 4 * 128 * 128 + 256 * 32;
    for (int l = 0; l < 2; l++)
        k_wprep<<<(WPREP_N + 255) / 256, 256>>>(Wc[l], Wsc[l],
                                                pWTP + l * 4 * 128 * 128,
                                                pWTE + l * 256 * 32);

    // ---- build CSR + conv1 (ea read exactly once) ----
    k_hist<<<N_EDGES / 256, 256>>>(ei, pDeg);
    k_scan_a<<<SCAN_NB, SCAN_B>>>(pDeg, pCur, pPart);
    k_scan_b<<<1, 256>>>(pPart, SCAN_NB);
    k_perm<<<N_EDGES / 256, 256>>>(ei, pCur, pPart, pEsd);
    k_gather_conv1<<<N_EDGES / 256, 256>>>(pEsd, ea, x, Wf1, bf1, Ws1, bs1,
                                           pSrcs, pDsts, pEAS, pAgg);
    k_node1<<<592, 256>>>(x, pAgg, Wp, bp, pH, pHH);

    // ---- hidden convs ----
    for (int l = 0; l < 2; l++) {
        k_proj_all<<<(N_NODES + 127) / 128, 256, PROJ_SMEM>>>(
            pHH, pWTP + l * 4 * 128 * 128, bcf[l], bcs[l], pPA, pPB);
        cudaMemsetAsync(pAgg, 0, (size_t)N_NODES * HID * sizeof(float));
        k_edge_fused<<<444, 256, EDGE_SMEM>>>(pSrcs, pDsts, pEAS, pPA, pPB,
                                              pWTE + l * 256 * 32, pAgg);
        if (l == 0)
            k_update<<<2048, 256>>>(pH, pHH, pAgg, N_NODES * HID);
        else
            k_update_pool<<<(N_NODES + 255) / 256, 128>>>(pH, pAgg, bat,
                                                          pPool, pPool + NGRAPH * HID);
    }

    // ---- head ----
    k_head<<<NGRAPH, 128>>>(pPool, pPool + NGRAPH * HID, W1, b1, W2, b2, out);
}

// round 15
// speedup vs baseline: 1.3332x; 1.0119x over previous
#include <cuda_runtime.h>
#include <cuda_fp16.h>
#include <math.h>

#define N_NODES 100000
#define N_EDGES 1600000
#define HID 128
#define NGRAPH 64
#define ETILE 64
#define NTILES (N_EDGES / ETILE)
#define SCAN_B 512
#define SCAN_NB ((N_NODES + SCAN_B - 1) / SCAN_B)   // 196
#define WPREP_N (4 * 128 * 128 + 256 * 32)

// ---------------- device scratch ----------------
__device__ float  g_h[N_NODES * HID];
__device__ __half g_hh[N_NODES * HID];
__device__ __half g_PA[N_NODES * 256];   // [f(128) | s(128)] per node (+bias)
__device__ __half g_PB[N_NODES * 256];
__device__ float  g_agg[N_NODES * HID];
__device__ float  g_pool[NGRAPH * HID + NGRAPH];
__device__ int    g_deg[N_NODES];
__device__ int    g_cursor[N_NODES];
__device__ int    g_part[256];
__device__ int4   g_esd[N_EDGES];
__device__ int    g_srcs[N_EDGES];
__device__ int    g_dsts[N_EDGES];
__device__ __half g_eas[(size_t)N_EDGES * 32];
__device__ __half g_wTproj[2 * 4 * 128 * 128];
__device__ __half g_wTedge[2 * 256 * 32];

// ---------------- helpers ----------------
__device__ __forceinline__ float sigmoidf_(float x) { return 1.0f / (1.0f + __expf(-x)); }
__device__ __forceinline__ float softplusf_(float x) {
    return fmaxf(x, 0.0f) + __logf(1.0f + __expf(-fabsf(x)));
}
__device__ __forceinline__ half2 ex2h2_(half2 x) {
    unsigned y;
    asm("ex2.approx.f16x2 %0, %1;" : "=r"(y) : "r"(*(unsigned*)&x));
    return *(half2*)&y;
}
__device__ __forceinline__ half2 tanhh2_(half2 x) {
    unsigned y;
    asm("tanh.approx.f16x2 %0, %1;" : "=r"(y) : "r"(*(unsigned*)&x));
    return *(half2*)&y;
}
__device__ __forceinline__ void red4(float* p, float4 v) {
    asm volatile("red.global.add.v4.f32 [%0], {%1,%2,%3,%4};"
                 :: "l"(p), "f"(v.x), "f"(v.y), "f"(v.z), "f"(v.w));
}
__device__ __forceinline__ void mma_f16(float d[4],
                                        unsigned a0, unsigned a1, unsigned a2, unsigned a3,
                                        unsigned b0, unsigned b1) {
    asm volatile("mma.sync.aligned.m16n8k16.row.col.f32.f16.f16.f32 "
                 "{%0,%1,%2,%3}, {%4,%5,%6,%7}, {%8,%9}, {%0,%1,%2,%3};\n"
                 : "+f"(d[0]), "+f"(d[1]), "+f"(d[2]), "+f"(d[3])
                 : "r"(a0), "r"(a1), "r"(a2), "r"(a3), "r"(b0), "r"(b1));
}

// ---------------- weight prep: both layers in one launch ----------------
__global__ void k_wprep2(const float* __restrict__ Wf2, const float* __restrict__ Ws2,
                         const float* __restrict__ Wf3, const float* __restrict__ Ws3,
                         __half* __restrict__ wTproj, __half* __restrict__ wTedge) {
    int gidx = blockIdx.x * blockDim.x + threadIdx.x;
    if (gidx >= 2 * WPREP_N) return;
    int layer = gidx / WPREP_N;
    int idx = gidx - layer * WPREP_N;
    const float* Wf = layer ? Wf3 : Wf2;
    const float* Ws = layer ? Ws3 : Ws2;
    if (idx < 4 * 128 * 128) {
        int part = idx >> 14;
        int rem = idx & 16383;
        int c = rem >> 7;
        int k = rem & 127;
        const float* W;
        if (part == 0)      W = Wf;
        else if (part == 1) W = Ws;
        else if (part == 2) W = Wf + 128 * 128;
        else                W = Ws + 128 * 128;
        wTproj[layer * 4 * 128 * 128 + idx] = __float2half_rn(W[k * 128 + c]);
    } else {
        int i2 = idx - 4 * 128 * 128;
        int c = i2 >> 5;
        int k = i2 & 31;
        float v = (c < 128) ? Wf[(256 + k) * 128 + c]
                            : Ws[(256 + k) * 128 + (c - 128)];
        wTedge[layer * 256 * 32 + i2] = __float2half_rn(v);
    }
}

// ---------------- CSR build ----------------
__global__ void k_hist(const int* __restrict__ ei, int* __restrict__ deg) {
    int e = blockIdx.x * blockDim.x + threadIdx.x;
    if (e < N_EDGES) atomicAdd(&deg[ei[N_EDGES + e]], 1);
}
__global__ void k_scan_a(const int* __restrict__ deg, int* __restrict__ cursor,
                         int* __restrict__ part) {
    __shared__ int s[SCAN_B];
    int i = blockIdx.x * SCAN_B + threadIdx.x;
    int v = (i < N_NODES) ? deg[i] : 0;
    s[threadIdx.x] = v;
    __syncthreads();
    for (int off = 1; off < SCAN_B; off <<= 1) {
        int t = (threadIdx.x >= off) ? s[threadIdx.x - off] : 0;
        __syncthreads();
        s[threadIdx.x] += t;
        __syncthreads();
    }
    if (i < N_NODES) cursor[i] = s[threadIdx.x] - v;
    if (threadIdx.x == SCAN_B - 1) part[blockIdx.x] = s[threadIdx.x];
}
__global__ void k_scan_b(int* __restrict__ part, int nb) {
    __shared__ int s[256];
    int v = (threadIdx.x < nb) ? part[threadIdx.x] : 0;
    s[threadIdx.x] = v;
    __syncthreads();
    for (int off = 1; off < 256; off <<= 1) {
        int t = (threadIdx.x >= off) ? s[threadIdx.x - off] : 0;
        __syncthreads();
        s[threadIdx.x] += t;
        __syncthreads();
    }
    if (threadIdx.x < nb) part[threadIdx.x] = s[threadIdx.x] - v;
}

// ---------------- pass 1: pure permutation scatter ----------------
__global__ void k_perm(const int* __restrict__ ei,
                       int* __restrict__ cursor, const int* __restrict__ part,
                       int4* __restrict__ esd) {
    int e = blockIdx.x * blockDim.x + threadIdx.x;
    if (e >= N_EDGES) return;
    int src = ei[e];
    int dst = ei[N_EDGES + e];
    int pos = atomicAdd(&cursor[dst], 1) + part[dst >> 9];  // SCAN_B = 512
    esd[pos] = make_int4(src, dst, e, 0);
}

// ---------------- pass 2: gather-convert + conv1 (single ea pass) ----------------
__global__ void k_gather_conv1(const int4* __restrict__ esd, const float* __restrict__ ea,
                               const float* __restrict__ x,
                               const float* __restrict__ Wf, const float* __restrict__ bf,
                               const float* __restrict__ Ws, const float* __restrict__ bs,
                               int* __restrict__ srcs, int* __restrict__ dsts,
                               __half* __restrict__ eas, float* __restrict__ agg) {
    __shared__ float sWf[38 * 3], sWs[38 * 3], sbf[3], sbs[3];
    int t = threadIdx.x;
    if (t < 114) { sWf[t] = Wf[t]; sWs[t] = Ws[t]; }
    if (t < 3)   { sbf[t] = bf[t]; sbs[t] = bs[t]; }
    __syncthreads();
    int p = blockIdx.x * blockDim.x + t;
    if (p >= N_EDGES) return;
    int4 rec = esd[p];
    int src = rec.x;
    int dst = rec.y;
    srcs[p] = src;
    dsts[p] = dst;

    float lf0 = sbf[0], lf1 = sbf[1], lf2 = sbf[2];
    float ls0 = sbs[0], ls1 = sbs[1], ls2 = sbs[2];
    {
        float zz[6] = { x[dst * 3 + 0], x[dst * 3 + 1], x[dst * 3 + 2],
                        x[src * 3 + 0], x[src * 3 + 1], x[src * 3 + 2] };
#pragma unroll
        for (int r = 0; r < 6; r++) {
            float zv = zz[r];
            lf0 = fmaf(zv, sWf[r * 3 + 0], lf0);
            lf1 = fmaf(zv, sWf[r * 3 + 1], lf1);
            lf2 = fmaf(zv, sWf[r * 3 + 2], lf2);
            ls0 = fmaf(zv, sWs[r * 3 + 0], ls0);
            ls1 = fmaf(zv, sWs[r * 3 + 1], ls1);
            ls2 = fmaf(zv, sWs[r * 3 + 2], ls2);
        }
    }
    const float4* s = (const float4*)&ea[(size_t)rec.z * 32];
    __half* d = &eas[(size_t)p * 32];
#pragma unroll
    for (int j = 0; j < 4; j++) {
        float4 a = s[j * 2];
        float4 b = s[j * 2 + 1];
        float q[8] = { a.x, a.y, a.z, a.w, b.x, b.y, b.z, b.w };
#pragma unroll
        for (int k = 0; k < 8; k++) {
            int r = 6 + j * 8 + k;
            float zv = q[k];
            lf0 = fmaf(zv, sWf[r * 3 + 0], lf0);
            lf1 = fmaf(zv, sWf[r * 3 + 1], lf1);
            lf2 = fmaf(zv, sWf[r * 3 + 2], lf2);
            ls0 = fmaf(zv, sWs[r * 3 + 0], ls0);
            ls1 = fmaf(zv, sWs[r * 3 + 1], ls1);
            ls2 = fmaf(zv, sWs[r * 3 + 2], ls2);
        }
        half2 h0 = __floats2half2_rn(a.x, a.y);
        half2 h1 = __floats2half2_rn(a.z, a.w);
        half2 h2 = __floats2half2_rn(b.x, b.y);
        half2 h3 = __floats2half2_rn(b.z, b.w);
        uint4 pk;
        pk.x = *(unsigned*)&h0; pk.y = *(unsigned*)&h1;
        pk.z = *(unsigned*)&h2; pk.w = *(unsigned*)&h3;
        *(uint4*)&d[j * 8] = pk;
    }
    atomicAdd(&agg[dst * 3 + 0], sigmoidf_(lf0) * softplusf_(ls0));
    atomicAdd(&agg[dst * 3 + 1], sigmoidf_(lf1) * softplusf_(ls1));
    atomicAdd(&agg[dst * 3 + 2], sigmoidf_(lf2) * softplusf_(ls2));
}

// ---------------- node projection after conv1 (grid-stride) ----------------
__global__ void k_node1(const float* __restrict__ x, const float* __restrict__ agg,
                        const float* __restrict__ Wp, const float* __restrict__ bp,
                        float* __restrict__ h, __half* __restrict__ hh) {
    int i = blockIdx.x * blockDim.x + threadIdx.x;
    int stride = gridDim.x * blockDim.x;
    for (; i < N_NODES * HID; i += stride) {
        int n = i >> 7;
        int c = i & 127;
        float s0 = x[n * 3 + 0] + agg[n * 3 + 0];
        float s1 = x[n * 3 + 1] + agg[n * 3 + 1];
        float s2 = x[n * 3 + 2] + agg[n * 3 + 2];
        float v = bp[c] + s0 * Wp[c] + s1 * Wp[128 + c] + s2 * Wp[256 + c];
        v = fmaxf(v, 0.0f);
        h[i] = v;
        hh[i] = __float2half_rn(v);
    }
}

// ---------------- fused 4-part node projection (prepped fp16 W) ----------------
#define PJ_S 136
__global__ __launch_bounds__(256, 3) void k_proj_all(
        const __half* __restrict__ hh,
        const __half* __restrict__ wT,
        const float* __restrict__ bf, const float* __restrict__ bs,
        __half* __restrict__ PA, __half* __restrict__ PB) {
    extern __shared__ __half psm[];
    __half* hs  = psm;                 // [128 rows][136]
    __half* wsT = psm + 128 * PJ_S;    // [128 cols][136 k]

    int t = threadIdx.x;
    int lane = t & 31;
    int w = t >> 5;
    int g = lane >> 2;
    int tig = lane & 3;
    int n0 = blockIdx.x * 128;

#pragma unroll
    for (int j = 0; j < 8; j++) {
        int idx = t + j * 256;
        int row = idx >> 4;
        int c = (idx & 15) * 8;
        uint4 v = make_uint4(0, 0, 0, 0);
        int n = n0 + row;
        if (n < N_NODES) v = *(const uint4*)&hh[(size_t)n * 128 + c];
        *(uint4*)&hs[row * PJ_S + c] = v;
    }

    int r0 = w * 16;
#pragma unroll 1
    for (int part = 0; part < 4; part++) {
        const float* bias; __half* out; int coloff;
        if (part == 0)      { bias = bf;      out = PA; coloff = 0;   }
        else if (part == 1) { bias = bs;      out = PA; coloff = 128; }
        else if (part == 2) { bias = nullptr; out = PB; coloff = 0;   }
        else                { bias = nullptr; out = PB; coloff = 128; }
        const uint4* wsrc = (const uint4*)&wT[part * 128 * 128];

        __syncthreads();
#pragma unroll
        for (int j = 0; j < 8; j++) {
            int idx4 = t + j * 256;
            int col = idx4 >> 4;
            int k8 = idx4 & 15;
            *(uint4*)&wsT[col * PJ_S + k8 * 8] = wsrc[idx4];
        }
        __syncthreads();

#pragma unroll
        for (int h2i = 0; h2i < 2; h2i++) {
            float acc[8][4];
#pragma unroll
            for (int i = 0; i < 8; i++)
#pragma unroll
                for (int j = 0; j < 4; j++) acc[i][j] = 0.0f;
#pragma unroll
            for (int kb8 = 0; kb8 < 8; kb8++) {
                int kb = kb8 * 16;
                unsigned a0 = *(const unsigned*)&hs[(r0 + g) * PJ_S + kb + 2 * tig];
                unsigned a1 = *(const unsigned*)&hs[(r0 + g + 8) * PJ_S + kb + 2 * tig];
                unsigned a2 = *(const unsigned*)&hs[(r0 + g) * PJ_S + kb + 2 * tig + 8];
                unsigned a3 = *(const unsigned*)&hs[(r0 + g + 8) * PJ_S + kb + 2 * tig + 8];
#pragma unroll
                for (int nt = 0; nt < 8; nt++) {
                    int col = h2i * 64 + nt * 8 + g;
                    unsigned b0 = *(const unsigned*)&wsT[col * PJ_S + kb + 2 * tig];
                    unsigned b1 = *(const unsigned*)&wsT[col * PJ_S + kb + 2 * tig + 8];
                    mma_f16(acc[nt], a0, a1, a2, a3, b0, b1);
                }
            }
#pragma unroll
            for (int nt = 0; nt < 8; nt++) {
                int c = h2i * 64 + nt * 8 + 2 * tig;
                float b0 = 0.f, b1 = 0.f;
                if (bias) { b0 = bias[c]; b1 = bias[c + 1]; }
                int n = n0 + r0 + g;
                if (n < N_NODES)
                    *(half2*)&out[(size_t)n * 256 + coloff + c] =
                        __floats2half2_rn(acc[nt][0] + b0, acc[nt][1] + b1);
                n = n0 + r0 + g + 8;
                if (n < N_NODES)
                    *(half2*)&out[(size_t)n * 256 + coloff + c] =
                        __floats2half2_rn(acc[nt][2] + b0, acc[nt][3] + b1);
            }
        }
    }
}

// ---------------- fused edge kernel (double-buffered seas, 2 barriers/tile) ----------------
#define WT_S 40
#define EA_S 40
#define EH_S 264
__global__ __launch_bounds__(256, 3) void k_edge_fused(
        const int* __restrict__ srcs, const int* __restrict__ dsts,
        const __half* __restrict__ eas,
        const __half* __restrict__ PA, const __half* __restrict__ PB,
        const __half* __restrict__ wTe,
        float* __restrict__ agg) {
    extern __shared__ __half sm[];
    __half* wsT  = sm;                               // 256*40
    __half* seas = sm + 256 * WT_S;                  // 2 buffers of 64*40
    __half* Eh   = sm + 256 * WT_S + 2 * 64 * EA_S;  // 64*264

    int t = threadIdx.x;
    int lane = t & 31;
    int w = t >> 5;
    int g = lane >> 2;
    int tig = lane & 3;

    {
        const uint4* wsrc = (const uint4*)wTe;
#pragma unroll
        for (int j = 0; j < 4; j++) {
            int idx4 = t + j * 256;
            int col = idx4 >> 2;
            int k8 = idx4 & 3;
            *(uint4*)&wsT[col * WT_S + k8 * 8] = wsrc[idx4];
        }
    }

    int erow0 = (w & 3) * 16;
    int col0 = (w >> 2) * 128;
    int srow = t >> 2;
    int scol = (t & 3) * 8;
    const half2 nl2e = __floats2half2_rn(-1.44269504f, -1.44269504f);
    const half2 two2 = __floats2half2_rn(2.f, 2.f);
    const half2 m1h  = __floats2half2_rn(-1.f, -1.f);
    const half2 zr2  = __floats2half2_rn(0.f, 0.f);
    const half2 h05  = __floats2half2_rn(0.5f, 0.5f);
    const half2 c0h = __floats2half2_rn(0.405542f, 0.405542f);
    const half2 c1h = __floats2half2_rn(0.333342f, 0.333342f);
    const half2 c2h = __floats2half2_rn(-0.0554078f, -0.0554078f);
    const half2 c3h = __floats2half2_rn(0.0122789f, 0.0122789f);
    const half2 c4h = __floats2half2_rn(-0.00346625f, -0.00346625f);
    const half2 c5h = __floats2half2_rn(0.000951552f, 0.000951552f);

    // preload first tile into buffer 0
    int buf = 0;
    {
        long t0 = blockIdx.x;
        if (t0 < NTILES) {
            uint4 r = *(const uint4*)&eas[t0 * ETILE * 32 + t * 8];
            *(uint4*)&seas[srow * EA_S + scol] = r;
        }
    }
    __syncthreads();

    for (long tile = blockIdx.x; tile < NTILES; tile += gridDim.x) {
        long e0 = tile * ETILE;
        const __half* sb = &seas[buf * 64 * EA_S];

        // phase 1: E = ea @ [Wef|Wes]  (reads seas[buf], writes Eh)
#pragma unroll
        for (int h2i = 0; h2i < 2; h2i++) {
            float acc[8][4];
#pragma unroll
            for (int i = 0; i < 8; i++)
#pragma unroll
                for (int j = 0; j < 4; j++) acc[i][j] = 0.0f;
#pragma unroll
            for (int ks = 0; ks < 2; ks++) {
                int kb = ks * 16;
                unsigned a0 = *(const unsigned*)&sb[(erow0 + g) * EA_S + kb + 2 * tig];
                unsigned a1 = *(const unsigned*)&sb[(erow0 + g + 8) * EA_S + kb + 2 * tig];
                unsigned a2 = *(const unsigned*)&sb[(erow0 + g) * EA_S + kb + 2 * tig + 8];
                unsigned a3 = *(const unsigned*)&sb[(erow0 + g + 8) * EA_S + kb + 2 * tig + 8];
#pragma unroll
                for (int nt = 0; nt < 8; nt++) {
                    int col = col0 + h2i * 64 + nt * 8 + g;
                    unsigned b0 = *(const unsigned*)&wsT[col * WT_S + kb + 2 * tig];
                    unsigned b1 = *(const unsigned*)&wsT[col * WT_S + kb + 2 * tig + 8];
                    mma_f16(acc[nt], a0, a1, a2, a3, b0, b1);
                }
            }
#pragma unroll
            for (int nt = 0; nt < 8; nt++) {
                int c = col0 + h2i * 64 + nt * 8 + 2 * tig;
                *(half2*)&Eh[(erow0 + g) * EH_S + c]     = __floats2half2_rn(acc[nt][0], acc[nt][1]);
                *(half2*)&Eh[(erow0 + g + 8) * EH_S + c] = __floats2half2_rn(acc[nt][2], acc[nt][3]);
            }
        }

        // prefetch next tile's ea into registers (overlaps with barrier + phase 2)
        long ntile = tile + gridDim.x;
        bool has_next = (ntile < NTILES);
        uint4 rn;
        if (has_next) rn = *(const uint4*)&eas[ntile * ETILE * 32 + t * 8];

        __syncthreads();   // Eh ready; seas[buf] free after this tile's phase 1

        // phase 2: prefetch-8 gather, fp16 gating, grouped flush
        {
            int srcs8[8], dsts8[8];
#pragma unroll
            for (int j = 0; j < 8; j++) {
                long e = e0 + w * 8 + j;
                srcs8[j] = srcs[e];
                dsts8[j] = dsts[e];
            }
            uint2 pbf[8], pbs[8];
#pragma unroll
            for (int j = 0; j < 8; j++) {
                size_t base = (size_t)srcs8[j] * 256 + lane * 4;
                pbf[j] = *(const uint2*)&PB[base];
                pbs[j] = *(const uint2*)&PB[base + 128];
            }
            int prev = -1;
            float4 acc = make_float4(0.f, 0.f, 0.f, 0.f);
            half2 af01, af23, as01, as23;
            af01 = af23 = as01 = as23 = __floats2half2_rn(0.f, 0.f);
#pragma unroll
            for (int j = 0; j < 8; j++) {
                int le = w * 8 + j;
                int dst = dsts8[j];
                if (dst != prev) {
                    if (prev >= 0)
                        red4(&agg[(size_t)prev * HID + lane * 4], acc);
                    acc = make_float4(0.f, 0.f, 0.f, 0.f);
                    size_t base = (size_t)dst * 256 + lane * 4;
                    uint2 pafu = *(const uint2*)&PA[base];
                    uint2 pasu = *(const uint2*)&PA[base + 128];
                    af01 = *(half2*)&pafu.x; af23 = *(half2*)&pafu.y;
                    as01 = *(half2*)&pasu.x; as23 = *(half2*)&pasu.y;
                    prev = dst;
                }
                uint2 efu = *(const uint2*)&Eh[le * EH_S + lane * 4];
                uint2 esu = *(const uint2*)&Eh[le * EH_S + 128 + lane * 4];

                half2 lf01 = __hadd2(__hadd2(*(half2*)&efu.x, af01), *(half2*)&pbf[j].x);
                half2 lf23 = __hadd2(__hadd2(*(half2*)&efu.y, af23), *(half2*)&pbf[j].y);
                half2 ls01 = __hadd2(__hadd2(*(half2*)&esu.x, as01), *(half2*)&pbs[j].x);
                half2 ls23 = __hadd2(__hadd2(*(half2*)&esu.y, as23), *(half2*)&pbs[j].y);

                half2 t01 = ex2h2_(__hmul2(__habs2(ls01), nl2e));
                half2 t23 = ex2h2_(__hmul2(__habs2(ls23), nl2e));
                half2 u01 = __hfma2(t01, two2, m1h);
                half2 u23 = __hfma2(t23, two2, m1h);
                half2 p01 = __hfma2(c5h, u01, c4h);
                half2 p23 = __hfma2(c5h, u23, c4h);
                p01 = __hfma2(p01, u01, c3h);  p23 = __hfma2(p23, u23, c3h);
                p01 = __hfma2(p01, u01, c2h);  p23 = __hfma2(p23, u23, c2h);
                p01 = __hfma2(p01, u01, c1h);  p23 = __hfma2(p23, u23, c1h);
                p01 = __hfma2(p01, u01, c0h);  p23 = __hfma2(p23, u23, c0h);
                half2 sp01 = __hadd2(__hmax2(ls01, zr2), p01);
                half2 sp23 = __hadd2(__hmax2(ls23, zr2), p23);

                half2 sg01 = __hfma2(tanhh2_(__hmul2(lf01, h05)), h05, h05);
                half2 sg23 = __hfma2(tanhh2_(__hmul2(lf23, h05)), h05, h05);

                float2 m0 = __half22float2(__hmul2(sg01, sp01));
                float2 m1 = __half22float2(__hmul2(sg23, sp23));
                acc.x += m0.x;
                acc.y += m0.y;
                acc.z += m1.x;
                acc.w += m1.y;
            }
            if (prev >= 0)
                red4(&agg[(size_t)prev * HID + lane * 4], acc);
        }

        // stage next tile's ea into the alternate buffer (free during phase 2)
        if (has_next)
            *(uint4*)&seas[(buf ^ 1) * 64 * EA_S + srow * EA_S + scol] = rn;

        __syncthreads();   // phase 2 done (Eh free) + seas[buf^1] written
        buf ^= 1;
    }
}

// ---------------- residual + relu (+ fp16 mirror) ----------------
__global__ void k_update(float* __restrict__ h, __half* __restrict__ hh,
                         const float* __restrict__ agg, int n) {
    int i = blockIdx.x * blockDim.x + threadIdx.x;
    int stride = gridDim.x * blockDim.x;
    for (; i < n; i += stride) {
        float v = fmaxf(h[i] + agg[i], 0.0f);
        h[i] = v;
        hh[i] = __float2half_rn(v);
    }
}

// ---------------- fused last update + pooling (batch sorted) ----------------
__global__ void k_update_pool(const float* __restrict__ h, const float* __restrict__ agg,
                              const int* __restrict__ batch,
                              float* __restrict__ pool, float* __restrict__ cnt) {
    const int NPB = 256;
    int n0 = blockIdx.x * NPB;
    if (n0 >= N_NODES) return;
    int c = threadIdx.x;  // 128
    float s = 0.0f;
    int cur = batch[n0];
    int mycnt = 0;
    for (int i = 0; i < NPB; i++) {
        int n = n0 + i;
        if (n >= N_NODES) break;
        int b = batch[n];
        if (b != cur) {
            atomicAdd(&pool[cur * HID + c], s);
            if (c == 0) atomicAdd(&cnt[cur], (float)mycnt);
            s = 0.0f; mycnt = 0; cur = b;
        }
        s += fmaxf(h[(size_t)n * HID + c] + agg[(size_t)n * HID + c], 0.0f);
        mycnt++;
    }
    atomicAdd(&pool[cur * HID + c], s);
    if (c == 0) atomicAdd(&cnt[cur], (float)mycnt);
}

// ---------------- head ----------------
__global__ void k_head(const float* __restrict__ pool, const float* __restrict__ cnt,
                       const float* __restrict__ W1, const float* __restrict__ b1,
                       const float* __restrict__ W2, const float* __restrict__ b2,
                       float* __restrict__ out) {
    int g = blockIdx.x;
    int c = threadIdx.x;
    __shared__ float p[128];
    __shared__ float t1[128];
    float invc = 1.0f / fmaxf(cnt[g], 1.0f);
    p[c] = pool[g * HID + c] * invc;
    __syncthreads();
    float v = b1[c];
#pragma unroll 16
    for (int k = 0; k < 128; k++) v += p[k] * W1[k * 128 + c];
    t1[c] = fmaxf(v, 0.0f);
    __syncthreads();
    if (c < 3) {
        float o = b2[c];
        for (int k = 0; k < 128; k++) o += t1[k] * W2[k * 3 + c];
        out[g * 3 + c] = o;
    }
}

// ---------------- launch ----------------
extern "C" void kernel_launch(void* const* d_in, const int* in_sizes, int n_in,
                              void* d_out, int out_size) {
    const float* x   = (const float*)d_in[0];
    const int*   ei  = (const int*)d_in[1];
    const float* ea  = (const float*)d_in[2];
    const int*   bat = (const int*)d_in[3];
    const float* Wf1 = (const float*)d_in[4];
    const float* bf1 = (const float*)d_in[5];
    const float* Ws1 = (const float*)d_in[6];
    const float* bs1 = (const float*)d_in[7];
    const float* Wp  = (const float*)d_in[8];
    const float* bp  = (const float*)d_in[9];
    const float* Wc[2]  = { (const float*)d_in[10], (const float*)d_in[14] };
    const float* bcf[2] = { (const float*)d_in[11], (const float*)d_in[15] };
    const float* Wsc[2] = { (const float*)d_in[12], (const float*)d_in[16] };
    const float* bcs[2] = { (const float*)d_in[13], (const float*)d_in[17] };
    const float* W1  = (const float*)d_in[18];
    const float* b1  = (const float*)d_in[19];
    const float* W2  = (const float*)d_in[20];
    const float* b2  = (const float*)d_in[21];
    float* out = (float*)d_out;

    float *pH, *pAgg, *pPool;
    __half *pPA, *pPB, *pHH, *pEAS, *pWTP, *pWTE;
    int *pDeg, *pCur, *pPart, *pSrcs, *pDsts;
    int4 *pEsd;
    cudaGetSymbolAddress((void**)&pH,    g_h);
    cudaGetSymbolAddress((void**)&pHH,   g_hh);
    cudaGetSymbolAddress((void**)&pPA,   g_PA);
    cudaGetSymbolAddress((void**)&pPB,   g_PB);
    cudaGetSymbolAddress((void**)&pAgg,  g_agg);
    cudaGetSymbolAddress((void**)&pPool, g_pool);
    cudaGetSymbolAddress((void**)&pDeg,  g_deg);
    cudaGetSymbolAddress((void**)&pCur,  g_cursor);
    cudaGetSymbolAddress((void**)&pPart, g_part);
    cudaGetSymbolAddress((void**)&pEsd,  g_esd);
    cudaGetSymbolAddress((void**)&pSrcs, g_srcs);
    cudaGetSymbolAddress((void**)&pDsts, g_dsts);
    cudaGetSymbolAddress((void**)&pEAS,  g_eas);
    cudaGetSymbolAddress((void**)&pWTP,  g_wTproj);
    cudaGetSymbolAddress((void**)&pWTE,  g_wTedge);

    const int EDGE_SMEM = (256 * WT_S + 2 * 64 * EA_S + 64 * EH_S) * 2;
    const int PROJ_SMEM = 2 * 128 * PJ_S * 2;
    cudaFuncSetAttribute(k_edge_fused, cudaFuncAttributeMaxDynamicSharedMemorySize, EDGE_SMEM);
    cudaFuncSetAttribute(k_proj_all, cudaFuncAttributeMaxDynamicSharedMemorySize, PROJ_SMEM);

    // ---- zeroing via graph memset nodes ----
    cudaMemsetAsync(pDeg, 0, N_NODES * sizeof(int));
    cudaMemsetAsync(pAgg, 0, N_NODES * 3 * sizeof(float));
    cudaMemsetAsync(pPool, 0, (NGRAPH * HID + NGRAPH) * sizeof(float));

    // ---- weight prep (both layers, one launch) ----
    k_wprep2<<<(2 * WPREP_N + 255) / 256, 256>>>(Wc[0], Wsc[0], Wc[1], Wsc[1],
                                                 pWTP, pWTE);

    // ---- build CSR + conv1 (ea read exactly once) ----
    k_hist<<<N_EDGES / 256, 256>>>(ei, pDeg);
    k_scan_a<<<SCAN_NB, SCAN_B>>>(pDeg, pCur, pPart);
    k_scan_b<<<1, 256>>>(pPart, SCAN_NB);
    k_perm<<<N_EDGES / 256, 256>>>(ei, pCur, pPart, pEsd);
    k_gather_conv1<<<N_EDGES / 256, 256>>>(pEsd, ea, x, Wf1, bf1, Ws1, bs1,
                                           pSrcs, pDsts, pEAS, pAgg);
    k_node1<<<592, 256>>>(x, pAgg, Wp, bp, pH, pHH);

    // ---- hidden convs ----
    for (int l = 0; l < 2; l++) {
        k_proj_all<<<(N_NODES + 127) / 128, 256, PROJ_SMEM>>>(
            pHH, pWTP + l * 4 * 128 * 128, bcf[l], bcs[l], pPA, pPB);
        cudaMemsetAsync(pAgg, 0, (size_t)N_NODES * HID * sizeof(float));
        k_edge_fused<<<444, 256, EDGE_SMEM>>>(pSrcs, pDsts, pEAS, pPA, pPB,
                                              pWTE + l * 256 * 32, pAgg);
        if (l == 0)
            k_update<<<2048, 256>>>(pH, pHH, pAgg, N_NODES * HID);
        else
            k_update_pool<<<(N_NODES + 255) / 256, 128>>>(pH, pAgg, bat,
                                                          pPool, pPool + NGRAPH * HID);
    }

    // ---- head ----
    k_head<<<NGRAPH, 128>>>(pPool, pPool + NGRAPH * HID, W1, b1, W2, b2, out);
}

// round 17
// speedup vs baseline: 1.3423x; 1.0069x over previous
#include <cuda_runtime.h>
#include <cuda_fp16.h>
#include <math.h>

#define N_NODES 100000
#define N_EDGES 1600000
#define HID 128
#define NGRAPH 64
#define ETILE 64
#define NTILES (N_EDGES / ETILE)
#define SCAN_B 512
#define SCAN_NB ((N_NODES + SCAN_B - 1) / SCAN_B)   // 196
#define WPREP_N (4 * 128 * 128 + 256 * 32)

// ---------------- device scratch ----------------
__device__ float  g_h[N_NODES * HID];
__device__ __half g_PA[N_NODES * 256];   // [f(128) | s(128)] per node (+bias)
__device__ __half g_PB[N_NODES * 256];
__device__ float  g_agg[N_NODES * HID];
__device__ float  g_pool[NGRAPH * HID + NGRAPH];
__device__ int    g_deg[N_NODES];
__device__ int    g_cursor[N_NODES];
__device__ int    g_part[256];
__device__ int4   g_esd[N_EDGES];
__device__ int    g_srcs[N_EDGES];
__device__ int    g_dsts[N_EDGES];
__device__ __half g_eas[(size_t)N_EDGES * 32];
__device__ __half g_wTproj[2 * 4 * 128 * 128];
__device__ __half g_wTedge[2 * 256 * 32];

// ---------------- helpers ----------------
__device__ __forceinline__ float sigmoidf_(float x) { return 1.0f / (1.0f + __expf(-x)); }
__device__ __forceinline__ float softplusf_(float x) {
    return fmaxf(x, 0.0f) + __logf(1.0f + __expf(-fabsf(x)));
}
__device__ __forceinline__ half2 ex2h2_(half2 x) {
    unsigned y;
    asm("ex2.approx.f16x2 %0, %1;" : "=r"(y) : "r"(*(unsigned*)&x));
    return *(half2*)&y;
}
__device__ __forceinline__ half2 tanhh2_(half2 x) {
    unsigned y;
    asm("tanh.approx.f16x2 %0, %1;" : "=r"(y) : "r"(*(unsigned*)&x));
    return *(half2*)&y;
}
__device__ __forceinline__ void red4(float* p, float4 v) {
    asm volatile("red.global.add.v4.f32 [%0], {%1,%2,%3,%4};"
                 :: "l"(p), "f"(v.x), "f"(v.y), "f"(v.z), "f"(v.w));
}
__device__ __forceinline__ void mma_f16(float d[4],
                                        unsigned a0, unsigned a1, unsigned a2, unsigned a3,
                                        unsigned b0, unsigned b1) {
    asm volatile("mma.sync.aligned.m16n8k16.row.col.f32.f16.f16.f32 "
                 "{%0,%1,%2,%3}, {%4,%5,%6,%7}, {%8,%9}, {%0,%1,%2,%3};\n"
                 : "+f"(d[0]), "+f"(d[1]), "+f"(d[2]), "+f"(d[3])
                 : "r"(a0), "r"(a1), "r"(a2), "r"(a3), "r"(b0), "r"(b1));
}

// ---------------- weight prep: both layers in one launch ----------------
__global__ void k_wprep2(const float* __restrict__ Wf2, const float* __restrict__ Ws2,
                         const float* __restrict__ Wf3, const float* __restrict__ Ws3,
                         __half* __restrict__ wTproj, __half* __restrict__ wTedge) {
    int gidx = blockIdx.x * blockDim.x + threadIdx.x;
    if (gidx >= 2 * WPREP_N) return;
    int layer = gidx / WPREP_N;
    int idx = gidx - layer * WPREP_N;
    const float* Wf = layer ? Wf3 : Wf2;
    const float* Ws = layer ? Ws3 : Ws2;
    if (idx < 4 * 128 * 128) {
        int part = idx >> 14;
        int rem = idx & 16383;
        int c = rem >> 7;
        int k = rem & 127;
        const float* W;
        if (part == 0)      W = Wf;
        else if (part == 1) W = Ws;
        else if (part == 2) W = Wf + 128 * 128;
        else                W = Ws + 128 * 128;
        wTproj[layer * 4 * 128 * 128 + idx] = __float2half_rn(W[k * 128 + c]);
    } else {
        int i2 = idx - 4 * 128 * 128;
        int c = i2 >> 5;
        int k = i2 & 31;
        float v = (c < 128) ? Wf[(256 + k) * 128 + c]
                            : Ws[(256 + k) * 128 + (c - 128)];
        wTedge[layer * 256 * 32 + i2] = __float2half_rn(v);
    }
}

// ---------------- CSR build ----------------
__global__ void k_hist(const int* __restrict__ ei, int* __restrict__ deg) {
    int e = blockIdx.x * blockDim.x + threadIdx.x;
    if (e < N_EDGES) atomicAdd(&deg[ei[N_EDGES + e]], 1);
}
__global__ void k_scan_a(const int* __restrict__ deg, int* __restrict__ cursor,
                         int* __restrict__ part) {
    __shared__ int s[SCAN_B];
    int i = blockIdx.x * SCAN_B + threadIdx.x;
    int v = (i < N_NODES) ? deg[i] : 0;
    s[threadIdx.x] = v;
    __syncthreads();
    for (int off = 1; off < SCAN_B; off <<= 1) {
        int t = (threadIdx.x >= off) ? s[threadIdx.x - off] : 0;
        __syncthreads();
        s[threadIdx.x] += t;
        __syncthreads();
    }
    if (i < N_NODES) cursor[i] = s[threadIdx.x] - v;
    if (threadIdx.x == SCAN_B - 1) part[blockIdx.x] = s[threadIdx.x];
}
__global__ void k_scan_b(int* __restrict__ part, int nb) {
    __shared__ int s[256];
    int v = (threadIdx.x < nb) ? part[threadIdx.x] : 0;
    s[threadIdx.x] = v;
    __syncthreads();
    for (int off = 1; off < 256; off <<= 1) {
        int t = (threadIdx.x >= off) ? s[threadIdx.x - off] : 0;
        __syncthreads();
        s[threadIdx.x] += t;
        __syncthreads();
    }
    if (threadIdx.x < nb) part[threadIdx.x] = s[threadIdx.x] - v;
}

// ---------------- pass 1: pure permutation scatter ----------------
__global__ void k_perm(const int* __restrict__ ei,
                       int* __restrict__ cursor, const int* __restrict__ part,
                       int4* __restrict__ esd) {
    int e = blockIdx.x * blockDim.x + threadIdx.x;
    if (e >= N_EDGES) return;
    int src = ei[e];
    int dst = ei[N_EDGES + e];
    int pos = atomicAdd(&cursor[dst], 1) + part[dst >> 9];  // SCAN_B = 512
    esd[pos] = make_int4(src, dst, e, 0);
}

// ---------------- pass 2: gather-convert + conv1 (single ea pass) ----------------
__global__ void k_gather_conv1(const int4* __restrict__ esd, const float* __restrict__ ea,
                               const float* __restrict__ x,
                               const float* __restrict__ Wf, const float* __restrict__ bf,
                               const float* __restrict__ Ws, const float* __restrict__ bs,
                               int* __restrict__ srcs, int* __restrict__ dsts,
                               __half* __restrict__ eas, float* __restrict__ agg) {
    __shared__ float sWf[38 * 3], sWs[38 * 3], sbf[3], sbs[3];
    int t = threadIdx.x;
    if (t < 114) { sWf[t] = Wf[t]; sWs[t] = Ws[t]; }
    if (t < 3)   { sbf[t] = bf[t]; sbs[t] = bs[t]; }
    __syncthreads();
    int p = blockIdx.x * blockDim.x + t;
    if (p >= N_EDGES) return;
    int4 rec = esd[p];
    int src = rec.x;
    int dst = rec.y;
    srcs[p] = src;
    dsts[p] = dst;

    float lf0 = sbf[0], lf1 = sbf[1], lf2 = sbf[2];
    float ls0 = sbs[0], ls1 = sbs[1], ls2 = sbs[2];
    {
        float zz[6] = { x[dst * 3 + 0], x[dst * 3 + 1], x[dst * 3 + 2],
                        x[src * 3 + 0], x[src * 3 + 1], x[src * 3 + 2] };
#pragma unroll
        for (int r = 0; r < 6; r++) {
            float zv = zz[r];
            lf0 = fmaf(zv, sWf[r * 3 + 0], lf0);
            lf1 = fmaf(zv, sWf[r * 3 + 1], lf1);
            lf2 = fmaf(zv, sWf[r * 3 + 2], lf2);
            ls0 = fmaf(zv, sWs[r * 3 + 0], ls0);
            ls1 = fmaf(zv, sWs[r * 3 + 1], ls1);
            ls2 = fmaf(zv, sWs[r * 3 + 2], ls2);
        }
    }
    const float4* s = (const float4*)&ea[(size_t)rec.z * 32];
    __half* d = &eas[(size_t)p * 32];
#pragma unroll
    for (int j = 0; j < 4; j++) {
        float4 a = s[j * 2];
        float4 b = s[j * 2 + 1];
        float q[8] = { a.x, a.y, a.z, a.w, b.x, b.y, b.z, b.w };
#pragma unroll
        for (int k = 0; k < 8; k++) {
            int r = 6 + j * 8 + k;
            float zv = q[k];
            lf0 = fmaf(zv, sWf[r * 3 + 0], lf0);
            lf1 = fmaf(zv, sWf[r * 3 + 1], lf1);
            lf2 = fmaf(zv, sWf[r * 3 + 2], lf2);
            ls0 = fmaf(zv, sWs[r * 3 + 0], ls0);
            ls1 = fmaf(zv, sWs[r * 3 + 1], ls1);
            ls2 = fmaf(zv, sWs[r * 3 + 2], ls2);
        }
        half2 h0 = __floats2half2_rn(a.x, a.y);
        half2 h1 = __floats2half2_rn(a.z, a.w);
        half2 h2 = __floats2half2_rn(b.x, b.y);
        half2 h3 = __floats2half2_rn(b.z, b.w);
        uint4 pk;
        pk.x = *(unsigned*)&h0; pk.y = *(unsigned*)&h1;
        pk.z = *(unsigned*)&h2; pk.w = *(unsigned*)&h3;
        *(uint4*)&d[j * 8] = pk;
    }
    atomicAdd(&agg[dst * 3 + 0], sigmoidf_(lf0) * softplusf_(ls0));
    atomicAdd(&agg[dst * 3 + 1], sigmoidf_(lf1) * softplusf_(ls1));
    atomicAdd(&agg[dst * 3 + 2], sigmoidf_(lf2) * softplusf_(ls2));
}

// ---------------- node projection after conv1 (grid-stride, fp32 h only) ----------------
__global__ void k_node1(const float* __restrict__ x, const float* __restrict__ agg,
                        const float* __restrict__ Wp, const float* __restrict__ bp,
                        float* __restrict__ h) {
    int i = blockIdx.x * blockDim.x + threadIdx.x;
    int stride = gridDim.x * blockDim.x;
    for (; i < N_NODES * HID; i += stride) {
        int n = i >> 7;
        int c = i & 127;
        float s0 = x[n * 3 + 0] + agg[n * 3 + 0];
        float s1 = x[n * 3 + 1] + agg[n * 3 + 1];
        float s2 = x[n * 3 + 2] + agg[n * 3 + 2];
        float v = bp[c] + s0 * Wp[c] + s1 * Wp[128 + c] + s2 * Wp[256 + c];
        h[i] = fmaxf(v, 0.0f);
    }
}

// ---------------- fused 4-part node projection + residual update ----------------
// mode 0: stage from h (already relu'd)
// mode 1: stage v = relu(h + agg), write h = v back (the layer-0 residual update)
#define PJ_S 136
__global__ __launch_bounds__(256, 3) void k_proj_all(
        float* __restrict__ h, const float* __restrict__ agg, int mode,
        const __half* __restrict__ wT,
        const float* __restrict__ bf, const float* __restrict__ bs,
        __half* __restrict__ PA, __half* __restrict__ PB) {
    extern __shared__ __half psm[];
    __half* hs  = psm;                 // [128 rows][136]
    __half* wsT = psm + 128 * PJ_S;    // [128 cols][136 k]

    int t = threadIdx.x;
    int lane = t & 31;
    int w = t >> 5;
    int g = lane >> 2;
    int tig = lane & 3;
    int n0 = blockIdx.x * 128;

    // stage h tile (fp32 -> fp16), optionally fused with residual update
#pragma unroll
    for (int j = 0; j < 8; j++) {
        int idx = t + j * 256;
        int row = idx >> 4;
        int c = (idx & 15) * 8;
        int n = n0 + row;
        half2 o0, o1, o2, o3;
        if (n < N_NODES) {
            size_t base = (size_t)n * 128 + c;
            float4 a = *(const float4*)&h[base];
            float4 b = *(const float4*)&h[base + 4];
            if (mode) {
                float4 ga = *(const float4*)&agg[base];
                float4 gb = *(const float4*)&agg[base + 4];
                a.x = fmaxf(a.x + ga.x, 0.f); a.y = fmaxf(a.y + ga.y, 0.f);
                a.z = fmaxf(a.z + ga.z, 0.f); a.w = fmaxf(a.w + ga.w, 0.f);
                b.x = fmaxf(b.x + gb.x, 0.f); b.y = fmaxf(b.y + gb.y, 0.f);
                b.z = fmaxf(b.z + gb.z, 0.f); b.w = fmaxf(b.w + gb.w, 0.f);
                *(float4*)&h[base] = a;
                *(float4*)&h[base + 4] = b;
            }
            o0 = __floats2half2_rn(a.x, a.y);
            o1 = __floats2half2_rn(a.z, a.w);
            o2 = __floats2half2_rn(b.x, b.y);
            o3 = __floats2half2_rn(b.z, b.w);
        } else {
            o0 = o1 = o2 = o3 = __floats2half2_rn(0.f, 0.f);
        }
        __half* dp = &hs[row * PJ_S + c];
        *(half2*)&dp[0] = o0;
        *(half2*)&dp[2] = o1;
        *(half2*)&dp[4] = o2;
        *(half2*)&dp[6] = o3;
    }

    int r0 = w * 16;
#pragma unroll 1
    for (int part = 0; part < 4; part++) {
        const float* bias; __half* out; int coloff;
        if (part == 0)      { bias = bf;      out = PA; coloff = 0;   }
        else if (part == 1) { bias = bs;      out = PA; coloff = 128; }
        else if (part == 2) { bias = nullptr; out = PB; coloff = 0;   }
        else                { bias = nullptr; out = PB; coloff = 128; }
        const uint4* wsrc = (const uint4*)&wT[part * 128 * 128];

        __syncthreads();
#pragma unroll
        for (int j = 0; j < 8; j++) {
            int idx4 = t + j * 256;
            int col = idx4 >> 4;
            int k8 = idx4 & 15;
            *(uint4*)&wsT[col * PJ_S + k8 * 8] = wsrc[idx4];
        }
        __syncthreads();

#pragma unroll
        for (int h2i = 0; h2i < 2; h2i++) {
            float acc[8][4];
#pragma unroll
            for (int i = 0; i < 8; i++)
#pragma unroll
                for (int j = 0; j < 4; j++) acc[i][j] = 0.0f;
#pragma unroll
            for (int kb8 = 0; kb8 < 8; kb8++) {
                int kb = kb8 * 16;
                unsigned a0 = *(const unsigned*)&hs[(r0 + g) * PJ_S + kb + 2 * tig];
                unsigned a1 = *(const unsigned*)&hs[(r0 + g + 8) * PJ_S + kb + 2 * tig];
                unsigned a2 = *(const unsigned*)&hs[(r0 + g) * PJ_S + kb + 2 * tig + 8];
                unsigned a3 = *(const unsigned*)&hs[(r0 + g + 8) * PJ_S + kb + 2 * tig + 8];
#pragma unroll
                for (int nt = 0; nt < 8; nt++) {
                    int col = h2i * 64 + nt * 8 + g;
                    unsigned b0 = *(const unsigned*)&wsT[col * PJ_S + kb + 2 * tig];
                    unsigned b1 = *(const unsigned*)&wsT[col * PJ_S + kb + 2 * tig + 8];
                    mma_f16(acc[nt], a0, a1, a2, a3, b0, b1);
                }
            }
#pragma unroll
            for (int nt = 0; nt < 8; nt++) {
                int c = h2i * 64 + nt * 8 + 2 * tig;
                float b0 = 0.f, b1 = 0.f;
                if (bias) { b0 = bias[c]; b1 = bias[c + 1]; }
                int n = n0 + r0 + g;
                if (n < N_NODES)
                    *(half2*)&out[(size_t)n * 256 + coloff + c] =
                        __floats2half2_rn(acc[nt][0] + b0, acc[nt][1] + b1);
                n = n0 + r0 + g + 8;
                if (n < N_NODES)
                    *(half2*)&out[(size_t)n * 256 + coloff + c] =
                        __floats2half2_rn(acc[nt][2] + b0, acc[nt][3] + b1);
            }
        }
    }
}

// ---------------- fused edge kernel (double-buffered seas, 2 barriers/tile) ----------------
#define WT_S 40
#define EA_S 40
#define EH_S 264
__global__ __launch_bounds__(256, 3) void k_edge_fused(
        const int* __restrict__ srcs, const int* __restrict__ dsts,
        const __half* __restrict__ eas,
        const __half* __restrict__ PA, const __half* __restrict__ PB,
        const __half* __restrict__ wTe,
        float* __restrict__ agg) {
    extern __shared__ __half sm[];
    __half* wsT  = sm;                               // 256*40
    __half* seas = sm + 256 * WT_S;                  // 2 buffers of 64*40
    __half* Eh   = sm + 256 * WT_S + 2 * 64 * EA_S;  // 64*264

    int t = threadIdx.x;
    int lane = t & 31;
    int w = t >> 5;
    int g = lane >> 2;
    int tig = lane & 3;

    {
        const uint4* wsrc = (const uint4*)wTe;
#pragma unroll
        for (int j = 0; j < 4; j++) {
            int idx4 = t + j * 256;
            int col = idx4 >> 2;
            int k8 = idx4 & 3;
            *(uint4*)&wsT[col * WT_S + k8 * 8] = wsrc[idx4];
        }
    }

    int erow0 = (w & 3) * 16;
    int col0 = (w >> 2) * 128;
    int srow = t >> 2;
    int scol = (t & 3) * 8;
    const half2 nl2e = __floats2half2_rn(-1.44269504f, -1.44269504f);
    const half2 two2 = __floats2half2_rn(2.f, 2.f);
    const half2 m1h  = __floats2half2_rn(-1.f, -1.f);
    const half2 zr2  = __floats2half2_rn(0.f, 0.f);
    const half2 h05  = __floats2half2_rn(0.5f, 0.5f);
    const half2 c0h = __floats2half2_rn(0.405542f, 0.405542f);
    const half2 c1h = __floats2half2_rn(0.333342f, 0.333342f);
    const half2 c2h = __floats2half2_rn(-0.0554078f, -0.0554078f);
    const half2 c3h = __floats2half2_rn(0.0122789f, 0.0122789f);
    const half2 c4h = __floats2half2_rn(-0.00346625f, -0.00346625f);
    const half2 c5h = __floats2half2_rn(0.000951552f, 0.000951552f);

    int buf = 0;
    {
        long t0 = blockIdx.x;
        if (t0 < NTILES) {
            uint4 r = *(const uint4*)&eas[t0 * ETILE * 32 + t * 8];
            *(uint4*)&seas[srow * EA_S + scol] = r;
        }
    }
    __syncthreads();

    for (long tile = blockIdx.x; tile < NTILES; tile += gridDim.x) {
        long e0 = tile * ETILE;
        const __half* sb = &seas[buf * 64 * EA_S];

        // phase 1: E = ea @ [Wef|Wes]
#pragma unroll
        for (int h2i = 0; h2i < 2; h2i++) {
            float acc[8][4];
#pragma unroll
            for (int i = 0; i < 8; i++)
#pragma unroll
                for (int j = 0; j < 4; j++) acc[i][j] = 0.0f;
#pragma unroll
            for (int ks = 0; ks < 2; ks++) {
                int kb = ks * 16;
                unsigned a0 = *(const unsigned*)&sb[(erow0 + g) * EA_S + kb + 2 * tig];
                unsigned a1 = *(const unsigned*)&sb[(erow0 + g + 8) * EA_S + kb + 2 * tig];
                unsigned a2 = *(const unsigned*)&sb[(erow0 + g) * EA_S + kb + 2 * tig + 8];
                unsigned a3 = *(const unsigned*)&sb[(erow0 + g + 8) * EA_S + kb + 2 * tig + 8];
#pragma unroll
                for (int nt = 0; nt < 8; nt++) {
                    int col = col0 + h2i * 64 + nt * 8 + g;
                    unsigned b0 = *(const unsigned*)&wsT[col * WT_S + kb + 2 * tig];
                    unsigned b1 = *(const unsigned*)&wsT[col * WT_S + kb + 2 * tig + 8];
                    mma_f16(acc[nt], a0, a1, a2, a3, b0, b1);
                }
            }
#pragma unroll
            for (int nt = 0; nt < 8; nt++) {
                int c = col0 + h2i * 64 + nt * 8 + 2 * tig;
                *(half2*)&Eh[(erow0 + g) * EH_S + c]     = __floats2half2_rn(acc[nt][0], acc[nt][1]);
                *(half2*)&Eh[(erow0 + g + 8) * EH_S + c] = __floats2half2_rn(acc[nt][2], acc[nt][3]);
            }
        }

        long ntile = tile + gridDim.x;
        bool has_next = (ntile < NTILES);
        uint4 rn;
        if (has_next) rn = *(const uint4*)&eas[ntile * ETILE * 32 + t * 8];

        __syncthreads();

        // phase 2: prefetch-8 gather, fp16 gating, grouped flush
        {
            int srcs8[8], dsts8[8];
#pragma unroll
            for (int j = 0; j < 8; j++) {
                long e = e0 + w * 8 + j;
                srcs8[j] = srcs[e];
                dsts8[j] = dsts[e];
            }
            uint2 pbf[8], pbs[8];
#pragma unroll
            for (int j = 0; j < 8; j++) {
                size_t base = (size_t)srcs8[j] * 256 + lane * 4;
                pbf[j] = *(const uint2*)&PB[base];
                pbs[j] = *(const uint2*)&PB[base + 128];
            }
            int prev = -1;
            float4 acc = make_float4(0.f, 0.f, 0.f, 0.f);
            half2 af01, af23, as01, as23;
            af01 = af23 = as01 = as23 = __floats2half2_rn(0.f, 0.f);
#pragma unroll
            for (int j = 0; j < 8; j++) {
                int le = w * 8 + j;
                int dst = dsts8[j];
                if (dst != prev) {
                    if (prev >= 0)
                        red4(&agg[(size_t)prev * HID + lane * 4], acc);
                    acc = make_float4(0.f, 0.f, 0.f, 0.f);
                    size_t base = (size_t)dst * 256 + lane * 4;
                    uint2 pafu = *(const uint2*)&PA[base];
                    uint2 pasu = *(const uint2*)&PA[base + 128];
                    af01 = *(half2*)&pafu.x; af23 = *(half2*)&pafu.y;
                    as01 = *(half2*)&pasu.x; as23 = *(half2*)&pasu.y;
                    prev = dst;
                }
                uint2 efu = *(const uint2*)&Eh[le * EH_S + lane * 4];
                uint2 esu = *(const uint2*)&Eh[le * EH_S + 128 + lane * 4];

                half2 lf01 = __hadd2(__hadd2(*(half2*)&efu.x, af01), *(half2*)&pbf[j].x);
                half2 lf23 = __hadd2(__hadd2(*(half2*)&efu.y, af23), *(half2*)&pbf[j].y);
                half2 ls01 = __hadd2(__hadd2(*(half2*)&esu.x, as01), *(half2*)&pbs[j].x);
                half2 ls23 = __hadd2(__hadd2(*(half2*)&esu.y, as23), *(half2*)&pbs[j].y);

                half2 t01 = ex2h2_(__hmul2(__habs2(ls01), nl2e));
                half2 t23 = ex2h2_(__hmul2(__habs2(ls23), nl2e));
                half2 u01 = __hfma2(t01, two2, m1h);
                half2 u23 = __hfma2(t23, two2, m1h);
                half2 p01 = __hfma2(c5h, u01, c4h);
                half2 p23 = __hfma2(c5h, u23, c4h);
                p01 = __hfma2(p01, u01, c3h);  p23 = __hfma2(p23, u23, c3h);
                p01 = __hfma2(p01, u01, c2h);  p23 = __hfma2(p23, u23, c2h);
                p01 = __hfma2(p01, u01, c1h);  p23 = __hfma2(p23, u23, c1h);
                p01 = __hfma2(p01, u01, c0h);  p23 = __hfma2(p23, u23, c0h);
                half2 sp01 = __hadd2(__hmax2(ls01, zr2), p01);
                half2 sp23 = __hadd2(__hmax2(ls23, zr2), p23);

                half2 sg01 = __hfma2(tanhh2_(__hmul2(lf01, h05)), h05, h05);
                half2 sg23 = __hfma2(tanhh2_(__hmul2(lf23, h05)), h05, h05);

                float2 m0 = __half22float2(__hmul2(sg01, sp01));
                float2 m1 = __half22float2(__hmul2(sg23, sp23));
                acc.x += m0.x;
                acc.y += m0.y;
                acc.z += m1.x;
                acc.w += m1.y;
            }
            if (prev >= 0)
                red4(&agg[(size_t)prev * HID + lane * 4], acc);
        }

        if (has_next)
            *(uint4*)&seas[(buf ^ 1) * 64 * EA_S + srow * EA_S + scol] = rn;

        __syncthreads();
        buf ^= 1;
    }
}

// ---------------- fused last update + pooling (batch sorted) ----------------
__global__ void k_update_pool(const float* __restrict__ h, const float* __restrict__ agg,
                              const int* __restrict__ batch,
                              float* __restrict__ pool, float* __restrict__ cnt) {
    const int NPB = 256;
    int n0 = blockIdx.x * NPB;
    if (n0 >= N_NODES) return;
    int c = threadIdx.x;  // 128
    float s = 0.0f;
    int cur = batch[n0];
    int mycnt = 0;
    for (int i = 0; i < NPB; i++) {
        int n = n0 + i;
        if (n >= N_NODES) break;
        int b = batch[n];
        if (b != cur) {
            atomicAdd(&pool[cur * HID + c], s);
            if (c == 0) atomicAdd(&cnt[cur], (float)mycnt);
            s = 0.0f; mycnt = 0; cur = b;
        }
        s += fmaxf(h[(size_t)n * HID + c] + agg[(size_t)n * HID + c], 0.0f);
        mycnt++;
    }
    atomicAdd(&pool[cur * HID + c], s);
    if (c == 0) atomicAdd(&cnt[cur], (float)mycnt);
}

// ---------------- head ----------------
__global__ void k_head(const float* __restrict__ pool, const float* __restrict__ cnt,
                       const float* __restrict__ W1, const float* __restrict__ b1,
                       const float* __restrict__ W2, const float* __restrict__ b2,
                       float* __restrict__ out) {
    int g = blockIdx.x;
    int c = threadIdx.x;
    __shared__ float p[128];
    __shared__ float t1[128];
    float invc = 1.0f / fmaxf(cnt[g], 1.0f);
    p[c] = pool[g * HID + c] * invc;
    __syncthreads();
    float v = b1[c];
#pragma unroll 16
    for (int k = 0; k < 128; k++) v += p[k] * W1[k * 128 + c];
    t1[c] = fmaxf(v, 0.0f);
    __syncthreads();
    if (c < 3) {
        float o = b2[c];
        for (int k = 0; k < 128; k++) o += t1[k] * W2[k * 3 + c];
        out[g * 3 + c] = o;
    }
}

// ---------------- launch ----------------
extern "C" void kernel_launch(void* const* d_in, const int* in_sizes, int n_in,
                              void* d_out, int out_size) {
    const float* x   = (const float*)d_in[0];
    const int*   ei  = (const int*)d_in[1];
    const float* ea  = (const float*)d_in[2];
    const int*   bat = (const int*)d_in[3];
    const float* Wf1 = (const float*)d_in[4];
    const float* bf1 = (const float*)d_in[5];
    const float* Ws1 = (const float*)d_in[6];
    const float* bs1 = (const float*)d_in[7];
    const float* Wp  = (const float*)d_in[8];
    const float* bp  = (const float*)d_in[9];
    const float* Wc[2]  = { (const float*)d_in[10], (const float*)d_in[14] };
    const float* bcf[2] = { (const float*)d_in[11], (const float*)d_in[15] };
    const float* Wsc[2] = { (const float*)d_in[12], (const float*)d_in[16] };
    const float* bcs[2] = { (const float*)d_in[13], (const float*)d_in[17] };
    const float* W1  = (const float*)d_in[18];
    const float* b1  = (const float*)d_in[19];
    const float* W2  = (const float*)d_in[20];
    const float* b2  = (const float*)d_in[21];
    float* out = (float*)d_out;

    float *pH, *pAgg, *pPool;
    __half *pPA, *pPB, *pEAS, *pWTP, *pWTE;
    int *pDeg, *pCur, *pPart, *pSrcs, *pDsts;
    int4 *pEsd;
    cudaGetSymbolAddress((void**)&pH,    g_h);
    cudaGetSymbolAddress((void**)&pPA,   g_PA);
    cudaGetSymbolAddress((void**)&pPB,   g_PB);
    cudaGetSymbolAddress((void**)&pAgg,  g_agg);
    cudaGetSymbolAddress((void**)&pPool, g_pool);
    cudaGetSymbolAddress((void**)&pDeg,  g_deg);
    cudaGetSymbolAddress((void**)&pCur,  g_cursor);
    cudaGetSymbolAddress((void**)&pPart, g_part);
    cudaGetSymbolAddress((void**)&pEsd,  g_esd);
    cudaGetSymbolAddress((void**)&pSrcs, g_srcs);
    cudaGetSymbolAddress((void**)&pDsts, g_dsts);
    cudaGetSymbolAddress((void**)&pEAS,  g_eas);
    cudaGetSymbolAddress((void**)&pWTP,  g_wTproj);
    cudaGetSymbolAddress((void**)&pWTE,  g_wTedge);

    const int EDGE_SMEM = (256 * WT_S + 2 * 64 * EA_S + 64 * EH_S) * 2;
    const int PROJ_SMEM = 2 * 128 * PJ_S * 2;
    cudaFuncSetAttribute(k_edge_fused, cudaFuncAttributeMaxDynamicSharedMemorySize, EDGE_SMEM);
    cudaFuncSetAttribute(k_proj_all, cudaFuncAttributeMaxDynamicSharedMemorySize, PROJ_SMEM);

    // ---- zeroing via graph memset nodes ----
    cudaMemsetAsync(pDeg, 0, N_NODES * sizeof(int));
    cudaMemsetAsync(pAgg, 0, N_NODES * 3 * sizeof(float));
    cudaMemsetAsync(pPool, 0, (NGRAPH * HID + NGRAPH) * sizeof(float));

    // ---- weight prep ----
    k_wprep2<<<(2 * WPREP_N + 255) / 256, 256>>>(Wc[0], Wsc[0], Wc[1], Wsc[1],
                                                 pWTP, pWTE);

    // ---- build CSR + conv1 (ea read exactly once) ----
    k_hist<<<N_EDGES / 256, 256>>>(ei, pDeg);
    k_scan_a<<<SCAN_NB, SCAN_B>>>(pDeg, pCur, pPart);
    k_scan_b<<<1, 256>>>(pPart, SCAN_NB);
    k_perm<<<N_EDGES / 256, 256>>>(ei, pCur, pPart, pEsd);
    k_gather_conv1<<<N_EDGES / 256, 256>>>(pEsd, ea, x, Wf1, bf1, Ws1, bs1,
                                           pSrcs, pDsts, pEAS, pAgg);
    k_node1<<<592, 256>>>(x, pAgg, Wp, bp, pH);

    // ---- hidden convs (update fused into next proj) ----
    for (int l = 0; l < 2; l++) {
        k_proj_all<<<(N_NODES + 127) / 128, 256, PROJ_SMEM>>>(
            pH, pAgg, l, pWTP + l * 4 * 128 * 128, bcf[l], bcs[l], pPA, pPB);
        cudaMemsetAsync(pAgg, 0, (size_t)N_NODES * HID * sizeof(float));
        k_edge_fused<<<444, 256, EDGE_SMEM>>>(pSrcs, pDsts, pEAS, pPA, pPB,
                                              pWTE + l * 256 * 32, pAgg);
    }

    // ---- final residual + pooling + head ----
    k_update_pool<<<(N_NODES + 255) / 256, 128>>>(pH, pAgg, bat,
                                                  pPool, pPool + NGRAPH * HID);
    k_head<<<NGRAPH, 128>>>(pPool, pPool + NGRAPH * HID, W1, b1, W2, b2, out);
}